// round 8
// baseline (speedup 1.0000x reference)
#include <cuda_runtime.h>
#include <cuda_bf16.h>
#include <cstdint>

#define B_   4
#define NQ_  2048
#define D_   512
#define H_   8
#define DH_  64
#define M_   (B_*NQ_)
#define BH_  (B_*H_)
#define GRP_ 8                      // bh per attention group

typedef __nv_bfloat16 bf16;

// ---------------- device scratch ----------------
__device__ __align__(16) bf16 g_Xq16[M_*D_];
__device__ __align__(16) bf16 g_Xe16[M_*D_];
__device__ __align__(16) bf16 g_W16[4*D_*D_];            // Wq,Wk,Wv,W0
__device__ __align__(16) bf16 g_W1h[D_*D_], g_W1l[D_*D_];
__device__ __align__(16) bf16 g_Q16[BH_*NQ_*DH_];
__device__ __align__(16) bf16 g_K16[BH_*NQ_*DH_];
__device__ __align__(16) float g_V[BH_*NQ_*DH_];
__device__ __align__(16) bf16 g_Vp16[BH_*NQ_*80];        // rcs-scaled V + rcs cols
__device__ __align__(16) bf16 g_E[(size_t)GRP_*NQ_*NQ_]; // exp(S) scratch, 1 group (67MB)
__device__ float g_csum[BH_*NQ_];
__device__ __align__(16) bf16 g_O16[M_*D_];
__device__ __align__(16) bf16 g_Yh[M_*D_], g_Yl[M_*D_];

// ---------------- helpers ----------------
__device__ __forceinline__ uint32_t smem_u32(const void* p) {
    uint32_t a;
    asm("{ .reg .u64 t; cvta.to.shared.u64 t, %1; cvt.u32.u64 %0, t; }" : "=r"(a) : "l"(p));
    return a;
}
__device__ __forceinline__ void mma16816(float* c, const uint32_t* a, const uint32_t* b) {
    asm volatile(
        "mma.sync.aligned.m16n8k16.row.col.f32.bf16.bf16.f32 "
        "{%0,%1,%2,%3}, {%4,%5,%6,%7}, {%8,%9}, {%0,%1,%2,%3};"
        : "+f"(c[0]), "+f"(c[1]), "+f"(c[2]), "+f"(c[3])
        : "r"(a[0]), "r"(a[1]), "r"(a[2]), "r"(a[3]), "r"(b[0]), "r"(b[1]));
}
__device__ __forceinline__ void ldmx4(uint32_t* r, uint32_t a) {
    asm volatile("ldmatrix.sync.aligned.m8n8.x4.shared.b16 {%0,%1,%2,%3}, [%4];"
                 : "=r"(r[0]), "=r"(r[1]), "=r"(r[2]), "=r"(r[3]) : "r"(a));
}
__device__ __forceinline__ void ldmx4t(uint32_t* r, uint32_t a) {
    asm volatile("ldmatrix.sync.aligned.m8n8.x4.trans.shared.b16 {%0,%1,%2,%3}, [%4];"
                 : "=r"(r[0]), "=r"(r[1]), "=r"(r[2]), "=r"(r[3]) : "r"(a));
}
__device__ __forceinline__ void ldmx2t(uint32_t* r, uint32_t a) {
    asm volatile("ldmatrix.sync.aligned.m8n8.x2.trans.shared.b16 {%0,%1}, [%2];"
                 : "=r"(r[0]), "=r"(r[1]) : "r"(a));
}
__device__ __forceinline__ void lda(uint32_t* r, uint32_t base, int row0, int kbyte,
                                    int SB, int lane) {
    uint32_t a = base + (uint32_t)(row0 + (lane & 15)) * SB + kbyte + ((lane >> 4) << 4);
    ldmx4(r, a);
}
__device__ __forceinline__ void ldb_nt(uint32_t* r, uint32_t base, int n0, int kbyte,
                                       int SB, int lane) {
    uint32_t a = base + (uint32_t)(n0 + (lane & 7) + ((lane >> 4) << 3)) * SB
               + kbyte + (((lane >> 3) & 1) << 4);
    ldmx4(r, a);
}
__device__ __forceinline__ void ldb_t(uint32_t* r, uint32_t base, int k0, int n0,
                                      int SB, int lane) {
    uint32_t a = base + (uint32_t)(k0 + (lane & 7) + (((lane >> 3) & 1) << 3)) * SB
               + n0 * 2 + ((lane >> 4) << 4);
    ldmx4t(r, a);
}
__device__ __forceinline__ void ldb_t2(uint32_t* r, uint32_t base, int k0, int n0,
                                       int SB, int lane) {
    uint32_t a = base + (uint32_t)(k0 + (lane & 15)) * SB + n0 * 2;
    ldmx2t(r, a);
}
__device__ __forceinline__ uint32_t pk(bf16 a, bf16 b) {
    return (uint32_t)__bfloat16_as_ushort(a) | ((uint32_t)__bfloat16_as_ushort(b) << 16);
}
__device__ __forceinline__ uint2 cvt4(float4 v) {
    return make_uint2(pk(__float2bfloat16(v.x), __float2bfloat16(v.y)),
                      pk(__float2bfloat16(v.z), __float2bfloat16(v.w)));
}
__device__ __forceinline__ void split4(float4 v, uint2& h, uint2& l) {
    bf16 h0 = __float2bfloat16(v.x), h1 = __float2bfloat16(v.y);
    bf16 h2 = __float2bfloat16(v.z), h3 = __float2bfloat16(v.w);
    bf16 l0 = __float2bfloat16(v.x - __bfloat162float(h0));
    bf16 l1 = __float2bfloat16(v.y - __bfloat162float(h1));
    bf16 l2 = __float2bfloat16(v.z - __bfloat162float(h2));
    bf16 l3 = __float2bfloat16(v.w - __bfloat162float(h3));
    h = make_uint2(pk(h0, h1), pk(h2, h3));
    l = make_uint2(pk(l0, l1), pk(l2, l3));
}
__device__ __forceinline__ void split2(float a, float b, uint32_t& ph, uint32_t& pl) {
    bf16 ha = __float2bfloat16(a), hb = __float2bfloat16(b);
    bf16 la = __float2bfloat16(a - __bfloat162float(ha));
    bf16 lb = __float2bfloat16(b - __bfloat162float(hb));
    ph = pk(ha, hb); pl = pk(la, lb);
}
__device__ __forceinline__ void cpa16(uint32_t dst, const void* src) {
    asm volatile("cp.async.cg.shared.global [%0], [%1], 16;" :: "r"(dst), "l"(src));
}
#define CP_COMMIT() asm volatile("cp.async.commit_group;" ::: "memory")
#define CP_WAIT1()  asm volatile("cp.async.wait_group 1;"  ::: "memory")
#define CP_WAIT0()  asm volatile("cp.async.wait_group 0;"  ::: "memory")

// =====================================================================
// prep: all conversions + csum zero in one launch.
// blocks [0,4096): x_q->bf16  [4096,8192): x_e  [8192,9216): W0..3
// [9216,9472): W1 split       [9472,9728): zero csum
// =====================================================================
__global__ void __launch_bounds__(256)
prep_kernel(const float* __restrict__ x_q, const float* __restrict__ x_e,
            const float* __restrict__ Wq, const float* __restrict__ Wk,
            const float* __restrict__ Wv, const float* __restrict__ W0,
            const float* __restrict__ W1)
{
    const int b = blockIdx.x, tid = threadIdx.x;
    if (b < 8192) {
        const float* s = (b < 4096) ? x_q : x_e;
        bf16* d = (b < 4096) ? g_Xq16 : g_Xe16;
        const int i = (((b & 4095) * 256) + tid) * 4;
        *(uint2*)&d[i] = cvt4(*(const float4*)&s[i]);
    } else if (b < 9216) {
        const int w = (b - 8192) >> 8;
        const float* s = (w == 0) ? Wq : (w == 1) ? Wk : (w == 2) ? Wv : W0;
        const int i = ((((b - 8192) & 255) * 256) + tid) * 4;
        *(uint2*)&g_W16[(size_t)w * D_ * D_ + i] = cvt4(*(const float4*)&s[i]);
    } else if (b < 9472) {
        const int i = (((b - 9216) * 256) + tid) * 4;
        float4 v = *(const float4*)&W1[i];
        uint2 h, l; split4(v, h, l);
        *(uint2*)&g_W1h[i] = h; *(uint2*)&g_W1l[i] = l;
    } else {
        g_csum[(b - 9472) * 256 + tid] = 0.f;
    }
}

// =====================================================================
// dense1: single-plane bf16 GEMM C[8192,512] = A @ W (1 mma product).
// MODE 0: head-split bf16 (Q,K); MODE 3: head-split fp32 (V);
// MODE 1: Y = X - (AW + b), split-plane store.
// =====================================================================
#define D1_ST 18944   // A 128*80 + B 32*272
template<int MODE>
__global__ void __launch_bounds__(256, 2)
dense1_mma(const bf16* __restrict__ A16, const bf16* __restrict__ W16,
           const float* __restrict__ X, const float* __restrict__ bias,
           float* __restrict__ Cf, bf16* __restrict__ C16,
           bf16* __restrict__ Ch, bf16* __restrict__ Cl)
{
    extern __shared__ __align__(16) char dyn[];
    const int tid = threadIdx.x, lane = tid & 31, wid = tid >> 5;
    const int wm = wid >> 2, wn = wid & 3;
    const int m0 = blockIdx.y * 128, n0 = blockIdx.x * 128;
    const uint32_t sb = smem_u32(dyn);

    auto load = [&](int kc, int st) {
        const uint32_t sAs = sb + st * D1_ST;
        const uint32_t sBs = sAs + 10240;
#pragma unroll
        for (int j = 0; j < 2; j++) {
            int cc = tid + 256 * j;
            int row = cc >> 2, off = (cc & 3) * 16, e = (cc & 3) * 8;
            cpa16(sAs + row * 80 + off, A16 + (size_t)(m0 + row) * 512 + kc * 32 + e);
        }
#pragma unroll
        for (int j = 0; j < 2; j++) {
            int cc = tid + 256 * j;
            int row = cc >> 4, off = (cc & 15) * 16, e = (cc & 15) * 8;
            cpa16(sBs + row * 272 + off, W16 + (size_t)(kc * 32 + row) * 512 + n0 + e);
        }
    };

    float acc[4][4][4];
#pragma unroll
    for (int i = 0; i < 4; i++)
#pragma unroll
        for (int j = 0; j < 4; j++)
#pragma unroll
            for (int c = 0; c < 4; c++) acc[i][j][c] = 0.f;

    load(0, 0); CP_COMMIT();
    load(1, 1); CP_COMMIT();

    for (int kc = 0; kc < 16; kc++) {
        CP_WAIT1();
        __syncthreads();
        const int st = kc & 1;
        const uint32_t sAs = sb + st * D1_ST;
        const uint32_t sBs = sAs + 10240;
#pragma unroll
        for (int ks = 0; ks < 2; ks++) {
            uint32_t ah[4][4];
#pragma unroll
            for (int sm = 0; sm < 4; sm++)
                lda(ah[sm], sAs, wm * 64 + sm * 16, ks * 32, 80, lane);
            uint32_t bh[4][2];
#pragma unroll
            for (int p = 0; p < 2; p++) {
                uint32_t r[4];
                ldb_t(r, sBs, ks * 16, wn * 32 + p * 16, 272, lane);
                bh[2*p][0] = r[0]; bh[2*p][1] = r[1];
                bh[2*p+1][0] = r[2]; bh[2*p+1][1] = r[3];
            }
#pragma unroll
            for (int sm = 0; sm < 4; sm++)
#pragma unroll
                for (int sn = 0; sn < 4; sn++)
                    mma16816(acc[sm][sn], ah[sm], bh[sn]);
        }
        __syncthreads();
        if (kc + 2 < 16) load(kc + 2, st);
        CP_COMMIT();
    }

#pragma unroll
    for (int sm = 0; sm < 4; sm++) {
        const int row = m0 + wm * 64 + sm * 16 + (lane >> 2);
#pragma unroll
        for (int sn = 0; sn < 4; sn++) {
            const int col = n0 + wn * 32 + sn * 8 + (lane & 3) * 2;
            const float* a = acc[sm][sn];
            if (MODE == 0 || MODE == 3) {
                const int hh = col >> 6, dd = col & 63;
#pragma unroll
                for (int half = 0; half < 2; half++) {
                    const int gm = row + half * 8;
                    const int bb = gm >> 11, nn = gm & 2047;
                    const size_t idx = ((size_t)(bb * H_ + hh) * NQ_ + nn) * DH_ + dd;
                    if (MODE == 3)
                        *(float2*)&Cf[idx] = make_float2(a[half*2], a[half*2+1]);
                    else
                        *(uint32_t*)&C16[idx] =
                            pk(__float2bfloat16(a[half*2]), __float2bfloat16(a[half*2+1]));
                }
            } else {   // MODE 1
                float2 bv = *(const float2*)&bias[col];
#pragma unroll
                for (int half = 0; half < 2; half++) {
                    const int gm = row + half * 8;
                    float2 xv = *(const float2*)&X[(size_t)gm * 512 + col];
                    float o0 = xv.x - (a[half*2] + bv.x);
                    float o1 = xv.y - (a[half*2+1] + bv.y);
                    uint32_t ph, pl;
                    split2(o0, o1, ph, pl);
                    *(uint32_t*)&Ch[(size_t)gm * 512 + col] = ph;
                    *(uint32_t*)&Cl[(size_t)gm * 512 + col] = pl;
                }
            }
        }
    }
}

// =====================================================================
// dense3: split-operand GEMM out = Y @ W1 + b1 (3 products, fp32 out)
// =====================================================================
#define DA_ST 35328
__global__ void __launch_bounds__(256, 2)
dense3_mma(const bf16* __restrict__ Ah, const bf16* __restrict__ Al,
           const bf16* __restrict__ Wh, const bf16* __restrict__ Wl,
           const float* __restrict__ bias, float* __restrict__ Cf)
{
    extern __shared__ __align__(16) char dyn[];
    const int tid = threadIdx.x, lane = tid & 31, wid = tid >> 5;
    const int wm = wid >> 2, wn = wid & 3;
    const int m0 = blockIdx.y * 128, n0 = blockIdx.x * 128;
    const uint32_t sb = smem_u32(dyn);

    auto load = [&](int kc, int st) {
        const uint32_t sAs = sb + st * DA_ST;
        const uint32_t sBs = sAs + 18432;
#pragma unroll
        for (int j = 0; j < 2; j++) {
            int cc = tid + 256 * j;
            int row = cc >> 2, off = (cc & 3) * 16, e = (cc & 3) * 8;
            const size_t gi = (size_t)(m0 + row) * 512 + kc * 32 + e;
            cpa16(sAs + row * 144 + off,      Ah + gi);
            cpa16(sAs + row * 144 + 64 + off, Al + gi);
        }
#pragma unroll
        for (int j = 0; j < 2; j++) {
            int cc = tid + 256 * j;
            int row = cc >> 4, off = (cc & 15) * 16, e = (cc & 15) * 8;
            const size_t gi = (size_t)(kc * 32 + row) * 512 + n0 + e;
            cpa16(sBs + row * 528 + off,       Wh + gi);
            cpa16(sBs + row * 528 + 256 + off, Wl + gi);
        }
    };

    float acc[4][4][4];
#pragma unroll
    for (int i = 0; i < 4; i++)
#pragma unroll
        for (int j = 0; j < 4; j++)
#pragma unroll
            for (int c = 0; c < 4; c++) acc[i][j][c] = 0.f;

    load(0, 0); CP_COMMIT();
    load(1, 1); CP_COMMIT();

    for (int kc = 0; kc < 16; kc++) {
        CP_WAIT1();
        __syncthreads();
        const int st = kc & 1;
        const uint32_t sAs = sb + st * DA_ST;
        const uint32_t sBs = sAs + 18432;
#pragma unroll
        for (int ks = 0; ks < 2; ks++) {
            uint32_t ah[4][4], al[4][4];
#pragma unroll
            for (int sm = 0; sm < 4; sm++) {
                lda(ah[sm], sAs, wm * 64 + sm * 16, ks * 32, 144, lane);
                lda(al[sm], sAs, wm * 64 + sm * 16, 64 + ks * 32, 144, lane);
            }
            uint32_t bh[4][2], bl[4][2];
#pragma unroll
            for (int p = 0; p < 2; p++) {
                uint32_t r[4];
                ldb_t(r, sBs, ks * 16, wn * 32 + p * 16, 528, lane);
                bh[2*p][0] = r[0]; bh[2*p][1] = r[1];
                bh[2*p+1][0] = r[2]; bh[2*p+1][1] = r[3];
                ldb_t(r, sBs + 256, ks * 16, wn * 32 + p * 16, 528, lane);
                bl[2*p][0] = r[0]; bl[2*p][1] = r[1];
                bl[2*p+1][0] = r[2]; bl[2*p+1][1] = r[3];
            }
#pragma unroll
            for (int sm = 0; sm < 4; sm++)
#pragma unroll
                for (int sn = 0; sn < 4; sn++) {
                    mma16816(acc[sm][sn], ah[sm], bh[sn]);
                    mma16816(acc[sm][sn], al[sm], bh[sn]);
                    mma16816(acc[sm][sn], ah[sm], bl[sn]);
                }
        }
        __syncthreads();
        if (kc + 2 < 16) load(kc + 2, st);
        CP_COMMIT();
    }

#pragma unroll
    for (int sm = 0; sm < 4; sm++) {
        const int row = m0 + wm * 64 + sm * 16 + (lane >> 2);
#pragma unroll
        for (int sn = 0; sn < 4; sn++) {
            const int col = n0 + wn * 32 + sn * 8 + (lane & 3) * 2;
            const float* a = acc[sm][sn];
            float2 bv = *(const float2*)&bias[col];
#pragma unroll
            for (int half = 0; half < 2; half++) {
                const int gm = row + half * 8;
                *(float2*)&Cf[(size_t)gm * 512 + col] =
                    make_float2(a[half*2] + bv.x, a[half*2+1] + bv.y);
            }
        }
    }
}

// =====================================================================
// Scores (per group): E = exp(Q @ K^T) into the group-local E scratch.
// =====================================================================
__global__ void __launch_bounds__(256, 2)
scores_mma(int bh0)
{
    extern __shared__ __align__(16) char dyn[];
    __shared__ float colsum[128];
    const int tid = threadIdx.x, lane = tid & 31, wid = tid >> 5;
    const int wm = wid >> 2, wn = wid & 3;
    const int bhl = blockIdx.z, bh = bh0 + bhl;
    const int m0 = blockIdx.y * 128, n0 = blockIdx.x * 128;
    const bf16* __restrict__ Qp = g_Q16 + (size_t)bh * NQ_ * DH_;
    const bf16* __restrict__ Kp = g_K16 + (size_t)bh * NQ_ * DH_;
    const uint32_t sQ = smem_u32(dyn);
    const uint32_t sK = sQ + 18432;

#pragma unroll
    for (int j = 0; j < 4; j++) {
        int cc = tid + 256 * j;
        int row = cc >> 3, off = (cc & 7) * 16, e = (cc & 7) * 8;
        cpa16(sQ + row * 144 + off, Qp + (size_t)(m0 + row) * 64 + e);
        cpa16(sK + row * 144 + off, Kp + (size_t)(n0 + row) * 64 + e);
    }
    CP_COMMIT();
    if (tid < 128) colsum[tid] = 0.f;
    CP_WAIT0();
    __syncthreads();

    float acc[4][4][4];
#pragma unroll
    for (int i = 0; i < 4; i++)
#pragma unroll
        for (int j = 0; j < 4; j++)
#pragma unroll
            for (int c = 0; c < 4; c++) acc[i][j][c] = 0.f;

#pragma unroll
    for (int ks = 0; ks < 4; ks++) {
        uint32_t ah[4][4];
#pragma unroll
        for (int sm = 0; sm < 4; sm++)
            lda(ah[sm], sQ, wm * 64 + sm * 16, ks * 32, 144, lane);
        uint32_t bh_[4][2];
#pragma unroll
        for (int p = 0; p < 2; p++) {
            uint32_t r[4];
            ldb_nt(r, sK, wn * 32 + p * 16, ks * 32, 144, lane);
            bh_[2*p][0] = r[0]; bh_[2*p][1] = r[1];
            bh_[2*p+1][0] = r[2]; bh_[2*p+1][1] = r[3];
        }
#pragma unroll
        for (int sm = 0; sm < 4; sm++)
#pragma unroll
            for (int sn = 0; sn < 4; sn++)
                mma16816(acc[sm][sn], ah[sm], bh_[sn]);
    }

    float cs[4][2];
#pragma unroll
    for (int sn = 0; sn < 4; sn++) { cs[sn][0] = 0.f; cs[sn][1] = 0.f; }
    bf16* __restrict__ Ep = g_E + (size_t)bhl * NQ_ * NQ_;
#pragma unroll
    for (int sm = 0; sm < 4; sm++) {
        const int row = m0 + wm * 64 + sm * 16 + (lane >> 2);
#pragma unroll
        for (int sn = 0; sn < 4; sn++) {
            const int col = n0 + wn * 32 + sn * 8 + (lane & 3) * 2;
            float e0 = __expf(acc[sm][sn][0]);
            float e1 = __expf(acc[sm][sn][1]);
            float e2 = __expf(acc[sm][sn][2]);
            float e3 = __expf(acc[sm][sn][3]);
            *(uint32_t*)&Ep[(size_t)row * NQ_ + col] =
                pk(__float2bfloat16(e0), __float2bfloat16(e1));
            *(uint32_t*)&Ep[(size_t)(row + 8) * NQ_ + col] =
                pk(__float2bfloat16(e2), __float2bfloat16(e3));
            cs[sn][0] += e0 + e2;
            cs[sn][1] += e1 + e3;
        }
    }
#pragma unroll
    for (int o = 4; o <= 16; o <<= 1)
#pragma unroll
        for (int sn = 0; sn < 4; sn++) {
            cs[sn][0] += __shfl_xor_sync(0xffffffffu, cs[sn][0], o);
            cs[sn][1] += __shfl_xor_sync(0xffffffffu, cs[sn][1], o);
        }
    if (lane < 4) {
#pragma unroll
        for (int sn = 0; sn < 4; sn++) {
            atomicAdd(&colsum[wn * 32 + sn * 8 + lane * 2],     cs[sn][0]);
            atomicAdd(&colsum[wn * 32 + sn * 8 + lane * 2 + 1], cs[sn][1]);
        }
    }
    __syncthreads();
    if (tid < 128) atomicAdd(&g_csum[bh * NQ_ + n0 + tid], colsum[tid]);
}

// =====================================================================
// vscale (per group): V'[0:64]=V/csum, [64:72]=1/csum, [72:80]=0 -> bf16
// =====================================================================
__global__ void __launch_bounds__(256)
vscale_kernel(int bh0)
{
    const int idx = blockIdx.x * 256 + threadIdx.x;     // GRP*2048*20
    const int c4 = (idx % 20) * 4;
    const int rowg = bh0 * NQ_ + idx / 20;
    const float r = 1.f / g_csum[rowg];
    float4 v;
    if (c4 < 64) {
        v = *(const float4*)&g_V[(size_t)rowg * 64 + c4];
        v.x *= r; v.y *= r; v.z *= r; v.w *= r;
    } else if (c4 < 72) {
        v = make_float4(r, r, r, r);
    } else {
        v = make_float4(0.f, 0.f, 0.f, 0.f);
    }
    *(uint2*)&g_Vp16[(size_t)rowg * 80 + c4] = cvt4(v);
}

// =====================================================================
// PV (per group): out[64q, 64d] = E @ V', rs from cols 64..71.
// 8 warps (4m x 2n), warp 16x40, k-chunk 64, cp.async x2-stage.
// =====================================================================
#define PV_ST 20480   // E 64*144 + V 64*176
__global__ void __launch_bounds__(256, 2)
pv_mma(int bh0)
{
    extern __shared__ __align__(16) char dyn[];
    __shared__ float srs[64];
    const int tid = threadIdx.x, lane = tid & 31, wid = tid >> 5;
    const int wm = wid >> 1, wn = wid & 1;
    const int bhl = blockIdx.y, bh = bh0 + bhl;
    const int q0 = blockIdx.x * 64;
    const int bb = bh >> 3, hh = bh & 7;
    const bf16* __restrict__ Ep = g_E + (size_t)bhl * NQ_ * NQ_;
    const bf16* __restrict__ Vp = g_Vp16 + (size_t)bh * NQ_ * 80;
    const uint32_t sb = smem_u32(dyn);

    auto load = [&](int kc, int st) {
        const uint32_t sEs = sb + st * PV_ST;
        const uint32_t sVs = sEs + 9216;
#pragma unroll
        for (int j = 0; j < 2; j++) {
            int cc = tid + 256 * j;
            int row = cc >> 3, off = (cc & 7) * 16, e = (cc & 7) * 8;
            cpa16(sEs + row * 144 + off, Ep + (size_t)(q0 + row) * NQ_ + kc * 64 + e);
        }
#pragma unroll
        for (int j = 0; j < 3; j++) {
            int cc = tid + 256 * j;
            if (cc < 640) {
                int row = cc / 10, m = cc - row * 10;
                cpa16(sVs + row * 176 + m * 16, Vp + (size_t)(kc * 64 + row) * 80 + m * 8);
            }
        }
    };

    float acc[5][4];
#pragma unroll
    for (int j = 0; j < 5; j++)
#pragma unroll
        for (int c = 0; c < 4; c++) acc[j][c] = 0.f;

    load(0, 0); CP_COMMIT();
    load(1, 1); CP_COMMIT();

    for (int kc = 0; kc < 32; kc++) {
        CP_WAIT1();
        __syncthreads();
        const int st = kc & 1;
        const uint32_t sEs = sb + st * PV_ST;
        const uint32_t sVs = sEs + 9216;
#pragma unroll
        for (int ks = 0; ks < 4; ks++) {
            uint32_t ah[4];
            lda(ah, sEs, wm * 16, ks * 32, 144, lane);
            uint32_t bhf[5][2];
            {
                uint32_t r[4];
                ldb_t(r, sVs, ks * 16, wn * 40, 176, lane);
                bhf[0][0] = r[0]; bhf[0][1] = r[1]; bhf[1][0] = r[2]; bhf[1][1] = r[3];
                ldb_t(r, sVs, ks * 16, wn * 40 + 16, 176, lane);
                bhf[2][0] = r[0]; bhf[2][1] = r[1]; bhf[3][0] = r[2]; bhf[3][1] = r[3];
                ldb_t2(bhf[4], sVs, ks * 16, wn * 40 + 32, 176, lane);
            }
#pragma unroll
            for (int sn = 0; sn < 5; sn++)
                mma16816(acc[sn], ah, bhf[sn]);
        }
        __syncthreads();
        if (kc + 2 < 32) load(kc + 2, st);
        CP_COMMIT();
    }

    // rs = global cols 64..71 -> (wn==1, sn==3, in-tile col 0)
    if (wn == 1 && (lane & 3) == 0) {
        const int r = wm * 16 + (lane >> 2);
        srs[r]     = acc[3][0];
        srs[r + 8] = acc[3][2];
    }
    __syncthreads();

    {
        const int r = wm * 16 + (lane >> 2);
        const float inv0 = 1.f / (1e-12f + srs[r]);
        const float inv1 = 1.f / (1e-12f + srs[r + 8]);
        const int gq = q0 + r;
        const int snmax = wn ? 3 : 5;
#pragma unroll
        for (int sn = 0; sn < 5; sn++) {
            if (sn >= snmax) break;
            const int col = wn * 40 + sn * 8 + (lane & 3) * 2;   // 0..63
            const float* a = acc[sn];
            size_t idx = (size_t)(bb * NQ_ + gq) * D_ + hh * DH_ + col;
            *(uint32_t*)&g_O16[idx] =
                pk(__float2bfloat16(a[0] * inv0), __float2bfloat16(a[1] * inv0));
            idx = (size_t)(bb * NQ_ + gq + 8) * D_ + hh * DH_ + col;
            *(uint32_t*)&g_O16[idx] =
                pk(__float2bfloat16(a[2] * inv1), __float2bfloat16(a[3] * inv1));
        }
    }
}

// =====================================================================
// Launch
// =====================================================================
extern "C" void kernel_launch(void* const* d_in, const int* in_sizes, int n_in,
                              void* d_out, int out_size)
{
    const float* x_q = (const float*)d_in[0];
    const float* x_e = (const float*)d_in[1];
    const float* Wq  = (const float*)d_in[2];
    const float* Wk  = (const float*)d_in[3];
    const float* Wv  = (const float*)d_in[4];
    const float* W0  = (const float*)d_in[5];
    const float* b0  = (const float*)d_in[6];
    const float* W1  = (const float*)d_in[7];
    const float* b1  = (const float*)d_in[8];
    float* out = (float*)d_out;

    bf16 *Xq16, *Xe16, *W16, *W1h, *W1l, *Q16, *K16, *O16, *Yh, *Yl;
    float *Vf;
    cudaGetSymbolAddress((void**)&Xq16, g_Xq16);
    cudaGetSymbolAddress((void**)&Xe16, g_Xe16);
    cudaGetSymbolAddress((void**)&W16,  g_W16);
    cudaGetSymbolAddress((void**)&W1h,  g_W1h);
    cudaGetSymbolAddress((void**)&W1l,  g_W1l);
    cudaGetSymbolAddress((void**)&Q16,  g_Q16);
    cudaGetSymbolAddress((void**)&K16,  g_K16);
    cudaGetSymbolAddress((void**)&Vf,   g_V);
    cudaGetSymbolAddress((void**)&O16,  g_O16);
    cudaGetSymbolAddress((void**)&Yh,   g_Yh);
    cudaGetSymbolAddress((void**)&Yl,   g_Yl);

    cudaFuncSetAttribute(dense1_mma<0>, cudaFuncAttributeMaxDynamicSharedMemorySize, 2*D1_ST);
    cudaFuncSetAttribute(dense1_mma<1>, cudaFuncAttributeMaxDynamicSharedMemorySize, 2*D1_ST);
    cudaFuncSetAttribute(dense1_mma<3>, cudaFuncAttributeMaxDynamicSharedMemorySize, 2*D1_ST);
    cudaFuncSetAttribute(dense3_mma,    cudaFuncAttributeMaxDynamicSharedMemorySize, 2*DA_ST);
    cudaFuncSetAttribute(scores_mma,    cudaFuncAttributeMaxDynamicSharedMemorySize, 36864);
    cudaFuncSetAttribute(pv_mma,        cudaFuncAttributeMaxDynamicSharedMemorySize, 2*PV_ST);

    prep_kernel<<<9728, 256>>>(x_q, x_e, Wq, Wk, Wv, W0, W1);

    const dim3 gemm_grid(4, 64);

    dense1_mma<0><<<gemm_grid, 256, 2*D1_ST>>>(Xq16, W16, nullptr, nullptr,
                                               nullptr, Q16, nullptr, nullptr);
    dense1_mma<0><<<gemm_grid, 256, 2*D1_ST>>>(Xe16, W16 + (size_t)D_*D_, nullptr, nullptr,
                                               nullptr, K16, nullptr, nullptr);
    dense1_mma<3><<<gemm_grid, 256, 2*D1_ST>>>(Xe16, W16 + (size_t)2*D_*D_, nullptr, nullptr,
                                               Vf, nullptr, nullptr, nullptr);

    for (int g = 0; g < BH_ / GRP_; g++) {
        const int bh0 = g * GRP_;
        scores_mma<<<dim3(16, 16, GRP_), 256, 36864>>>(bh0);
        vscale_kernel<<<GRP_ * NQ_ * 20 / 256, 256>>>(bh0);
        pv_mma<<<dim3(32, GRP_), 256, 2*PV_ST>>>(bh0);
    }

    dense1_mma<1><<<gemm_grid, 256, 2*D1_ST>>>(O16, W16 + (size_t)3*D_*D_, x_q, b0,
                                               nullptr, nullptr, Yh, Yl);

    dense3_mma<<<gemm_grid, 256, 2*DA_ST>>>(Yh, Yl, W1h, W1l, b1, out);
}

// round 9
// speedup vs baseline: 1.1786x; 1.1786x over previous
#include <cuda_runtime.h>
#include <cuda_bf16.h>
#include <cstdint>

#define B_   4
#define NQ_  2048
#define D_   512
#define H_   8
#define DH_  64
#define M_   (B_*NQ_)
#define BH_  (B_*H_)

typedef __nv_bfloat16 bf16;

// ---------------- device scratch ----------------
__device__ __align__(16) bf16 g_Xq16[M_*D_];
__device__ __align__(16) bf16 g_Xe16[M_*D_];
__device__ __align__(16) bf16 g_W16[4*D_*D_];            // Wq,Wk,Wv,W0
__device__ __align__(16) bf16 g_W1h[D_*D_], g_W1l[D_*D_];
__device__ __align__(16) bf16 g_Q16[BH_*NQ_*DH_];
__device__ __align__(16) bf16 g_K16[BH_*NQ_*DH_];
__device__ __align__(16) float g_V[BH_*NQ_*DH_];
__device__ __align__(16) bf16 g_Vp16[BH_*NQ_*80];        // rcs-scaled V + rcs cols
__device__ __align__(16) bf16 g_E[134217728ull];         // exp(S), bf16, full
__device__ float g_csum[BH_*NQ_];
__device__ __align__(16) bf16 g_O16[M_*D_];
__device__ __align__(16) bf16 g_Yh[M_*D_], g_Yl[M_*D_];

// ---------------- helpers ----------------
__device__ __forceinline__ uint32_t smem_u32(const void* p) {
    uint32_t a;
    asm("{ .reg .u64 t; cvta.to.shared.u64 t, %1; cvt.u32.u64 %0, t; }" : "=r"(a) : "l"(p));
    return a;
}
__device__ __forceinline__ void mma16816(float* c, const uint32_t* a, const uint32_t* b) {
    asm volatile(
        "mma.sync.aligned.m16n8k16.row.col.f32.bf16.bf16.f32 "
        "{%0,%1,%2,%3}, {%4,%5,%6,%7}, {%8,%9}, {%0,%1,%2,%3};"
        : "+f"(c[0]), "+f"(c[1]), "+f"(c[2]), "+f"(c[3])
        : "r"(a[0]), "r"(a[1]), "r"(a[2]), "r"(a[3]), "r"(b[0]), "r"(b[1]));
}
__device__ __forceinline__ void ldmx4(uint32_t* r, uint32_t a) {
    asm volatile("ldmatrix.sync.aligned.m8n8.x4.shared.b16 {%0,%1,%2,%3}, [%4];"
                 : "=r"(r[0]), "=r"(r[1]), "=r"(r[2]), "=r"(r[3]) : "r"(a));
}
__device__ __forceinline__ void ldmx4t(uint32_t* r, uint32_t a) {
    asm volatile("ldmatrix.sync.aligned.m8n8.x4.trans.shared.b16 {%0,%1,%2,%3}, [%4];"
                 : "=r"(r[0]), "=r"(r[1]), "=r"(r[2]), "=r"(r[3]) : "r"(a));
}
__device__ __forceinline__ void ldmx2t(uint32_t* r, uint32_t a) {
    asm volatile("ldmatrix.sync.aligned.m8n8.x2.trans.shared.b16 {%0,%1}, [%2];"
                 : "=r"(r[0]), "=r"(r[1]) : "r"(a));
}
__device__ __forceinline__ void lda(uint32_t* r, uint32_t base, int row0, int kbyte,
                                    int SB, int lane) {
    uint32_t a = base + (uint32_t)(row0 + (lane & 15)) * SB + kbyte + ((lane >> 4) << 4);
    ldmx4(r, a);
}
__device__ __forceinline__ void ldb_nt(uint32_t* r, uint32_t base, int n0, int kbyte,
                                       int SB, int lane) {
    uint32_t a = base + (uint32_t)(n0 + (lane & 7) + ((lane >> 4) << 3)) * SB
               + kbyte + (((lane >> 3) & 1) << 4);
    ldmx4(r, a);
}
__device__ __forceinline__ void ldb_t(uint32_t* r, uint32_t base, int k0, int n0,
                                      int SB, int lane) {
    uint32_t a = base + (uint32_t)(k0 + (lane & 7) + (((lane >> 3) & 1) << 3)) * SB
               + n0 * 2 + ((lane >> 4) << 4);
    ldmx4t(r, a);
}
__device__ __forceinline__ void ldb_t2(uint32_t* r, uint32_t base, int k0, int n0,
                                       int SB, int lane) {
    uint32_t a = base + (uint32_t)(k0 + (lane & 15)) * SB + n0 * 2;
    ldmx2t(r, a);
}
__device__ __forceinline__ uint32_t pk(bf16 a, bf16 b) {
    return (uint32_t)__bfloat16_as_ushort(a) | ((uint32_t)__bfloat16_as_ushort(b) << 16);
}
__device__ __forceinline__ uint2 cvt4(float4 v) {
    return make_uint2(pk(__float2bfloat16(v.x), __float2bfloat16(v.y)),
                      pk(__float2bfloat16(v.z), __float2bfloat16(v.w)));
}
__device__ __forceinline__ void split4(float4 v, uint2& h, uint2& l) {
    bf16 h0 = __float2bfloat16(v.x), h1 = __float2bfloat16(v.y);
    bf16 h2 = __float2bfloat16(v.z), h3 = __float2bfloat16(v.w);
    bf16 l0 = __float2bfloat16(v.x - __bfloat162float(h0));
    bf16 l1 = __float2bfloat16(v.y - __bfloat162float(h1));
    bf16 l2 = __float2bfloat16(v.z - __bfloat162float(h2));
    bf16 l3 = __float2bfloat16(v.w - __bfloat162float(h3));
    h = make_uint2(pk(h0, h1), pk(h2, h3));
    l = make_uint2(pk(l0, l1), pk(l2, l3));
}
__device__ __forceinline__ void split2(float a, float b, uint32_t& ph, uint32_t& pl) {
    bf16 ha = __float2bfloat16(a), hb = __float2bfloat16(b);
    bf16 la = __float2bfloat16(a - __bfloat162float(ha));
    bf16 lb = __float2bfloat16(b - __bfloat162float(hb));
    ph = pk(ha, hb); pl = pk(la, lb);
}
__device__ __forceinline__ void cpa16(uint32_t dst, const void* src) {
    asm volatile("cp.async.cg.shared.global [%0], [%1], 16;" :: "r"(dst), "l"(src));
}
#define CP_COMMIT() asm volatile("cp.async.commit_group;" ::: "memory")
#define CP_WAIT2()  asm volatile("cp.async.wait_group 2;"  ::: "memory")
#define CP_WAIT0()  asm volatile("cp.async.wait_group 0;"  ::: "memory")

// =====================================================================
// prep: all conversions + csum zero in one launch.
// =====================================================================
__global__ void __launch_bounds__(256)
prep_kernel(const float* __restrict__ x_q, const float* __restrict__ x_e,
            const float* __restrict__ Wq, const float* __restrict__ Wk,
            const float* __restrict__ Wv, const float* __restrict__ W0,
            const float* __restrict__ W1)
{
    const int b = blockIdx.x, tid = threadIdx.x;
    if (b < 8192) {
        const float* s = (b < 4096) ? x_q : x_e;
        bf16* d = (b < 4096) ? g_Xq16 : g_Xe16;
        const int i = (((b & 4095) * 256) + tid) * 4;
        *(uint2*)&d[i] = cvt4(*(const float4*)&s[i]);
    } else if (b < 9216) {
        const int w = (b - 8192) >> 8;
        const float* s = (w == 0) ? Wq : (w == 1) ? Wk : (w == 2) ? Wv : W0;
        const int i = ((((b - 8192) & 255) * 256) + tid) * 4;
        *(uint2*)&g_W16[(size_t)w * D_ * D_ + i] = cvt4(*(const float4*)&s[i]);
    } else if (b < 9472) {
        const int i = (((b - 9216) * 256) + tid) * 4;
        float4 v = *(const float4*)&W1[i];
        uint2 h, l; split4(v, h, l);
        *(uint2*)&g_W1h[i] = h; *(uint2*)&g_W1l[i] = l;
    } else {
        g_csum[(b - 9472) * 256 + tid] = 0.f;
    }
}

// =====================================================================
// dense1: single-plane bf16 GEMM, 3-stage cp.async pipeline.
// MODE 0: head-split bf16 (Q,K); MODE 3: head-split fp32 (V);
// MODE 1: Y = X - (AW + b), split-plane store.
// =====================================================================
#define D1_ST 18944   // A 128*80 + B 32*272
template<int MODE>
__global__ void __launch_bounds__(256, 2)
dense1_mma(const bf16* __restrict__ A16, const bf16* __restrict__ W16,
           const float* __restrict__ X, const float* __restrict__ bias,
           float* __restrict__ Cf, bf16* __restrict__ C16,
           bf16* __restrict__ Ch, bf16* __restrict__ Cl)
{
    extern __shared__ __align__(16) char dyn[];
    const int tid = threadIdx.x, lane = tid & 31, wid = tid >> 5;
    const int wm = wid >> 2, wn = wid & 3;
    const int m0 = blockIdx.y * 128, n0 = blockIdx.x * 128;
    const uint32_t sb = smem_u32(dyn);

    auto load = [&](int kc, int st) {
        const uint32_t sAs = sb + st * D1_ST;
        const uint32_t sBs = sAs + 10240;
#pragma unroll
        for (int j = 0; j < 2; j++) {
            int cc = tid + 256 * j;
            int row = cc >> 2, off = (cc & 3) * 16, e = (cc & 3) * 8;
            cpa16(sAs + row * 80 + off, A16 + (size_t)(m0 + row) * 512 + kc * 32 + e);
        }
#pragma unroll
        for (int j = 0; j < 2; j++) {
            int cc = tid + 256 * j;
            int row = cc >> 4, off = (cc & 15) * 16, e = (cc & 15) * 8;
            cpa16(sBs + row * 272 + off, W16 + (size_t)(kc * 32 + row) * 512 + n0 + e);
        }
    };

    float acc[4][4][4];
#pragma unroll
    for (int i = 0; i < 4; i++)
#pragma unroll
        for (int j = 0; j < 4; j++)
#pragma unroll
            for (int c = 0; c < 4; c++) acc[i][j][c] = 0.f;

    load(0, 0); CP_COMMIT();
    load(1, 1); CP_COMMIT();
    load(2, 2); CP_COMMIT();

    for (int kc = 0; kc < 16; kc++) {
        CP_WAIT2();
        __syncthreads();
        const int st = kc % 3;
        const uint32_t sAs = sb + st * D1_ST;
        const uint32_t sBs = sAs + 10240;
#pragma unroll
        for (int ks = 0; ks < 2; ks++) {
            uint32_t ah[4][4];
#pragma unroll
            for (int sm = 0; sm < 4; sm++)
                lda(ah[sm], sAs, wm * 64 + sm * 16, ks * 32, 80, lane);
            uint32_t bh[4][2];
#pragma unroll
            for (int p = 0; p < 2; p++) {
                uint32_t r[4];
                ldb_t(r, sBs, ks * 16, wn * 32 + p * 16, 272, lane);
                bh[2*p][0] = r[0]; bh[2*p][1] = r[1];
                bh[2*p+1][0] = r[2]; bh[2*p+1][1] = r[3];
            }
#pragma unroll
            for (int sm = 0; sm < 4; sm++)
#pragma unroll
                for (int sn = 0; sn < 4; sn++)
                    mma16816(acc[sm][sn], ah[sm], bh[sn]);
        }
        __syncthreads();
        if (kc + 3 < 16) load(kc + 3, st);
        CP_COMMIT();
    }

#pragma unroll
    for (int sm = 0; sm < 4; sm++) {
        const int row = m0 + wm * 64 + sm * 16 + (lane >> 2);
#pragma unroll
        for (int sn = 0; sn < 4; sn++) {
            const int col = n0 + wn * 32 + sn * 8 + (lane & 3) * 2;
            const float* a = acc[sm][sn];
            if (MODE == 0 || MODE == 3) {
                const int hh = col >> 6, dd = col & 63;
#pragma unroll
                for (int half = 0; half < 2; half++) {
                    const int gm = row + half * 8;
                    const int bb = gm >> 11, nn = gm & 2047;
                    const size_t idx = ((size_t)(bb * H_ + hh) * NQ_ + nn) * DH_ + dd;
                    if (MODE == 3)
                        *(float2*)&Cf[idx] = make_float2(a[half*2], a[half*2+1]);
                    else
                        *(uint32_t*)&C16[idx] =
                            pk(__float2bfloat16(a[half*2]), __float2bfloat16(a[half*2+1]));
                }
            } else {   // MODE 1
                float2 bv = *(const float2*)&bias[col];
#pragma unroll
                for (int half = 0; half < 2; half++) {
                    const int gm = row + half * 8;
                    float2 xv = *(const float2*)&X[(size_t)gm * 512 + col];
                    float o0 = xv.x - (a[half*2] + bv.x);
                    float o1 = xv.y - (a[half*2+1] + bv.y);
                    uint32_t ph, pl;
                    split2(o0, o1, ph, pl);
                    *(uint32_t*)&Ch[(size_t)gm * 512 + col] = ph;
                    *(uint32_t*)&Cl[(size_t)gm * 512 + col] = pl;
                }
            }
        }
    }
}

// =====================================================================
// dense3: split-operand GEMM out = Y @ W1 + b1 (3 products), 3-stage.
// =====================================================================
#define DA_ST 35328
__global__ void __launch_bounds__(256, 2)
dense3_mma(const bf16* __restrict__ Ah, const bf16* __restrict__ Al,
           const bf16* __restrict__ Wh, const bf16* __restrict__ Wl,
           const float* __restrict__ bias, float* __restrict__ Cf)
{
    extern __shared__ __align__(16) char dyn[];
    const int tid = threadIdx.x, lane = tid & 31, wid = tid >> 5;
    const int wm = wid >> 2, wn = wid & 3;
    const int m0 = blockIdx.y * 128, n0 = blockIdx.x * 128;
    const uint32_t sb = smem_u32(dyn);

    auto load = [&](int kc, int st) {
        const uint32_t sAs = sb + st * DA_ST;
        const uint32_t sBs = sAs + 18432;
#pragma unroll
        for (int j = 0; j < 2; j++) {
            int cc = tid + 256 * j;
            int row = cc >> 2, off = (cc & 3) * 16, e = (cc & 3) * 8;
            const size_t gi = (size_t)(m0 + row) * 512 + kc * 32 + e;
            cpa16(sAs + row * 144 + off,      Ah + gi);
            cpa16(sAs + row * 144 + 64 + off, Al + gi);
        }
#pragma unroll
        for (int j = 0; j < 2; j++) {
            int cc = tid + 256 * j;
            int row = cc >> 4, off = (cc & 15) * 16, e = (cc & 15) * 8;
            const size_t gi = (size_t)(kc * 32 + row) * 512 + n0 + e;
            cpa16(sBs + row * 528 + off,       Wh + gi);
            cpa16(sBs + row * 528 + 256 + off, Wl + gi);
        }
    };

    float acc[4][4][4];
#pragma unroll
    for (int i = 0; i < 4; i++)
#pragma unroll
        for (int j = 0; j < 4; j++)
#pragma unroll
            for (int c = 0; c < 4; c++) acc[i][j][c] = 0.f;

    load(0, 0); CP_COMMIT();
    load(1, 1); CP_COMMIT();
    load(2, 2); CP_COMMIT();

    for (int kc = 0; kc < 16; kc++) {
        CP_WAIT2();
        __syncthreads();
        const int st = kc % 3;
        const uint32_t sAs = sb + st * DA_ST;
        const uint32_t sBs = sAs + 18432;
#pragma unroll
        for (int ks = 0; ks < 2; ks++) {
            uint32_t ah[4][4], al[4][4];
#pragma unroll
            for (int sm = 0; sm < 4; sm++) {
                lda(ah[sm], sAs, wm * 64 + sm * 16, ks * 32, 144, lane);
                lda(al[sm], sAs, wm * 64 + sm * 16, 64 + ks * 32, 144, lane);
            }
            uint32_t bh[4][2], bl[4][2];
#pragma unroll
            for (int p = 0; p < 2; p++) {
                uint32_t r[4];
                ldb_t(r, sBs, ks * 16, wn * 32 + p * 16, 528, lane);
                bh[2*p][0] = r[0]; bh[2*p][1] = r[1];
                bh[2*p+1][0] = r[2]; bh[2*p+1][1] = r[3];
                ldb_t(r, sBs + 256, ks * 16, wn * 32 + p * 16, 528, lane);
                bl[2*p][0] = r[0]; bl[2*p][1] = r[1];
                bl[2*p+1][0] = r[2]; bl[2*p+1][1] = r[3];
            }
#pragma unroll
            for (int sm = 0; sm < 4; sm++)
#pragma unroll
                for (int sn = 0; sn < 4; sn++) {
                    mma16816(acc[sm][sn], ah[sm], bh[sn]);
                    mma16816(acc[sm][sn], al[sm], bh[sn]);
                    mma16816(acc[sm][sn], ah[sm], bl[sn]);
                }
        }
        __syncthreads();
        if (kc + 3 < 16) load(kc + 3, st);
        CP_COMMIT();
    }

#pragma unroll
    for (int sm = 0; sm < 4; sm++) {
        const int row = m0 + wm * 64 + sm * 16 + (lane >> 2);
#pragma unroll
        for (int sn = 0; sn < 4; sn++) {
            const int col = n0 + wn * 32 + sn * 8 + (lane & 3) * 2;
            const float* a = acc[sm][sn];
            float2 bv = *(const float2*)&bias[col];
#pragma unroll
            for (int half = 0; half < 2; half++) {
                const int gm = row + half * 8;
                *(float2*)&Cf[(size_t)gm * 512 + col] =
                    make_float2(a[half*2] + bv.x, a[half*2+1] + bv.y);
            }
        }
    }
}

// =====================================================================
// Scores: per (bh): E = exp(Q @ K^T) -> bf16 plane; csum atomics.
// =====================================================================
__global__ void __launch_bounds__(256, 2)
scores_mma()
{
    extern __shared__ __align__(16) char dyn[];
    __shared__ float colsum[128];
    const int tid = threadIdx.x, lane = tid & 31, wid = tid >> 5;
    const int wm = wid >> 2, wn = wid & 3;
    const int bh = blockIdx.z, m0 = blockIdx.y * 128, n0 = blockIdx.x * 128;
    const bf16* __restrict__ Qp = g_Q16 + (size_t)bh * NQ_ * DH_;
    const bf16* __restrict__ Kp = g_K16 + (size_t)bh * NQ_ * DH_;
    const uint32_t sQ = smem_u32(dyn);
    const uint32_t sK = sQ + 18432;

#pragma unroll
    for (int j = 0; j < 4; j++) {
        int cc = tid + 256 * j;
        int row = cc >> 3, off = (cc & 7) * 16, e = (cc & 7) * 8;
        cpa16(sQ + row * 144 + off, Qp + (size_t)(m0 + row) * 64 + e);
        cpa16(sK + row * 144 + off, Kp + (size_t)(n0 + row) * 64 + e);
    }
    CP_COMMIT();
    if (tid < 128) colsum[tid] = 0.f;
    CP_WAIT0();
    __syncthreads();

    float acc[4][4][4];
#pragma unroll
    for (int i = 0; i < 4; i++)
#pragma unroll
        for (int j = 0; j < 4; j++)
#pragma unroll
            for (int c = 0; c < 4; c++) acc[i][j][c] = 0.f;

#pragma unroll
    for (int ks = 0; ks < 4; ks++) {
        uint32_t ah[4][4];
#pragma unroll
        for (int sm = 0; sm < 4; sm++)
            lda(ah[sm], sQ, wm * 64 + sm * 16, ks * 32, 144, lane);
        uint32_t bh_[4][2];
#pragma unroll
        for (int p = 0; p < 2; p++) {
            uint32_t r[4];
            ldb_nt(r, sK, wn * 32 + p * 16, ks * 32, 144, lane);
            bh_[2*p][0] = r[0]; bh_[2*p][1] = r[1];
            bh_[2*p+1][0] = r[2]; bh_[2*p+1][1] = r[3];
        }
#pragma unroll
        for (int sm = 0; sm < 4; sm++)
#pragma unroll
            for (int sn = 0; sn < 4; sn++)
                mma16816(acc[sm][sn], ah[sm], bh_[sn]);
    }

    float cs[4][2];
#pragma unroll
    for (int sn = 0; sn < 4; sn++) { cs[sn][0] = 0.f; cs[sn][1] = 0.f; }
    bf16* __restrict__ Ep = g_E + (size_t)bh * NQ_ * NQ_;
#pragma unroll
    for (int sm = 0; sm < 4; sm++) {
        const int row = m0 + wm * 64 + sm * 16 + (lane >> 2);
#pragma unroll
        for (int sn = 0; sn < 4; sn++) {
            const int col = n0 + wn * 32 + sn * 8 + (lane & 3) * 2;
            float e0 = __expf(acc[sm][sn][0]);
            float e1 = __expf(acc[sm][sn][1]);
            float e2 = __expf(acc[sm][sn][2]);
            float e3 = __expf(acc[sm][sn][3]);
            *(uint32_t*)&Ep[(size_t)row * NQ_ + col] =
                pk(__float2bfloat16(e0), __float2bfloat16(e1));
            *(uint32_t*)&Ep[(size_t)(row + 8) * NQ_ + col] =
                pk(__float2bfloat16(e2), __float2bfloat16(e3));
            cs[sn][0] += e0 + e2;
            cs[sn][1] += e1 + e3;
        }
    }
#pragma unroll
    for (int o = 4; o <= 16; o <<= 1)
#pragma unroll
        for (int sn = 0; sn < 4; sn++) {
            cs[sn][0] += __shfl_xor_sync(0xffffffffu, cs[sn][0], o);
            cs[sn][1] += __shfl_xor_sync(0xffffffffu, cs[sn][1], o);
        }
    if (lane < 4) {
#pragma unroll
        for (int sn = 0; sn < 4; sn++) {
            atomicAdd(&colsum[wn * 32 + sn * 8 + lane * 2],     cs[sn][0]);
            atomicAdd(&colsum[wn * 32 + sn * 8 + lane * 2 + 1], cs[sn][1]);
        }
    }
    __syncthreads();
    if (tid < 128) atomicAdd(&g_csum[bh * NQ_ + n0 + tid], colsum[tid]);
}

// =====================================================================
// vscale: V'[0:64]=V/csum, [64:72]=1/csum, [72:80]=0 -> bf16
// =====================================================================
__global__ void __launch_bounds__(256)
vscale_kernel()
{
    const int idx = blockIdx.x * 256 + threadIdx.x;
    const int c4 = (idx % 20) * 4;
    const int rowg = idx / 20;
    const float r = 1.f / g_csum[rowg];
    float4 v;
    if (c4 < 64) {
        v = *(const float4*)&g_V[(size_t)rowg * 64 + c4];
        v.x *= r; v.y *= r; v.z *= r; v.w *= r;
    } else if (c4 < 72) {
        v = make_float4(r, r, r, r);
    } else {
        v = make_float4(0.f, 0.f, 0.f, 0.f);
    }
    *(uint2*)&g_Vp16[(size_t)rowg * 80 + c4] = cvt4(v);
}

// =====================================================================
// PV: out[128q, 64d] = E @ V' (1 product), rs from cols 64..71.
// 8 warps (4m x 2n), warp 32x40, k-chunk 64, 3-stage cp.async.
// =====================================================================
#define PV_ST 29696   // E 128*144 + V 64*176
__global__ void __launch_bounds__(256, 2)
pv_mma()
{
    extern __shared__ __align__(16) char dyn[];
    __shared__ float srs[128];
    const int tid = threadIdx.x, lane = tid & 31, wid = tid >> 5;
    const int wm = wid >> 1, wn = wid & 1;
    const int bh = blockIdx.y, q0 = blockIdx.x * 128;
    const int bb = bh >> 3, hh = bh & 7;
    const bf16* __restrict__ Ep = g_E + (size_t)bh * NQ_ * NQ_;
    const bf16* __restrict__ Vp = g_Vp16 + (size_t)bh * NQ_ * 80;
    const uint32_t sb = smem_u32(dyn);

    auto load = [&](int kc, int st) {
        const uint32_t sEs = sb + st * PV_ST;
        const uint32_t sVs = sEs + 18432;
#pragma unroll
        for (int j = 0; j < 4; j++) {
            int cc = tid + 256 * j;
            int row = cc >> 3, off = (cc & 7) * 16, e = (cc & 7) * 8;
            cpa16(sEs + row * 144 + off, Ep + (size_t)(q0 + row) * NQ_ + kc * 64 + e);
        }
#pragma unroll
        for (int j = 0; j < 3; j++) {
            int cc = tid + 256 * j;
            if (cc < 640) {
                int row = cc / 10, m = cc - row * 10;
                cpa16(sVs + row * 176 + m * 16, Vp + (size_t)(kc * 64 + row) * 80 + m * 8);
            }
        }
    };

    float acc[2][5][4];
#pragma unroll
    for (int i = 0; i < 2; i++)
#pragma unroll
        for (int j = 0; j < 5; j++)
#pragma unroll
            for (int c = 0; c < 4; c++) acc[i][j][c] = 0.f;

    load(0, 0); CP_COMMIT();
    load(1, 1); CP_COMMIT();
    load(2, 2); CP_COMMIT();

    for (int kc = 0; kc < 32; kc++) {
        CP_WAIT2();
        __syncthreads();
        const int st = kc % 3;
        const uint32_t sEs = sb + st * PV_ST;
        const uint32_t sVs = sEs + 18432;
#pragma unroll
        for (int ks = 0; ks < 4; ks++) {
            uint32_t ah[2][4];
#pragma unroll
            for (int sm = 0; sm < 2; sm++)
                lda(ah[sm], sEs, wm * 32 + sm * 16, ks * 32, 144, lane);
            uint32_t bhf[5][2];
            {
                uint32_t r[4];
                ldb_t(r, sVs, ks * 16, wn * 40, 176, lane);
                bhf[0][0] = r[0]; bhf[0][1] = r[1]; bhf[1][0] = r[2]; bhf[1][1] = r[3];
                ldb_t(r, sVs, ks * 16, wn * 40 + 16, 176, lane);
                bhf[2][0] = r[0]; bhf[2][1] = r[1]; bhf[3][0] = r[2]; bhf[3][1] = r[3];
                ldb_t2(bhf[4], sVs, ks * 16, wn * 40 + 32, 176, lane);
            }
#pragma unroll
            for (int sm = 0; sm < 2; sm++)
#pragma unroll
                for (int sn = 0; sn < 5; sn++)
                    mma16816(acc[sm][sn], ah[sm], bhf[sn]);
        }
        __syncthreads();
        if (kc + 3 < 32) load(kc + 3, st);
        CP_COMMIT();
    }

    // rs = global cols 64..71 -> (wn==1, sn==3, in-tile col 0)
#pragma unroll
    for (int sm = 0; sm < 2; sm++) {
        if (wn == 1 && (lane & 3) == 0) {
            const int r = wm * 32 + sm * 16 + (lane >> 2);
            srs[r]     = acc[sm][3][0];
            srs[r + 8] = acc[sm][3][2];
        }
    }
    __syncthreads();

#pragma unroll
    for (int sm = 0; sm < 2; sm++) {
        const int r = wm * 32 + sm * 16 + (lane >> 2);
        const float inv0 = 1.f / (1e-12f + srs[r]);
        const float inv1 = 1.f / (1e-12f + srs[r + 8]);
        const int gq = q0 + r;
        const int snmax = wn ? 3 : 5;
#pragma unroll
        for (int sn = 0; sn < 5; sn++) {
            if (sn >= snmax) break;
            const int col = wn * 40 + sn * 8 + (lane & 3) * 2;
            const float* a = acc[sm][sn];
            size_t idx = (size_t)(bb * NQ_ + gq) * D_ + hh * DH_ + col;
            *(uint32_t*)&g_O16[idx] =
                pk(__float2bfloat16(a[0] * inv0), __float2bfloat16(a[1] * inv0));
            idx = (size_t)(bb * NQ_ + gq + 8) * D_ + hh * DH_ + col;
            *(uint32_t*)&g_O16[idx] =
                pk(__float2bfloat16(a[2] * inv1), __float2bfloat16(a[3] * inv1));
        }
    }
}

// =====================================================================
// Launch
// =====================================================================
extern "C" void kernel_launch(void* const* d_in, const int* in_sizes, int n_in,
                              void* d_out, int out_size)
{
    const float* x_q = (const float*)d_in[0];
    const float* x_e = (const float*)d_in[1];
    const float* Wq  = (const float*)d_in[2];
    const float* Wk  = (const float*)d_in[3];
    const float* Wv  = (const float*)d_in[4];
    const float* W0  = (const float*)d_in[5];
    const float* b0  = (const float*)d_in[6];
    const float* W1  = (const float*)d_in[7];
    const float* b1  = (const float*)d_in[8];
    float* out = (float*)d_out;

    bf16 *Xq16, *Xe16, *W16, *W1h, *W1l, *Q16, *K16, *O16, *Yh, *Yl;
    float *Vf;
    cudaGetSymbolAddress((void**)&Xq16, g_Xq16);
    cudaGetSymbolAddress((void**)&Xe16, g_Xe16);
    cudaGetSymbolAddress((void**)&W16,  g_W16);
    cudaGetSymbolAddress((void**)&W1h,  g_W1h);
    cudaGetSymbolAddress((void**)&W1l,  g_W1l);
    cudaGetSymbolAddress((void**)&Q16,  g_Q16);
    cudaGetSymbolAddress((void**)&K16,  g_K16);
    cudaGetSymbolAddress((void**)&Vf,   g_V);
    cudaGetSymbolAddress((void**)&O16,  g_O16);
    cudaGetSymbolAddress((void**)&Yh,   g_Yh);
    cudaGetSymbolAddress((void**)&Yl,   g_Yl);

    cudaFuncSetAttribute(dense1_mma<0>, cudaFuncAttributeMaxDynamicSharedMemorySize, 3*D1_ST);
    cudaFuncSetAttribute(dense1_mma<1>, cudaFuncAttributeMaxDynamicSharedMemorySize, 3*D1_ST);
    cudaFuncSetAttribute(dense1_mma<3>, cudaFuncAttributeMaxDynamicSharedMemorySize, 3*D1_ST);
    cudaFuncSetAttribute(dense3_mma,    cudaFuncAttributeMaxDynamicSharedMemorySize, 3*DA_ST);
    cudaFuncSetAttribute(scores_mma,    cudaFuncAttributeMaxDynamicSharedMemorySize, 36864);
    cudaFuncSetAttribute(pv_mma,        cudaFuncAttributeMaxDynamicSharedMemorySize, 3*PV_ST);

    prep_kernel<<<9728, 256>>>(x_q, x_e, Wq, Wk, Wv, W0, W1);

    const dim3 gemm_grid(4, 64);

    dense1_mma<0><<<gemm_grid, 256, 3*D1_ST>>>(Xq16, W16, nullptr, nullptr,
                                               nullptr, Q16, nullptr, nullptr);
    dense1_mma<0><<<gemm_grid, 256, 3*D1_ST>>>(Xe16, W16 + (size_t)D_*D_, nullptr, nullptr,
                                               nullptr, K16, nullptr, nullptr);
    dense1_mma<3><<<gemm_grid, 256, 3*D1_ST>>>(Xe16, W16 + (size_t)2*D_*D_, nullptr, nullptr,
                                               Vf, nullptr, nullptr, nullptr);

    scores_mma<<<dim3(16, 16, 32), 256, 36864>>>();

    vscale_kernel<<<5120, 256>>>();

    pv_mma<<<dim3(16, 32), 256, 3*PV_ST>>>();

    dense1_mma<1><<<gemm_grid, 256, 3*D1_ST>>>(O16, W16 + (size_t)3*D_*D_, x_q, b0,
                                               nullptr, nullptr, Yh, Yl);

    dense3_mma<<<gemm_grid, 256, 3*DA_ST>>>(Yh, Yl, W1h, W1l, b1, out);
}

// round 10
// speedup vs baseline: 1.2260x; 1.0402x over previous
#include <cuda_runtime.h>
#include <cuda_bf16.h>
#include <cstdint>

#define B_   4
#define NQ_  2048
#define D_   512
#define H_   8
#define DH_  64
#define M_   (B_*NQ_)
#define BH_  (B_*H_)

typedef __nv_bfloat16 bf16;

// ---------------- device scratch ----------------
__device__ __align__(16) bf16 g_Xq16[M_*D_];
__device__ __align__(16) bf16 g_Xe16[M_*D_];
__device__ __align__(16) bf16 g_W16[4*D_*D_];            // Wq,Wk,Wv,W0
__device__ __align__(16) bf16 g_W1h[D_*D_], g_W1l[D_*D_];
__device__ __align__(16) bf16 g_Q16[BH_*NQ_*DH_];
__device__ __align__(16) bf16 g_K16[BH_*NQ_*DH_];
__device__ __align__(16) bf16 g_Vp16[BH_*NQ_*80];        // V bf16 [k][80]; cols64-71=1, 72-79=0
__device__ float g_csum[BH_*NQ_];
__device__ float g_rcs[BH_*NQ_];
__device__ __align__(16) bf16 g_O16[M_*D_];
__device__ __align__(16) bf16 g_Yh[M_*D_], g_Yl[M_*D_];

// ---------------- helpers ----------------
__device__ __forceinline__ uint32_t smem_u32(const void* p) {
    uint32_t a;
    asm("{ .reg .u64 t; cvta.to.shared.u64 t, %1; cvt.u32.u64 %0, t; }" : "=r"(a) : "l"(p));
    return a;
}
__device__ __forceinline__ void mma16816(float* c, const uint32_t* a, const uint32_t* b) {
    asm volatile(
        "mma.sync.aligned.m16n8k16.row.col.f32.bf16.bf16.f32 "
        "{%0,%1,%2,%3}, {%4,%5,%6,%7}, {%8,%9}, {%0,%1,%2,%3};"
        : "+f"(c[0]), "+f"(c[1]), "+f"(c[2]), "+f"(c[3])
        : "r"(a[0]), "r"(a[1]), "r"(a[2]), "r"(a[3]), "r"(b[0]), "r"(b[1]));
}
__device__ __forceinline__ void ldmx4(uint32_t* r, uint32_t a) {
    asm volatile("ldmatrix.sync.aligned.m8n8.x4.shared.b16 {%0,%1,%2,%3}, [%4];"
                 : "=r"(r[0]), "=r"(r[1]), "=r"(r[2]), "=r"(r[3]) : "r"(a));
}
__device__ __forceinline__ void ldmx4t(uint32_t* r, uint32_t a) {
    asm volatile("ldmatrix.sync.aligned.m8n8.x4.trans.shared.b16 {%0,%1,%2,%3}, [%4];"
                 : "=r"(r[0]), "=r"(r[1]), "=r"(r[2]), "=r"(r[3]) : "r"(a));
}
__device__ __forceinline__ void ldmx2t(uint32_t* r, uint32_t a) {
    asm volatile("ldmatrix.sync.aligned.m8n8.x2.trans.shared.b16 {%0,%1}, [%2];"
                 : "=r"(r[0]), "=r"(r[1]) : "r"(a));
}
__device__ __forceinline__ void lda(uint32_t* r, uint32_t base, int row0, int kbyte,
                                    int SB, int lane) {
    uint32_t a = base + (uint32_t)(row0 + (lane & 15)) * SB + kbyte + ((lane >> 4) << 4);
    ldmx4(r, a);
}
__device__ __forceinline__ void ldb_nt(uint32_t* r, uint32_t base, int n0, int kbyte,
                                       int SB, int lane) {
    uint32_t a = base + (uint32_t)(n0 + (lane & 7) + ((lane >> 4) << 3)) * SB
               + kbyte + (((lane >> 3) & 1) << 4);
    ldmx4(r, a);
}
__device__ __forceinline__ void ldb_t(uint32_t* r, uint32_t base, int k0, int n0,
                                      int SB, int lane) {
    uint32_t a = base + (uint32_t)(k0 + (lane & 7) + (((lane >> 3) & 1) << 3)) * SB
               + n0 * 2 + ((lane >> 4) << 4);
    ldmx4t(r, a);
}
__device__ __forceinline__ void ldb_t2(uint32_t* r, uint32_t base, int k0, int n0,
                                       int SB, int lane) {
    uint32_t a = base + (uint32_t)(k0 + (lane & 15)) * SB + n0 * 2;
    ldmx2t(r, a);
}
__device__ __forceinline__ uint32_t pk(bf16 a, bf16 b) {
    return (uint32_t)__bfloat16_as_ushort(a) | ((uint32_t)__bfloat16_as_ushort(b) << 16);
}
__device__ __forceinline__ uint32_t pkf(float a, float b) {
    return pk(__float2bfloat16(a), __float2bfloat16(b));
}
__device__ __forceinline__ uint2 cvt4(float4 v) {
    return make_uint2(pkf(v.x, v.y), pkf(v.z, v.w));
}
__device__ __forceinline__ void split4(float4 v, uint2& h, uint2& l) {
    bf16 h0 = __float2bfloat16(v.x), h1 = __float2bfloat16(v.y);
    bf16 h2 = __float2bfloat16(v.z), h3 = __float2bfloat16(v.w);
    bf16 l0 = __float2bfloat16(v.x - __bfloat162float(h0));
    bf16 l1 = __float2bfloat16(v.y - __bfloat162float(h1));
    bf16 l2 = __float2bfloat16(v.z - __bfloat162float(h2));
    bf16 l3 = __float2bfloat16(v.w - __bfloat162float(h3));
    h = make_uint2(pk(h0, h1), pk(h2, h3));
    l = make_uint2(pk(l0, l1), pk(l2, l3));
}
__device__ __forceinline__ void split2(float a, float b, uint32_t& ph, uint32_t& pl) {
    bf16 ha = __float2bfloat16(a), hb = __float2bfloat16(b);
    bf16 la = __float2bfloat16(a - __bfloat162float(ha));
    bf16 lb = __float2bfloat16(b - __bfloat162float(hb));
    ph = pk(ha, hb); pl = pk(la, lb);
}
__device__ __forceinline__ void cpa16(uint32_t dst, const void* src) {
    asm volatile("cp.async.cg.shared.global [%0], [%1], 16;" :: "r"(dst), "l"(src));
}
#define CP_COMMIT() asm volatile("cp.async.commit_group;" ::: "memory")
#define CP_WAIT1()  asm volatile("cp.async.wait_group 1;"  ::: "memory")
#define CP_WAIT2()  asm volatile("cp.async.wait_group 2;"  ::: "memory")
#define CP_WAIT0()  asm volatile("cp.async.wait_group 0;"  ::: "memory")

// =====================================================================
// prep: conversions + csum zero + V' pad columns, one launch.
// =====================================================================
__global__ void __launch_bounds__(256)
prep_kernel(const float* __restrict__ x_q, const float* __restrict__ x_e,
            const float* __restrict__ Wq, const float* __restrict__ Wk,
            const float* __restrict__ Wv, const float* __restrict__ W0,
            const float* __restrict__ W1)
{
    const int b = blockIdx.x, tid = threadIdx.x;
    if (b < 8192) {
        const float* s = (b < 4096) ? x_q : x_e;
        bf16* d = (b < 4096) ? g_Xq16 : g_Xe16;
        const int i = (((b & 4095) * 256) + tid) * 4;
        *(uint2*)&d[i] = cvt4(*(const float4*)&s[i]);
    } else if (b < 9216) {
        const int w = (b - 8192) >> 8;
        const float* s = (w == 0) ? Wq : (w == 1) ? Wk : (w == 2) ? Wv : W0;
        const int i = ((((b - 8192) & 255) * 256) + tid) * 4;
        *(uint2*)&g_W16[(size_t)w * D_ * D_ + i] = cvt4(*(const float4*)&s[i]);
    } else if (b < 9472) {
        const int i = (((b - 9216) * 256) + tid) * 4;
        float4 v = *(const float4*)&W1[i];
        uint2 h, l; split4(v, h, l);
        *(uint2*)&g_W1h[i] = h; *(uint2*)&g_W1l[i] = l;
    } else if (b < 9728) {
        g_csum[(b - 9472) * 256 + tid] = 0.f;
    } else {
        // V' pad: rows of g_Vp16, cols 64-71 = 1.0 bf16, 72-79 = 0
        const int row = (b - 9728) * 256 + tid;            // 65536 rows
        uint4 ones = make_uint4(0x3F803F80u, 0x3F803F80u, 0x3F803F80u, 0x3F803F80u);
        uint4 zero = make_uint4(0u, 0u, 0u, 0u);
        *(uint4*)&g_Vp16[(size_t)row * 80 + 64] = ones;
        *(uint4*)&g_Vp16[(size_t)row * 80 + 72] = zero;
    }
}

// =====================================================================
// dense1: single-plane bf16 GEMM, 3-stage cp.async pipeline.
// MODE 0: head-split bf16 stride 64 (Q,K); MODE 3: head-split bf16 stride 80 (V');
// MODE 1: Y = X - (AW + b), split-plane store.
// =====================================================================
#define D1_ST 18944   // A 128*80 + B 32*272
template<int MODE>
__global__ void __launch_bounds__(256, 2)
dense1_mma(const bf16* __restrict__ A16, const bf16* __restrict__ W16,
           const float* __restrict__ X, const float* __restrict__ bias,
           bf16* __restrict__ C16, bf16* __restrict__ Ch, bf16* __restrict__ Cl)
{
    extern __shared__ __align__(16) char dyn[];
    const int tid = threadIdx.x, lane = tid & 31, wid = tid >> 5;
    const int wm = wid >> 2, wn = wid & 3;
    const int m0 = blockIdx.y * 128, n0 = blockIdx.x * 128;
    const uint32_t sb = smem_u32(dyn);

    auto load = [&](int kc, int st) {
        const uint32_t sAs = sb + st * D1_ST;
        const uint32_t sBs = sAs + 10240;
#pragma unroll
        for (int j = 0; j < 2; j++) {
            int cc = tid + 256 * j;
            int row = cc >> 2, off = (cc & 3) * 16, e = (cc & 3) * 8;
            cpa16(sAs + row * 80 + off, A16 + (size_t)(m0 + row) * 512 + kc * 32 + e);
        }
#pragma unroll
        for (int j = 0; j < 2; j++) {
            int cc = tid + 256 * j;
            int row = cc >> 4, off = (cc & 15) * 16, e = (cc & 15) * 8;
            cpa16(sBs + row * 272 + off, W16 + (size_t)(kc * 32 + row) * 512 + n0 + e);
        }
    };

    float acc[4][4][4];
#pragma unroll
    for (int i = 0; i < 4; i++)
#pragma unroll
        for (int j = 0; j < 4; j++)
#pragma unroll
            for (int c = 0; c < 4; c++) acc[i][j][c] = 0.f;

    load(0, 0); CP_COMMIT();
    load(1, 1); CP_COMMIT();
    load(2, 2); CP_COMMIT();

    for (int kc = 0; kc < 16; kc++) {
        CP_WAIT2();
        __syncthreads();
        const int st = kc % 3;
        const uint32_t sAs = sb + st * D1_ST;
        const uint32_t sBs = sAs + 10240;
#pragma unroll
        for (int ks = 0; ks < 2; ks++) {
            uint32_t ah[4][4];
#pragma unroll
            for (int sm = 0; sm < 4; sm++)
                lda(ah[sm], sAs, wm * 64 + sm * 16, ks * 32, 80, lane);
            uint32_t bh[4][2];
#pragma unroll
            for (int p = 0; p < 2; p++) {
                uint32_t r[4];
                ldb_t(r, sBs, ks * 16, wn * 32 + p * 16, 272, lane);
                bh[2*p][0] = r[0]; bh[2*p][1] = r[1];
                bh[2*p+1][0] = r[2]; bh[2*p+1][1] = r[3];
            }
#pragma unroll
            for (int sm = 0; sm < 4; sm++)
#pragma unroll
                for (int sn = 0; sn < 4; sn++)
                    mma16816(acc[sm][sn], ah[sm], bh[sn]);
        }
        __syncthreads();
        if (kc + 3 < 16) load(kc + 3, st);
        CP_COMMIT();
    }

#pragma unroll
    for (int sm = 0; sm < 4; sm++) {
        const int row = m0 + wm * 64 + sm * 16 + (lane >> 2);
#pragma unroll
        for (int sn = 0; sn < 4; sn++) {
            const int col = n0 + wn * 32 + sn * 8 + (lane & 3) * 2;
            const float* a = acc[sm][sn];
            if (MODE == 0 || MODE == 3) {
                const int hh = col >> 6, dd = col & 63;
                const int stride = (MODE == 3) ? 80 : 64;
#pragma unroll
                for (int half = 0; half < 2; half++) {
                    const int gm = row + half * 8;
                    const int bb = gm >> 11, nn = gm & 2047;
                    const size_t idx = ((size_t)(bb * H_ + hh) * NQ_ + nn) * stride + dd;
                    *(uint32_t*)&C16[idx] = pkf(a[half*2], a[half*2+1]);
                }
            } else {   // MODE 1
                float2 bv = *(const float2*)&bias[col];
#pragma unroll
                for (int half = 0; half < 2; half++) {
                    const int gm = row + half * 8;
                    float2 xv = *(const float2*)&X[(size_t)gm * 512 + col];
                    float o0 = xv.x - (a[half*2] + bv.x);
                    float o1 = xv.y - (a[half*2+1] + bv.y);
                    uint32_t ph, pl;
                    split2(o0, o1, ph, pl);
                    *(uint32_t*)&Ch[(size_t)gm * 512 + col] = ph;
                    *(uint32_t*)&Cl[(size_t)gm * 512 + col] = pl;
                }
            }
        }
    }
}

// =====================================================================
// dense3: split-operand GEMM out = Y @ W1 + b1 (3 products), 3-stage.
// =====================================================================
#define DA_ST 35328
__global__ void __launch_bounds__(256, 2)
dense3_mma(const bf16* __restrict__ Ah, const bf16* __restrict__ Al,
           const bf16* __restrict__ Wh, const bf16* __restrict__ Wl,
           const float* __restrict__ bias, float* __restrict__ Cf)
{
    extern __shared__ __align__(16) char dyn[];
    const int tid = threadIdx.x, lane = tid & 31, wid = tid >> 5;
    const int wm = wid >> 2, wn = wid & 3;
    const int m0 = blockIdx.y * 128, n0 = blockIdx.x * 128;
    const uint32_t sb = smem_u32(dyn);

    auto load = [&](int kc, int st) {
        const uint32_t sAs = sb + st * DA_ST;
        const uint32_t sBs = sAs + 18432;
#pragma unroll
        for (int j = 0; j < 2; j++) {
            int cc = tid + 256 * j;
            int row = cc >> 2, off = (cc & 3) * 16, e = (cc & 3) * 8;
            const size_t gi = (size_t)(m0 + row) * 512 + kc * 32 + e;
            cpa16(sAs + row * 144 + off,      Ah + gi);
            cpa16(sAs + row * 144 + 64 + off, Al + gi);
        }
#pragma unroll
        for (int j = 0; j < 2; j++) {
            int cc = tid + 256 * j;
            int row = cc >> 4, off = (cc & 15) * 16, e = (cc & 15) * 8;
            const size_t gi = (size_t)(kc * 32 + row) * 512 + n0 + e;
            cpa16(sBs + row * 528 + off,       Wh + gi);
            cpa16(sBs + row * 528 + 256 + off, Wl + gi);
        }
    };

    float acc[4][4][4];
#pragma unroll
    for (int i = 0; i < 4; i++)
#pragma unroll
        for (int j = 0; j < 4; j++)
#pragma unroll
            for (int c = 0; c < 4; c++) acc[i][j][c] = 0.f;

    load(0, 0); CP_COMMIT();
    load(1, 1); CP_COMMIT();
    load(2, 2); CP_COMMIT();

    for (int kc = 0; kc < 16; kc++) {
        CP_WAIT2();
        __syncthreads();
        const int st = kc % 3;
        const uint32_t sAs = sb + st * DA_ST;
        const uint32_t sBs = sAs + 18432;
#pragma unroll
        for (int ks = 0; ks < 2; ks++) {
            uint32_t ah[4][4], al[4][4];
#pragma unroll
            for (int sm = 0; sm < 4; sm++) {
                lda(ah[sm], sAs, wm * 64 + sm * 16, ks * 32, 144, lane);
                lda(al[sm], sAs, wm * 64 + sm * 16, 64 + ks * 32, 144, lane);
            }
            uint32_t bh[4][2], bl[4][2];
#pragma unroll
            for (int p = 0; p < 2; p++) {
                uint32_t r[4];
                ldb_t(r, sBs, ks * 16, wn * 32 + p * 16, 528, lane);
                bh[2*p][0] = r[0]; bh[2*p][1] = r[1];
                bh[2*p+1][0] = r[2]; bh[2*p+1][1] = r[3];
                ldb_t(r, sBs + 256, ks * 16, wn * 32 + p * 16, 528, lane);
                bl[2*p][0] = r[0]; bl[2*p][1] = r[1];
                bl[2*p+1][0] = r[2]; bl[2*p+1][1] = r[3];
            }
#pragma unroll
            for (int sm = 0; sm < 4; sm++)
#pragma unroll
                for (int sn = 0; sn < 4; sn++) {
                    mma16816(acc[sm][sn], ah[sm], bh[sn]);
                    mma16816(acc[sm][sn], al[sm], bh[sn]);
                    mma16816(acc[sm][sn], ah[sm], bl[sn]);
                }
        }
        __syncthreads();
        if (kc + 3 < 16) load(kc + 3, st);
        CP_COMMIT();
    }

#pragma unroll
    for (int sm = 0; sm < 4; sm++) {
        const int row = m0 + wm * 64 + sm * 16 + (lane >> 2);
#pragma unroll
        for (int sn = 0; sn < 4; sn++) {
            const int col = n0 + wn * 32 + sn * 8 + (lane & 3) * 2;
            const float* a = acc[sm][sn];
            float2 bv = *(const float2*)&bias[col];
#pragma unroll
            for (int half = 0; half < 2; half++) {
                const int gm = row + half * 8;
                *(float2*)&Cf[(size_t)gm * 512 + col] =
                    make_float2(a[half*2] + bv.x, a[half*2+1] + bv.y);
            }
        }
    }
}

// =====================================================================
// Pass 1: colsum = sum over q of exp(Q @ K^T) — NO E store.
// =====================================================================
__global__ void __launch_bounds__(256, 2)
colsum_mma()
{
    extern __shared__ __align__(16) char dyn[];
    __shared__ float colsum[128];
    const int tid = threadIdx.x, lane = tid & 31, wid = tid >> 5;
    const int wm = wid >> 2, wn = wid & 3;
    const int bh = blockIdx.z, m0 = blockIdx.y * 128, n0 = blockIdx.x * 128;
    const bf16* __restrict__ Qp = g_Q16 + (size_t)bh * NQ_ * DH_;
    const bf16* __restrict__ Kp = g_K16 + (size_t)bh * NQ_ * DH_;
    const uint32_t sQ = smem_u32(dyn);
    const uint32_t sK = sQ + 18432;

#pragma unroll
    for (int j = 0; j < 4; j++) {
        int cc = tid + 256 * j;
        int row = cc >> 3, off = (cc & 7) * 16, e = (cc & 7) * 8;
        cpa16(sQ + row * 144 + off, Qp + (size_t)(m0 + row) * 64 + e);
        cpa16(sK + row * 144 + off, Kp + (size_t)(n0 + row) * 64 + e);
    }
    CP_COMMIT();
    if (tid < 128) colsum[tid] = 0.f;
    CP_WAIT0();
    __syncthreads();

    float acc[4][4][4];
#pragma unroll
    for (int i = 0; i < 4; i++)
#pragma unroll
        for (int j = 0; j < 4; j++)
#pragma unroll
            for (int c = 0; c < 4; c++) acc[i][j][c] = 0.f;

#pragma unroll
    for (int ks = 0; ks < 4; ks++) {
        uint32_t ah[4][4];
#pragma unroll
        for (int sm = 0; sm < 4; sm++)
            lda(ah[sm], sQ, wm * 64 + sm * 16, ks * 32, 144, lane);
        uint32_t bh_[4][2];
#pragma unroll
        for (int p = 0; p < 2; p++) {
            uint32_t r[4];
            ldb_nt(r, sK, wn * 32 + p * 16, ks * 32, 144, lane);
            bh_[2*p][0] = r[0]; bh_[2*p][1] = r[1];
            bh_[2*p+1][0] = r[2]; bh_[2*p+1][1] = r[3];
        }
#pragma unroll
        for (int sm = 0; sm < 4; sm++)
#pragma unroll
            for (int sn = 0; sn < 4; sn++)
                mma16816(acc[sm][sn], ah[sm], bh_[sn]);
    }

    float cs[4][2];
#pragma unroll
    for (int sn = 0; sn < 4; sn++) { cs[sn][0] = 0.f; cs[sn][1] = 0.f; }
#pragma unroll
    for (int sm = 0; sm < 4; sm++) {
#pragma unroll
        for (int sn = 0; sn < 4; sn++) {
            cs[sn][0] += __expf(acc[sm][sn][0]) + __expf(acc[sm][sn][2]);
            cs[sn][1] += __expf(acc[sm][sn][1]) + __expf(acc[sm][sn][3]);
        }
    }
#pragma unroll
    for (int o = 4; o <= 16; o <<= 1)
#pragma unroll
        for (int sn = 0; sn < 4; sn++) {
            cs[sn][0] += __shfl_xor_sync(0xffffffffu, cs[sn][0], o);
            cs[sn][1] += __shfl_xor_sync(0xffffffffu, cs[sn][1], o);
        }
    if (lane < 4) {
#pragma unroll
        for (int sn = 0; sn < 4; sn++) {
            atomicAdd(&colsum[wn * 32 + sn * 8 + lane * 2],     cs[sn][0]);
            atomicAdd(&colsum[wn * 32 + sn * 8 + lane * 2 + 1], cs[sn][1]);
        }
    }
    __syncthreads();
    if (tid < 128) atomicAdd(&g_csum[bh * NQ_ + n0 + tid], colsum[tid]);
}

__global__ void __launch_bounds__(256)
invert_kernel() {
    const int i = blockIdx.x * 256 + threadIdx.x;
    g_rcs[i] = 1.f / g_csum[i];
}

// =====================================================================
// Pass 2: fused attention. Per (bh, 128-q block): stream K/V'/rcs tiles,
// recompute S = QK^T, E = exp(S)*rcs in registers, feed C-frags directly
// as PV A-frags. rs from V' ones-columns 64-71. 8 warps, each m16 x full k.
// =====================================================================
#define FA_Q  18432                 // Q 128*144
#define FA_ST 41472                 // K 128*144 + V 128*176 + rcs 512
__global__ void __launch_bounds__(256, 2)
fused_pv()
{
    extern __shared__ __align__(16) char dyn[];
    const int tid = threadIdx.x, lane = tid & 31, wid = tid >> 5;
    const int bh = blockIdx.y, q0 = blockIdx.x * 128;
    const int bb = bh >> 3, hh = bh & 7;
    const bf16* __restrict__ Qp = g_Q16 + (size_t)bh * NQ_ * DH_;
    const bf16* __restrict__ Kp = g_K16 + (size_t)bh * NQ_ * DH_;
    const bf16* __restrict__ Vp = g_Vp16 + (size_t)bh * NQ_ * 80;
    const float* __restrict__ rp = g_rcs + bh * NQ_;
    const uint32_t sb = smem_u32(dyn);
    const uint32_t sQ = sb;

    auto loadKV = [&](int kc, int st) {
        const uint32_t base = sb + FA_Q + st * FA_ST;
        const uint32_t sK = base, sV = base + 18432, sR = base + 40960;
#pragma unroll
        for (int j = 0; j < 4; j++) {
            int cc = tid + 256 * j;
            int row = cc >> 3, off = (cc & 7) * 16, e = (cc & 7) * 8;
            cpa16(sK + row * 144 + off, Kp + (size_t)(kc * 128 + row) * 64 + e);
        }
#pragma unroll
        for (int j = 0; j < 5; j++) {
            int cc = tid + 256 * j;
            int row = cc / 10, m = cc - row * 10;
            cpa16(sV + row * 176 + m * 16, Vp + (size_t)(kc * 128 + row) * 80 + m * 8);
        }
        if (tid < 32) cpa16(sR + tid * 16, rp + kc * 128 + tid * 4);
    };

    // initial: Q + stage0 in group 0, stage1 in group 1
#pragma unroll
    for (int j = 0; j < 4; j++) {
        int cc = tid + 256 * j;
        int row = cc >> 3, off = (cc & 7) * 16, e = (cc & 7) * 8;
        cpa16(sQ + row * 144 + off, Qp + (size_t)(q0 + row) * 64 + e);
    }
    loadKV(0, 0); CP_COMMIT();
    loadKV(1, 1); CP_COMMIT();

    float pacc[9][4];
#pragma unroll
    for (int j = 0; j < 9; j++)
#pragma unroll
        for (int c = 0; c < 4; c++) pacc[j][c] = 0.f;

    uint32_t Qa[4][4];
    bool qloaded = false;

    for (int kc = 0; kc < 16; kc++) {
        CP_WAIT1();
        __syncthreads();
        const uint32_t base = sb + FA_Q + (kc & 1) * FA_ST;
        const uint32_t sK = base, sV = base + 18432;
        const char* sRp = dyn + FA_Q + (kc & 1) * FA_ST + 40960;
        if (!qloaded) {
#pragma unroll
            for (int ks = 0; ks < 4; ks++)
                lda(Qa[ks], sQ, wid * 16, ks * 32, 144, lane);
            qloaded = true;
        }
#pragma unroll
        for (int h = 0; h < 2; h++) {
            // --- QK: m16 x n64 (this half) x k64 ---
            float qk[8][4];
#pragma unroll
            for (int j = 0; j < 8; j++)
#pragma unroll
                for (int c = 0; c < 4; c++) qk[j][c] = 0.f;
#pragma unroll
            for (int ks = 0; ks < 4; ks++) {
#pragma unroll
                for (int p = 0; p < 4; p++) {
                    uint32_t r[4];
                    ldb_nt(r, sK, h * 64 + p * 16, ks * 32, 144, lane);
                    mma16816(qk[2*p],   Qa[ks], r);
                    mma16816(qk[2*p+1], Qa[ks], r + 2);
                }
            }
            // --- exp, scale by rcs, pack to PV A-frags; PV mma per k16 ---
#pragma unroll
            for (int kp = 0; kp < 4; kp++) {
                const int colb = h * 64 + kp * 16 + (lane & 3) * 2;
                float2 rc0 = *(const float2*)(sRp + colb * 4);
                float2 rc1 = *(const float2*)(sRp + (colb + 8) * 4);
                const float* s0 = qk[2*kp];
                const float* s1 = qk[2*kp+1];
                uint32_t pa[4];
                pa[0] = pkf(__expf(s0[0]) * rc0.x, __expf(s0[1]) * rc0.y);
                pa[1] = pkf(__expf(s0[2]) * rc0.x, __expf(s0[3]) * rc0.y);
                pa[2] = pkf(__expf(s1[0]) * rc1.x, __expf(s1[1]) * rc1.y);
                pa[3] = pkf(__expf(s1[2]) * rc1.x, __expf(s1[3]) * rc1.y);
                const int k0 = h * 64 + kp * 16;
                uint32_t v0[4], v1[4], v2[4], v3[4], v4[2];
                ldb_t(v0, sV, k0, 0,  176, lane);
                ldb_t(v1, sV, k0, 16, 176, lane);
                ldb_t(v2, sV, k0, 32, 176, lane);
                ldb_t(v3, sV, k0, 48, 176, lane);
                ldb_t2(v4, sV, k0, 64, 176, lane);
                mma16816(pacc[0], pa, v0);
                mma16816(pacc[1], pa, v0 + 2);
                mma16816(pacc[2], pa, v1);
                mma16816(pacc[3], pa, v1 + 2);
                mma16816(pacc[4], pa, v2);
                mma16816(pacc[5], pa, v2 + 2);
                mma16816(pacc[6], pa, v3);
                mma16816(pacc[7], pa, v3 + 2);
                mma16816(pacc[8], pa, v4);
            }
        }
        __syncthreads();
        if (kc + 2 < 16) loadKV(kc + 2, kc & 1);
        CP_COMMIT();
    }

    // epilogue: divide by rs (pacc[8]: ones columns) and store
    const float inv0 = 1.f / (1e-12f + pacc[8][0]);
    const float inv1 = 1.f / (1e-12f + pacc[8][2]);
    const int gq = q0 + wid * 16 + (lane >> 2);
#pragma unroll
    for (int sn = 0; sn < 8; sn++) {
        const int col = sn * 8 + (lane & 3) * 2;
        size_t idx = (size_t)(bb * NQ_ + gq) * D_ + hh * DH_ + col;
        *(uint32_t*)&g_O16[idx] = pkf(pacc[sn][0] * inv0, pacc[sn][1] * inv0);
        idx = (size_t)(bb * NQ_ + gq + 8) * D_ + hh * DH_ + col;
        *(uint32_t*)&g_O16[idx] = pkf(pacc[sn][2] * inv1, pacc[sn][3] * inv1);
    }
}

// =====================================================================
// Launch
// =====================================================================
extern "C" void kernel_launch(void* const* d_in, const int* in_sizes, int n_in,
                              void* d_out, int out_size)
{
    const float* x_q = (const float*)d_in[0];
    const float* x_e = (const float*)d_in[1];
    const float* Wq  = (const float*)d_in[2];
    const float* Wk  = (const float*)d_in[3];
    const float* Wv  = (const float*)d_in[4];
    const float* W0  = (const float*)d_in[5];
    const float* b0  = (const float*)d_in[6];
    const float* W1  = (const float*)d_in[7];
    const float* b1  = (const float*)d_in[8];
    float* out = (float*)d_out;

    bf16 *Xq16, *Xe16, *W16, *W1h, *W1l, *Q16, *K16, *Vp16, *O16, *Yh, *Yl;
    cudaGetSymbolAddress((void**)&Xq16, g_Xq16);
    cudaGetSymbolAddress((void**)&Xe16, g_Xe16);
    cudaGetSymbolAddress((void**)&W16,  g_W16);
    cudaGetSymbolAddress((void**)&W1h,  g_W1h);
    cudaGetSymbolAddress((void**)&W1l,  g_W1l);
    cudaGetSymbolAddress((void**)&Q16,  g_Q16);
    cudaGetSymbolAddress((void**)&K16,  g_K16);
    cudaGetSymbolAddress((void**)&Vp16, g_Vp16);
    cudaGetSymbolAddress((void**)&O16,  g_O16);
    cudaGetSymbolAddress((void**)&Yh,   g_Yh);
    cudaGetSymbolAddress((void**)&Yl,   g_Yl);

    cudaFuncSetAttribute(dense1_mma<0>, cudaFuncAttributeMaxDynamicSharedMemorySize, 3*D1_ST);
    cudaFuncSetAttribute(dense1_mma<1>, cudaFuncAttributeMaxDynamicSharedMemorySize, 3*D1_ST);
    cudaFuncSetAttribute(dense1_mma<3>, cudaFuncAttributeMaxDynamicSharedMemorySize, 3*D1_ST);
    cudaFuncSetAttribute(dense3_mma,    cudaFuncAttributeMaxDynamicSharedMemorySize, 3*DA_ST);
    cudaFuncSetAttribute(colsum_mma,    cudaFuncAttributeMaxDynamicSharedMemorySize, 36864);
    cudaFuncSetAttribute(fused_pv,      cudaFuncAttributeMaxDynamicSharedMemorySize,
                         FA_Q + 2*FA_ST);

    prep_kernel<<<9984, 256>>>(x_q, x_e, Wq, Wk, Wv, W0, W1);

    const dim3 gemm_grid(4, 64);

    dense1_mma<0><<<gemm_grid, 256, 3*D1_ST>>>(Xq16, W16, nullptr, nullptr,
                                               Q16, nullptr, nullptr);
    dense1_mma<0><<<gemm_grid, 256, 3*D1_ST>>>(Xe16, W16 + (size_t)D_*D_, nullptr, nullptr,
                                               K16, nullptr, nullptr);
    dense1_mma<3><<<gemm_grid, 256, 3*D1_ST>>>(Xe16, W16 + (size_t)2*D_*D_, nullptr, nullptr,
                                               Vp16, nullptr, nullptr);

    colsum_mma<<<dim3(16, 16, 32), 256, 36864>>>();
    invert_kernel<<<256, 256>>>();
    fused_pv<<<dim3(16, 32), 256, FA_Q + 2*FA_ST>>>();

    dense1_mma<1><<<gemm_grid, 256, 3*D1_ST>>>(O16, W16 + (size_t)3*D_*D_, x_q, b0,
                                               nullptr, Yh, Yl);

    dense3_mma<<<gemm_grid, 256, 3*DA_ST>>>(Yh, Yl, W1h, W1l, b1, out);
}

// round 12
// speedup vs baseline: 1.2657x; 1.0324x over previous
#include <cuda_runtime.h>
#include <cuda_bf16.h>
#include <cstdint>

#define B_   4
#define NQ_  2048
#define D_   512
#define H_   8
#define DH_  64
#define M_   (B_*NQ_)
#define BH_  (B_*H_)

typedef __nv_bfloat16 bf16;

// ---------------- device scratch ----------------
__device__ __align__(16) bf16 g_Xq16[M_*D_];
__device__ __align__(16) bf16 g_Xe16[M_*D_];
__device__ __align__(16) bf16 g_W16[4*D_*D_];            // Wq*log2e, Wk, Wv, W0
__device__ __align__(16) bf16 g_W1h[D_*D_], g_W1l[D_*D_];
__device__ __align__(16) bf16 g_Q16[BH_*NQ_*DH_];        // Q' = X Wq log2e
__device__ __align__(16) bf16 g_K16[BH_*NQ_*DH_];
__device__ __align__(16) bf16 g_Vp16[BH_*NQ_*80];        // V bf16 [k][80]; 64-71=1, 72-79=0
__device__ float g_csum[BH_*NQ_];
__device__ __align__(16) bf16 g_O16[M_*D_];
__device__ __align__(16) bf16 g_Yh[M_*D_], g_Yl[M_*D_];

// ---------------- helpers ----------------
__device__ __forceinline__ uint32_t smem_u32(const void* p) {
    uint32_t a;
    asm("{ .reg .u64 t; cvta.to.shared.u64 t, %1; cvt.u32.u64 %0, t; }" : "=r"(a) : "l"(p));
    return a;
}
__device__ __forceinline__ float ex2f(float x) {
    float y; asm("ex2.approx.ftz.f32 %0, %1;" : "=f"(y) : "f"(x)); return y;
}
__device__ __forceinline__ void mma16816(float* c, const uint32_t* a, const uint32_t* b) {
    asm volatile(
        "mma.sync.aligned.m16n8k16.row.col.f32.bf16.bf16.f32 "
        "{%0,%1,%2,%3}, {%4,%5,%6,%7}, {%8,%9}, {%0,%1,%2,%3};"
        : "+f"(c[0]), "+f"(c[1]), "+f"(c[2]), "+f"(c[3])
        : "r"(a[0]), "r"(a[1]), "r"(a[2]), "r"(a[3]), "r"(b[0]), "r"(b[1]));
}
__device__ __forceinline__ void ldmx4(uint32_t* r, uint32_t a) {
    asm volatile("ldmatrix.sync.aligned.m8n8.x4.shared.b16 {%0,%1,%2,%3}, [%4];"
                 : "=r"(r[0]), "=r"(r[1]), "=r"(r[2]), "=r"(r[3]) : "r"(a));
}
__device__ __forceinline__ void ldmx4t(uint32_t* r, uint32_t a) {
    asm volatile("ldmatrix.sync.aligned.m8n8.x4.trans.shared.b16 {%0,%1,%2,%3}, [%4];"
                 : "=r"(r[0]), "=r"(r[1]), "=r"(r[2]), "=r"(r[3]) : "r"(a));
}
__device__ __forceinline__ void ldmx2t(uint32_t* r, uint32_t a) {
    asm volatile("ldmatrix.sync.aligned.m8n8.x2.trans.shared.b16 {%0,%1}, [%2];"
                 : "=r"(r[0]), "=r"(r[1]) : "r"(a));
}
__device__ __forceinline__ void lda(uint32_t* r, uint32_t base, int row0, int kbyte,
                                    int SB, int lane) {
    uint32_t a = base + (uint32_t)(row0 + (lane & 15)) * SB + kbyte + ((lane >> 4) << 4);
    ldmx4(r, a);
}
__device__ __forceinline__ void ldb_nt(uint32_t* r, uint32_t base, int n0, int kbyte,
                                       int SB, int lane) {
    uint32_t a = base + (uint32_t)(n0 + (lane & 7) + ((lane >> 4) << 3)) * SB
               + kbyte + (((lane >> 3) & 1) << 4);
    ldmx4(r, a);
}
__device__ __forceinline__ void ldb_t(uint32_t* r, uint32_t base, int k0, int n0,
                                      int SB, int lane) {
    uint32_t a = base + (uint32_t)(k0 + (lane & 7) + (((lane >> 3) & 1) << 3)) * SB
               + n0 * 2 + ((lane >> 4) << 4);
    ldmx4t(r, a);
}
__device__ __forceinline__ void ldb_t2(uint32_t* r, uint32_t base, int k0, int n0,
                                       int SB, int lane) {
    uint32_t a = base + (uint32_t)(k0 + (lane & 15)) * SB + n0 * 2;
    ldmx2t(r, a);
}
__device__ __forceinline__ uint32_t pk(bf16 a, bf16 b) {
    return (uint32_t)__bfloat16_as_ushort(a) | ((uint32_t)__bfloat16_as_ushort(b) << 16);
}
__device__ __forceinline__ uint32_t pkf(float a, float b) {
    return pk(__float2bfloat16(a), __float2bfloat16(b));
}
__device__ __forceinline__ uint2 cvt4(float4 v) {
    return make_uint2(pkf(v.x, v.y), pkf(v.z, v.w));
}
__device__ __forceinline__ void split4(float4 v, uint2& h, uint2& l) {
    bf16 h0 = __float2bfloat16(v.x), h1 = __float2bfloat16(v.y);
    bf16 h2 = __float2bfloat16(v.z), h3 = __float2bfloat16(v.w);
    bf16 l0 = __float2bfloat16(v.x - __bfloat162float(h0));
    bf16 l1 = __float2bfloat16(v.y - __bfloat162float(h1));
    bf16 l2 = __float2bfloat16(v.z - __bfloat162float(h2));
    bf16 l3 = __float2bfloat16(v.w - __bfloat162float(h3));
    h = make_uint2(pk(h0, h1), pk(h2, h3));
    l = make_uint2(pk(l0, l1), pk(l2, l3));
}
__device__ __forceinline__ void split2(float a, float b, uint32_t& ph, uint32_t& pl) {
    bf16 ha = __float2bfloat16(a), hb = __float2bfloat16(b);
    bf16 la = __float2bfloat16(a - __bfloat162float(ha));
    bf16 lb = __float2bfloat16(b - __bfloat162float(hb));
    ph = pk(ha, hb); pl = pk(la, lb);
}
__device__ __forceinline__ void cpa16(uint32_t dst, const void* src) {
    asm volatile("cp.async.cg.shared.global [%0], [%1], 16;" :: "r"(dst), "l"(src));
}
#define CP_COMMIT() asm volatile("cp.async.commit_group;" ::: "memory")
#define CP_WAIT1()  asm volatile("cp.async.wait_group 1;"  ::: "memory")
#define CP_WAIT2()  asm volatile("cp.async.wait_group 2;"  ::: "memory")
#define CP_WAIT0()  asm volatile("cp.async.wait_group 0;"  ::: "memory")

// =====================================================================
// prep: conversions (Wq scaled by log2e) + csum zero + V' pad columns.
// =====================================================================
__global__ void __launch_bounds__(256)
prep_kernel(const float* __restrict__ x_q, const float* __restrict__ x_e,
            const float* __restrict__ Wq, const float* __restrict__ Wk,
            const float* __restrict__ Wv, const float* __restrict__ W0,
            const float* __restrict__ W1)
{
    const int b = blockIdx.x, tid = threadIdx.x;
    if (b < 8192) {
        const float* s = (b < 4096) ? x_q : x_e;
        bf16* d = (b < 4096) ? g_Xq16 : g_Xe16;
        const int i = (((b & 4095) * 256) + tid) * 4;
        *(uint2*)&d[i] = cvt4(*(const float4*)&s[i]);
    } else if (b < 9216) {
        const int w = (b - 8192) >> 8;
        const float* s = (w == 0) ? Wq : (w == 1) ? Wk : (w == 2) ? Wv : W0;
        const float sc = (w == 0) ? 1.4426950408889634f : 1.0f;   // log2(e) into Wq
        const int i = ((((b - 8192) & 255) * 256) + tid) * 4;
        float4 v = *(const float4*)&s[i];
        v.x *= sc; v.y *= sc; v.z *= sc; v.w *= sc;
        *(uint2*)&g_W16[(size_t)w * D_ * D_ + i] = cvt4(v);
    } else if (b < 9472) {
        const int i = (((b - 9216) * 256) + tid) * 4;
        float4 v = *(const float4*)&W1[i];
        uint2 h, l; split4(v, h, l);
        *(uint2*)&g_W1h[i] = h; *(uint2*)&g_W1l[i] = l;
    } else if (b < 9728) {
        g_csum[(b - 9472) * 256 + tid] = 0.f;
    } else {
        const int row = (b - 9728) * 256 + tid;            // 65536 rows
        uint4 ones = make_uint4(0x3F803F80u, 0x3F803F80u, 0x3F803F80u, 0x3F803F80u);
        uint4 zero = make_uint4(0u, 0u, 0u, 0u);
        *(uint4*)&g_Vp16[(size_t)row * 80 + 64] = ones;
        *(uint4*)&g_Vp16[(size_t)row * 80 + 72] = zero;
    }
}

// =====================================================================
// dense1: single-plane bf16 GEMM, 3-stage cp.async pipeline.
// MODE 0: head-split bf16 stride 64 (Q,K); MODE 3: head-split stride 80 (V');
// MODE 1: Y = X - (AW + b), split-plane store.
// =====================================================================
#define D1_ST 18944   // A 128*80 + B 32*272
template<int MODE>
__global__ void __launch_bounds__(256, 2)
dense1_mma(const bf16* __restrict__ A16, const bf16* __restrict__ W16,
           const float* __restrict__ X, const float* __restrict__ bias,
           bf16* __restrict__ C16, bf16* __restrict__ Ch, bf16* __restrict__ Cl)
{
    extern __shared__ __align__(16) char dyn[];
    const int tid = threadIdx.x, lane = tid & 31, wid = tid >> 5;
    const int wm = wid >> 2, wn = wid & 3;
    const int m0 = blockIdx.y * 128, n0 = blockIdx.x * 128;
    const uint32_t sb = smem_u32(dyn);

    auto load = [&](int kc, int st) {
        const uint32_t sAs = sb + st * D1_ST;
        const uint32_t sBs = sAs + 10240;
#pragma unroll
        for (int j = 0; j < 2; j++) {
            int cc = tid + 256 * j;
            int row = cc >> 2, off = (cc & 3) * 16, e = (cc & 3) * 8;
            cpa16(sAs + row * 80 + off, A16 + (size_t)(m0 + row) * 512 + kc * 32 + e);
        }
#pragma unroll
        for (int j = 0; j < 2; j++) {
            int cc = tid + 256 * j;
            int row = cc >> 4, off = (cc & 15) * 16, e = (cc & 15) * 8;
            cpa16(sBs + row * 272 + off, W16 + (size_t)(kc * 32 + row) * 512 + n0 + e);
        }
    };

    float acc[4][4][4];
#pragma unroll
    for (int i = 0; i < 4; i++)
#pragma unroll
        for (int j = 0; j < 4; j++)
#pragma unroll
            for (int c = 0; c < 4; c++) acc[i][j][c] = 0.f;

    load(0, 0); CP_COMMIT();
    load(1, 1); CP_COMMIT();
    load(2, 2); CP_COMMIT();

    for (int kc = 0; kc < 16; kc++) {
        CP_WAIT2();
        __syncthreads();
        const int st = kc % 3;
        const uint32_t sAs = sb + st * D1_ST;
        const uint32_t sBs = sAs + 10240;
#pragma unroll
        for (int ks = 0; ks < 2; ks++) {
            uint32_t ah[4][4];
#pragma unroll
            for (int sm = 0; sm < 4; sm++)
                lda(ah[sm], sAs, wm * 64 + sm * 16, ks * 32, 80, lane);
            uint32_t bh[4][2];
#pragma unroll
            for (int p = 0; p < 2; p++) {
                uint32_t r[4];
                ldb_t(r, sBs, ks * 16, wn * 32 + p * 16, 272, lane);
                bh[2*p][0] = r[0]; bh[2*p][1] = r[1];
                bh[2*p+1][0] = r[2]; bh[2*p+1][1] = r[3];
            }
#pragma unroll
            for (int sm = 0; sm < 4; sm++)
#pragma unroll
                for (int sn = 0; sn < 4; sn++)
                    mma16816(acc[sm][sn], ah[sm], bh[sn]);
        }
        __syncthreads();
        if (kc + 3 < 16) load(kc + 3, st);
        CP_COMMIT();
    }

#pragma unroll
    for (int sm = 0; sm < 4; sm++) {
        const int row = m0 + wm * 64 + sm * 16 + (lane >> 2);
#pragma unroll
        for (int sn = 0; sn < 4; sn++) {
            const int col = n0 + wn * 32 + sn * 8 + (lane & 3) * 2;
            const float* a = acc[sm][sn];
            if (MODE == 0 || MODE == 3) {
                const int hh = col >> 6, dd = col & 63;
                const int stride = (MODE == 3) ? 80 : 64;
#pragma unroll
                for (int half = 0; half < 2; half++) {
                    const int gm = row + half * 8;
                    const int bb = gm >> 11, nn = gm & 2047;
                    const size_t idx = ((size_t)(bb * H_ + hh) * NQ_ + nn) * stride + dd;
                    *(uint32_t*)&C16[idx] = pkf(a[half*2], a[half*2+1]);
                }
            } else {   // MODE 1
                float2 bv = *(const float2*)&bias[col];
#pragma unroll
                for (int half = 0; half < 2; half++) {
                    const int gm = row + half * 8;
                    float2 xv = *(const float2*)&X[(size_t)gm * 512 + col];
                    float o0 = xv.x - (a[half*2] + bv.x);
                    float o1 = xv.y - (a[half*2+1] + bv.y);
                    uint32_t ph, pl;
                    split2(o0, o1, ph, pl);
                    *(uint32_t*)&Ch[(size_t)gm * 512 + col] = ph;
                    *(uint32_t*)&Cl[(size_t)gm * 512 + col] = pl;
                }
            }
        }
    }
}

// =====================================================================
// dense3: split-operand GEMM out = Y @ W1 + b1 (3 products), 3-stage.
// =====================================================================
#define DA_ST 35328
__global__ void __launch_bounds__(256, 2)
dense3_mma(const bf16* __restrict__ Ah, const bf16* __restrict__ Al,
           const bf16* __restrict__ Wh, const bf16* __restrict__ Wl,
           const float* __restrict__ bias, float* __restrict__ Cf)
{
    extern __shared__ __align__(16) char dyn[];
    const int tid = threadIdx.x, lane = tid & 31, wid = tid >> 5;
    const int wm = wid >> 2, wn = wid & 3;
    const int m0 = blockIdx.y * 128, n0 = blockIdx.x * 128;
    const uint32_t sb = smem_u32(dyn);

    auto load = [&](int kc, int st) {
        const uint32_t sAs = sb + st * DA_ST;
        const uint32_t sBs = sAs + 18432;
#pragma unroll
        for (int j = 0; j < 2; j++) {
            int cc = tid + 256 * j;
            int row = cc >> 2, off = (cc & 3) * 16, e = (cc & 3) * 8;
            const size_t gi = (size_t)(m0 + row) * 512 + kc * 32 + e;
            cpa16(sAs + row * 144 + off,      Ah + gi);
            cpa16(sAs + row * 144 + 64 + off, Al + gi);
        }
#pragma unroll
        for (int j = 0; j < 2; j++) {
            int cc = tid + 256 * j;
            int row = cc >> 4, off = (cc & 15) * 16, e = (cc & 15) * 8;
            const size_t gi = (size_t)(kc * 32 + row) * 512 + n0 + e;
            cpa16(sBs + row * 528 + off,       Wh + gi);
            cpa16(sBs + row * 528 + 256 + off, Wl + gi);
        }
    };

    float acc[4][4][4];
#pragma unroll
    for (int i = 0; i < 4; i++)
#pragma unroll
        for (int j = 0; j < 4; j++)
#pragma unroll
            for (int c = 0; c < 4; c++) acc[i][j][c] = 0.f;

    load(0, 0); CP_COMMIT();
    load(1, 1); CP_COMMIT();
    load(2, 2); CP_COMMIT();

    for (int kc = 0; kc < 16; kc++) {
        CP_WAIT2();
        __syncthreads();
        const int st = kc % 3;
        const uint32_t sAs = sb + st * DA_ST;
        const uint32_t sBs = sAs + 18432;
#pragma unroll
        for (int ks = 0; ks < 2; ks++) {
            uint32_t ah[4][4], al[4][4];
#pragma unroll
            for (int sm = 0; sm < 4; sm++) {
                lda(ah[sm], sAs, wm * 64 + sm * 16, ks * 32, 144, lane);
                lda(al[sm], sAs, wm * 64 + sm * 16, 64 + ks * 32, 144, lane);
            }
            uint32_t bh[4][2], bl[4][2];
#pragma unroll
            for (int p = 0; p < 2; p++) {
                uint32_t r[4];
                ldb_t(r, sBs, ks * 16, wn * 32 + p * 16, 528, lane);
                bh[2*p][0] = r[0]; bh[2*p][1] = r[1];
                bh[2*p+1][0] = r[2]; bh[2*p+1][1] = r[3];
                ldb_t(r, sBs + 256, ks * 16, wn * 32 + p * 16, 528, lane);
                bl[2*p][0] = r[0]; bl[2*p][1] = r[1];
                bl[2*p+1][0] = r[2]; bl[2*p+1][1] = r[3];
            }
#pragma unroll
            for (int sm = 0; sm < 4; sm++)
#pragma unroll
                for (int sn = 0; sn < 4; sn++) {
                    mma16816(acc[sm][sn], ah[sm], bh[sn]);
                    mma16816(acc[sm][sn], al[sm], bh[sn]);
                    mma16816(acc[sm][sn], ah[sm], bl[sn]);
                }
        }
        __syncthreads();
        if (kc + 3 < 16) load(kc + 3, st);
        CP_COMMIT();
    }

#pragma unroll
    for (int sm = 0; sm < 4; sm++) {
        const int row = m0 + wm * 64 + sm * 16 + (lane >> 2);
#pragma unroll
        for (int sn = 0; sn < 4; sn++) {
            const int col = n0 + wn * 32 + sn * 8 + (lane & 3) * 2;
            const float* a = acc[sm][sn];
            float2 bv = *(const float2*)&bias[col];
#pragma unroll
            for (int half = 0; half < 2; half++) {
                const int gm = row + half * 8;
                *(float2*)&Cf[(size_t)gm * 512 + col] =
                    make_float2(a[half*2] + bv.x, a[half*2+1] + bv.y);
            }
        }
    }
}

// =====================================================================
// Pass 1: colsum = sum over q of exp2(Q' @ K^T) — NO E store.
// =====================================================================
__global__ void __launch_bounds__(256, 2)
colsum_mma()
{
    extern __shared__ __align__(16) char dyn[];
    __shared__ float colsum[128];
    const int tid = threadIdx.x, lane = tid & 31, wid = tid >> 5;
    const int wm = wid >> 2, wn = wid & 3;
    const int bh = blockIdx.z, m0 = blockIdx.y * 128, n0 = blockIdx.x * 128;
    const bf16* __restrict__ Qp = g_Q16 + (size_t)bh * NQ_ * DH_;
    const bf16* __restrict__ Kp = g_K16 + (size_t)bh * NQ_ * DH_;
    const uint32_t sQ = smem_u32(dyn);
    const uint32_t sK = sQ + 18432;

#pragma unroll
    for (int j = 0; j < 4; j++) {
        int cc = tid + 256 * j;
        int row = cc >> 3, off = (cc & 7) * 16, e = (cc & 7) * 8;
        cpa16(sQ + row * 144 + off, Qp + (size_t)(m0 + row) * 64 + e);
        cpa16(sK + row * 144 + off, Kp + (size_t)(n0 + row) * 64 + e);
    }
    CP_COMMIT();
    if (tid < 128) colsum[tid] = 0.f;
    CP_WAIT0();
    __syncthreads();

    float acc[4][4][4];
#pragma unroll
    for (int i = 0; i < 4; i++)
#pragma unroll
        for (int j = 0; j < 4; j++)
#pragma unroll
            for (int c = 0; c < 4; c++) acc[i][j][c] = 0.f;

#pragma unroll
    for (int ks = 0; ks < 4; ks++) {
        uint32_t ah[4][4];
#pragma unroll
        for (int sm = 0; sm < 4; sm++)
            lda(ah[sm], sQ, wm * 64 + sm * 16, ks * 32, 144, lane);
        uint32_t bh_[4][2];
#pragma unroll
        for (int p = 0; p < 2; p++) {
            uint32_t r[4];
            ldb_nt(r, sK, wn * 32 + p * 16, ks * 32, 144, lane);
            bh_[2*p][0] = r[0]; bh_[2*p][1] = r[1];
            bh_[2*p+1][0] = r[2]; bh_[2*p+1][1] = r[3];
        }
#pragma unroll
        for (int sm = 0; sm < 4; sm++)
#pragma unroll
            for (int sn = 0; sn < 4; sn++)
                mma16816(acc[sm][sn], ah[sm], bh_[sn]);
    }

    float cs[4][2];
#pragma unroll
    for (int sn = 0; sn < 4; sn++) { cs[sn][0] = 0.f; cs[sn][1] = 0.f; }
#pragma unroll
    for (int sm = 0; sm < 4; sm++) {
#pragma unroll
        for (int sn = 0; sn < 4; sn++) {
            cs[sn][0] += ex2f(acc[sm][sn][0]) + ex2f(acc[sm][sn][2]);
            cs[sn][1] += ex2f(acc[sm][sn][1]) + ex2f(acc[sm][sn][3]);
        }
    }
#pragma unroll
    for (int o = 4; o <= 16; o <<= 1)
#pragma unroll
        for (int sn = 0; sn < 4; sn++) {
            cs[sn][0] += __shfl_xor_sync(0xffffffffu, cs[sn][0], o);
            cs[sn][1] += __shfl_xor_sync(0xffffffffu, cs[sn][1], o);
        }
    if (lane < 4) {
#pragma unroll
        for (int sn = 0; sn < 4; sn++) {
            atomicAdd(&colsum[wn * 32 + sn * 8 + lane * 2],     cs[sn][0]);
            atomicAdd(&colsum[wn * 32 + sn * 8 + lane * 2 + 1], cs[sn][1]);
        }
    }
    __syncthreads();
    if (tid < 128) atomicAdd(&g_csum[bh * NQ_ + n0 + tid], colsum[tid]);
}

// =====================================================================
// vscale: V' *= 1/csum in place (ones cols become rcs; zeros stay 0).
// 65536 rows x 10 chunks of 8 bf16 (uint4 = 16 bytes each).
// =====================================================================
__global__ void __launch_bounds__(256)
vscale_kernel()
{
    const int idx = blockIdx.x * 256 + threadIdx.x;     // 655360
    const int row = idx / 10, c8 = (idx - row * 10) * 8;
    const float r = 1.f / g_csum[row];
    uint4 v = *(uint4*)&g_Vp16[(size_t)row * 80 + c8];
    const bf16* p = (const bf16*)&v;
    uint32_t* w = (uint32_t*)&v;
#pragma unroll
    for (int i = 0; i < 4; i++) {
        float a = __bfloat162float(p[2*i])     * r;
        float b = __bfloat162float(p[2*i + 1]) * r;
        w[i] = pkf(a, b);
    }
    *(uint4*)&g_Vp16[(size_t)row * 80 + c8] = v;
}

// =====================================================================
// Pass 2: fused attention. S' = Q'K^T, E = exp2(S') in registers,
// C-frags -> PV A-frags, V' pre-scaled by rcs, rs from cols 64-71.
// =====================================================================
#define FA_Q  18432                 // Q 128*144
#define FA_ST 40960                 // K 128*144 + V 128*176
__global__ void __launch_bounds__(256, 2)
fused_pv()
{
    extern __shared__ __align__(16) char dyn[];
    const int tid = threadIdx.x, lane = tid & 31, wid = tid >> 5;
    const int bh = blockIdx.y, q0 = blockIdx.x * 128;
    const int bb = bh >> 3, hh = bh & 7;
    const bf16* __restrict__ Qp = g_Q16 + (size_t)bh * NQ_ * DH_;
    const bf16* __restrict__ Kp = g_K16 + (size_t)bh * NQ_ * DH_;
    const bf16* __restrict__ Vp = g_Vp16 + (size_t)bh * NQ_ * 80;
    const uint32_t sb = smem_u32(dyn);
    const uint32_t sQ = sb;

    auto loadKV = [&](int kc, int st) {
        const uint32_t base = sb + FA_Q + st * FA_ST;
        const uint32_t sK = base, sV = base + 18432;
#pragma unroll
        for (int j = 0; j < 4; j++) {
            int cc = tid + 256 * j;
            int row = cc >> 3, off = (cc & 7) * 16, e = (cc & 7) * 8;
            cpa16(sK + row * 144 + off, Kp + (size_t)(kc * 128 + row) * 64 + e);
        }
#pragma unroll
        for (int j = 0; j < 5; j++) {
            int cc = tid + 256 * j;
            int row = cc / 10, m = cc - row * 10;
            cpa16(sV + row * 176 + m * 16, Vp + (size_t)(kc * 128 + row) * 80 + m * 8);
        }
    };

#pragma unroll
    for (int j = 0; j < 4; j++) {
        int cc = tid + 256 * j;
        int row = cc >> 3, off = (cc & 7) * 16, e = (cc & 7) * 8;
        cpa16(sQ + row * 144 + off, Qp + (size_t)(q0 + row) * 64 + e);
    }
    loadKV(0, 0); CP_COMMIT();
    loadKV(1, 1); CP_COMMIT();

    float pacc[9][4];
#pragma unroll
    for (int j = 0; j < 9; j++)
#pragma unroll
        for (int c = 0; c < 4; c++) pacc[j][c] = 0.f;

    uint32_t Qa[4][4];
    bool qloaded = false;

    for (int kc = 0; kc < 16; kc++) {
        CP_WAIT1();
        __syncthreads();
        const uint32_t base = sb + FA_Q + (kc & 1) * FA_ST;
        const uint32_t sK = base, sV = base + 18432;
        if (!qloaded) {
#pragma unroll
            for (int ks = 0; ks < 4; ks++)
                lda(Qa[ks], sQ, wid * 16, ks * 32, 144, lane);
            qloaded = true;
        }
#pragma unroll
        for (int h = 0; h < 2; h++) {
            float qk[8][4];
#pragma unroll
            for (int j = 0; j < 8; j++)
#pragma unroll
                for (int c = 0; c < 4; c++) qk[j][c] = 0.f;
#pragma unroll
            for (int ks = 0; ks < 4; ks++) {
#pragma unroll
                for (int p = 0; p < 4; p++) {
                    uint32_t r[4];
                    ldb_nt(r, sK, h * 64 + p * 16, ks * 32, 144, lane);
                    mma16816(qk[2*p],   Qa[ks], r);
                    mma16816(qk[2*p+1], Qa[ks], r + 2);
                }
            }
#pragma unroll
            for (int kp = 0; kp < 4; kp++) {
                const float* s0 = qk[2*kp];
                const float* s1 = qk[2*kp+1];
                uint32_t pa[4];
                pa[0] = pkf(ex2f(s0[0]), ex2f(s0[1]));
                pa[1] = pkf(ex2f(s0[2]), ex2f(s0[3]));
                pa[2] = pkf(ex2f(s1[0]), ex2f(s1[1]));
                pa[3] = pkf(ex2f(s1[2]), ex2f(s1[3]));
                const int k0 = h * 64 + kp * 16;
                uint32_t v0[4], v1[4], v2[4], v3[4], v4[2];
                ldb_t(v0, sV, k0, 0,  176, lane);
                ldb_t(v1, sV, k0, 16, 176, lane);
                ldb_t(v2, sV, k0, 32, 176, lane);
                ldb_t(v3, sV, k0, 48, 176, lane);
                ldb_t2(v4, sV, k0, 64, 176, lane);
                mma16816(pacc[0], pa, v0);
                mma16816(pacc[1], pa, v0 + 2);
                mma16816(pacc[2], pa, v1);
                mma16816(pacc[3], pa, v1 + 2);
                mma16816(pacc[4], pa, v2);
                mma16816(pacc[5], pa, v2 + 2);
                mma16816(pacc[6], pa, v3);
                mma16816(pacc[7], pa, v3 + 2);
                mma16816(pacc[8], pa, v4);
            }
        }
        __syncthreads();
        if (kc + 2 < 16) loadKV(kc + 2, kc & 1);
        CP_COMMIT();
    }

    const float inv0 = 1.f / (1e-12f + pacc[8][0]);
    const float inv1 = 1.f / (1e-12f + pacc[8][2]);
    const int gq = q0 + wid * 16 + (lane >> 2);
#pragma unroll
    for (int sn = 0; sn < 8; sn++) {
        const int col = sn * 8 + (lane & 3) * 2;
        size_t idx = (size_t)(bb * NQ_ + gq) * D_ + hh * DH_ + col;
        *(uint32_t*)&g_O16[idx] = pkf(pacc[sn][0] * inv0, pacc[sn][1] * inv0);
        idx = (size_t)(bb * NQ_ + gq + 8) * D_ + hh * DH_ + col;
        *(uint32_t*)&g_O16[idx] = pkf(pacc[sn][2] * inv1, pacc[sn][3] * inv1);
    }
}

// =====================================================================
// Launch
// =====================================================================
extern "C" void kernel_launch(void* const* d_in, const int* in_sizes, int n_in,
                              void* d_out, int out_size)
{
    const float* x_q = (const float*)d_in[0];
    const float* x_e = (const float*)d_in[1];
    const float* Wq  = (const float*)d_in[2];
    const float* Wk  = (const float*)d_in[3];
    const float* Wv  = (const float*)d_in[4];
    const float* W0  = (const float*)d_in[5];
    const float* b0  = (const float*)d_in[6];
    const float* W1  = (const float*)d_in[7];
    const float* b1  = (const float*)d_in[8];
    float* out = (float*)d_out;

    bf16 *Xq16, *Xe16, *W16, *W1h, *W1l, *Q16, *K16, *Vp16, *O16, *Yh, *Yl;
    cudaGetSymbolAddress((void**)&Xq16, g_Xq16);
    cudaGetSymbolAddress((void**)&Xe16, g_Xe16);
    cudaGetSymbolAddress((void**)&W16,  g_W16);
    cudaGetSymbolAddress((void**)&W1h,  g_W1h);
    cudaGetSymbolAddress((void**)&W1l,  g_W1l);
    cudaGetSymbolAddress((void**)&Q16,  g_Q16);
    cudaGetSymbolAddress((void**)&K16,  g_K16);
    cudaGetSymbolAddress((void**)&Vp16, g_Vp16);
    cudaGetSymbolAddress((void**)&O16,  g_O16);
    cudaGetSymbolAddress((void**)&Yh,   g_Yh);
    cudaGetSymbolAddress((void**)&Yl,   g_Yl);

    cudaFuncSetAttribute(dense1_mma<0>, cudaFuncAttributeMaxDynamicSharedMemorySize, 3*D1_ST);
    cudaFuncSetAttribute(dense1_mma<1>, cudaFuncAttributeMaxDynamicSharedMemorySize, 3*D1_ST);
    cudaFuncSetAttribute(dense1_mma<3>, cudaFuncAttributeMaxDynamicSharedMemorySize, 3*D1_ST);
    cudaFuncSetAttribute(dense3_mma,    cudaFuncAttributeMaxDynamicSharedMemorySize, 3*DA_ST);
    cudaFuncSetAttribute(colsum_mma,    cudaFuncAttributeMaxDynamicSharedMemorySize, 36864);
    cudaFuncSetAttribute(fused_pv,      cudaFuncAttributeMaxDynamicSharedMemorySize,
                         FA_Q + 2*FA_ST);

    prep_kernel<<<9984, 256>>>(x_q, x_e, Wq, Wk, Wv, W0, W1);

    const dim3 gemm_grid(4, 64);

    dense1_mma<0><<<gemm_grid, 256, 3*D1_ST>>>(Xq16, W16, nullptr, nullptr,
                                               Q16, nullptr, nullptr);
    dense1_mma<0><<<gemm_grid, 256, 3*D1_ST>>>(Xe16, W16 + (size_t)D_*D_, nullptr, nullptr,
                                               K16, nullptr, nullptr);
    dense1_mma<3><<<gemm_grid, 256, 3*D1_ST>>>(Xe16, W16 + (size_t)2*D_*D_, nullptr, nullptr,
                                               Vp16, nullptr, nullptr);

    colsum_mma<<<dim3(16, 16, 32), 256, 36864>>>();
    vscale_kernel<<<2560, 256>>>();
    fused_pv<<<dim3(16, 32), 256, FA_Q + 2*FA_ST>>>();

    dense1_mma<1><<<gemm_grid, 256, 3*D1_ST>>>(O16, W16 + (size_t)3*D_*D_, x_q, b0,
                                               nullptr, Yh, Yl);

    dense3_mma<<<gemm_grid, 256, 3*DA_ST>>>(Yh, Yl, W1h, W1l, b1, out);
}

// round 13
// speedup vs baseline: 1.3059x; 1.0317x over previous
#include <cuda_runtime.h>
#include <cuda_bf16.h>
#include <cstdint>

#define B_   4
#define NQ_  2048
#define D_   512
#define H_   8
#define DH_  64
#define M_   (B_*NQ_)
#define BH_  (B_*H_)

typedef __nv_bfloat16 bf16;

// ---------------- device scratch ----------------
__device__ __align__(16) bf16 g_Xq16[M_*D_];
__device__ __align__(16) bf16 g_Xe16[M_*D_];
__device__ __align__(16) bf16 g_W16[4*D_*D_];            // Wq*log2e, Wk, Wv, W0
__device__ __align__(16) bf16 g_W1h[D_*D_], g_W1l[D_*D_];
__device__ __align__(16) bf16 g_Q16[BH_*NQ_*DH_];        // Q' = X Wq log2e
__device__ __align__(16) bf16 g_K16[BH_*NQ_*DH_];
__device__ __align__(16) bf16 g_Vp16[BH_*NQ_*80];        // V bf16 [k][80]; 64-71=1, 72-79=0
__device__ float g_csum[BH_*NQ_];
__device__ __align__(16) bf16 g_O16[M_*D_];
__device__ __align__(16) bf16 g_Yh[M_*D_], g_Yl[M_*D_];

// ---------------- helpers ----------------
__device__ __forceinline__ uint32_t smem_u32(const void* p) {
    uint32_t a;
    asm("{ .reg .u64 t; cvta.to.shared.u64 t, %1; cvt.u32.u64 %0, t; }" : "=r"(a) : "l"(p));
    return a;
}
__device__ __forceinline__ float ex2f(float x) {
    float y; asm("ex2.approx.ftz.f32 %0, %1;" : "=f"(y) : "f"(x)); return y;
}
__device__ __forceinline__ void mma16816(float* c, const uint32_t* a, const uint32_t* b) {
    asm volatile(
        "mma.sync.aligned.m16n8k16.row.col.f32.bf16.bf16.f32 "
        "{%0,%1,%2,%3}, {%4,%5,%6,%7}, {%8,%9}, {%0,%1,%2,%3};"
        : "+f"(c[0]), "+f"(c[1]), "+f"(c[2]), "+f"(c[3])
        : "r"(a[0]), "r"(a[1]), "r"(a[2]), "r"(a[3]), "r"(b[0]), "r"(b[1]));
}
__device__ __forceinline__ void ldmx4(uint32_t* r, uint32_t a) {
    asm volatile("ldmatrix.sync.aligned.m8n8.x4.shared.b16 {%0,%1,%2,%3}, [%4];"
                 : "=r"(r[0]), "=r"(r[1]), "=r"(r[2]), "=r"(r[3]) : "r"(a));
}
__device__ __forceinline__ void ldmx4t(uint32_t* r, uint32_t a) {
    asm volatile("ldmatrix.sync.aligned.m8n8.x4.trans.shared.b16 {%0,%1,%2,%3}, [%4];"
                 : "=r"(r[0]), "=r"(r[1]), "=r"(r[2]), "=r"(r[3]) : "r"(a));
}
__device__ __forceinline__ void ldmx2t(uint32_t* r, uint32_t a) {
    asm volatile("ldmatrix.sync.aligned.m8n8.x2.trans.shared.b16 {%0,%1}, [%2];"
                 : "=r"(r[0]), "=r"(r[1]) : "r"(a));
}
__device__ __forceinline__ void lda(uint32_t* r, uint32_t base, int row0, int kbyte,
                                    int SB, int lane) {
    uint32_t a = base + (uint32_t)(row0 + (lane & 15)) * SB + kbyte + ((lane >> 4) << 4);
    ldmx4(r, a);
}
__device__ __forceinline__ void ldb_nt(uint32_t* r, uint32_t base, int n0, int kbyte,
                                       int SB, int lane) {
    uint32_t a = base + (uint32_t)(n0 + (lane & 7) + ((lane >> 4) << 3)) * SB
               + kbyte + (((lane >> 3) & 1) << 4);
    ldmx4(r, a);
}
__device__ __forceinline__ void ldb_t(uint32_t* r, uint32_t base, int k0, int n0,
                                      int SB, int lane) {
    uint32_t a = base + (uint32_t)(k0 + (lane & 7) + (((lane >> 3) & 1) << 3)) * SB
               + n0 * 2 + ((lane >> 4) << 4);
    ldmx4t(r, a);
}
__device__ __forceinline__ void ldb_t2(uint32_t* r, uint32_t base, int k0, int n0,
                                       int SB, int lane) {
    uint32_t a = base + (uint32_t)(k0 + (lane & 15)) * SB + n0 * 2;
    ldmx2t(r, a);
}
__device__ __forceinline__ uint32_t pk(bf16 a, bf16 b) {
    return (uint32_t)__bfloat16_as_ushort(a) | ((uint32_t)__bfloat16_as_ushort(b) << 16);
}
__device__ __forceinline__ uint32_t pkf(float a, float b) {
    return pk(__float2bfloat16(a), __float2bfloat16(b));
}
__device__ __forceinline__ uint2 cvt4(float4 v) {
    return make_uint2(pkf(v.x, v.y), pkf(v.z, v.w));
}
__device__ __forceinline__ void split4(float4 v, uint2& h, uint2& l) {
    bf16 h0 = __float2bfloat16(v.x), h1 = __float2bfloat16(v.y);
    bf16 h2 = __float2bfloat16(v.z), h3 = __float2bfloat16(v.w);
    bf16 l0 = __float2bfloat16(v.x - __bfloat162float(h0));
    bf16 l1 = __float2bfloat16(v.y - __bfloat162float(h1));
    bf16 l2 = __float2bfloat16(v.z - __bfloat162float(h2));
    bf16 l3 = __float2bfloat16(v.w - __bfloat162float(h3));
    h = make_uint2(pk(h0, h1), pk(h2, h3));
    l = make_uint2(pk(l0, l1), pk(l2, l3));
}
__device__ __forceinline__ void split2(float a, float b, uint32_t& ph, uint32_t& pl) {
    bf16 ha = __float2bfloat16(a), hb = __float2bfloat16(b);
    bf16 la = __float2bfloat16(a - __bfloat162float(ha));
    bf16 lb = __float2bfloat16(b - __bfloat162float(hb));
    ph = pk(ha, hb); pl = pk(la, lb);
}
__device__ __forceinline__ void cpa16(uint32_t dst, const void* src) {
    asm volatile("cp.async.cg.shared.global [%0], [%1], 16;" :: "r"(dst), "l"(src));
}
#define CP_COMMIT() asm volatile("cp.async.commit_group;" ::: "memory")
#define CP_WAIT1()  asm volatile("cp.async.wait_group 1;"  ::: "memory")
#define CP_WAIT0()  asm volatile("cp.async.wait_group 0;"  ::: "memory")

// =====================================================================
// prep: conversions (Wq scaled by log2e) + csum zero + V' pad columns.
// =====================================================================
__global__ void __launch_bounds__(256)
prep_kernel(const float* __restrict__ x_q, const float* __restrict__ x_e,
            const float* __restrict__ Wq, const float* __restrict__ Wk,
            const float* __restrict__ Wv, const float* __restrict__ W0,
            const float* __restrict__ W1)
{
    const int b = blockIdx.x, tid = threadIdx.x;
    if (b < 8192) {
        const float* s = (b < 4096) ? x_q : x_e;
        bf16* d = (b < 4096) ? g_Xq16 : g_Xe16;
        const int i = (((b & 4095) * 256) + tid) * 4;
        *(uint2*)&d[i] = cvt4(*(const float4*)&s[i]);
    } else if (b < 9216) {
        const int w = (b - 8192) >> 8;
        const float* s = (w == 0) ? Wq : (w == 1) ? Wk : (w == 2) ? Wv : W0;
        const float sc = (w == 0) ? 1.4426950408889634f : 1.0f;   // log2(e) into Wq
        const int i = ((((b - 8192) & 255) * 256) + tid) * 4;
        float4 v = *(const float4*)&s[i];
        v.x *= sc; v.y *= sc; v.z *= sc; v.w *= sc;
        *(uint2*)&g_W16[(size_t)w * D_ * D_ + i] = cvt4(v);
    } else if (b < 9472) {
        const int i = (((b - 9216) * 256) + tid) * 4;
        float4 v = *(const float4*)&W1[i];
        uint2 h, l; split4(v, h, l);
        *(uint2*)&g_W1h[i] = h; *(uint2*)&g_W1l[i] = l;
    } else if (b < 9728) {
        g_csum[(b - 9472) * 256 + tid] = 0.f;
    } else {
        const int row = (b - 9728) * 256 + tid;            // 65536 rows
        uint4 ones = make_uint4(0x3F803F80u, 0x3F803F80u, 0x3F803F80u, 0x3F803F80u);
        uint4 zero = make_uint4(0u, 0u, 0u, 0u);
        *(uint4*)&g_Vp16[(size_t)row * 80 + 64] = ones;
        *(uint4*)&g_Vp16[(size_t)row * 80 + 72] = zero;
    }
}

// =====================================================================
// proj: merged Q/K/V projections, blockIdx.z selects the problem.
// Single-plane bf16, 3-stage single-barrier pipeline.
// =====================================================================
#define D1_ST 18944   // A 128*80 + B 32*272
__global__ void __launch_bounds__(256, 2)
proj_mma()
{
    extern __shared__ __align__(16) char dyn[];
    const int tid = threadIdx.x, lane = tid & 31, wid = tid >> 5;
    const int wm = wid >> 2, wn = wid & 3;
    const int m0 = blockIdx.y * 128, n0 = blockIdx.x * 128;
    const int z = blockIdx.z;
    const bf16* __restrict__ A16 = (z == 0) ? g_Xq16 : g_Xe16;
    const bf16* __restrict__ W16 = g_W16 + (size_t)z * D_ * D_;
    bf16* __restrict__ C16 = (z == 0) ? g_Q16 : ((z == 1) ? g_K16 : g_Vp16);
    const int cstride = (z == 2) ? 80 : 64;
    const uint32_t sb = smem_u32(dyn);

    auto load = [&](int kc, int st) {
        const uint32_t sAs = sb + st * D1_ST;
        const uint32_t sBs = sAs + 10240;
#pragma unroll
        for (int j = 0; j < 2; j++) {
            int cc = tid + 256 * j;
            int row = cc >> 2, off = (cc & 3) * 16, e = (cc & 3) * 8;
            cpa16(sAs + row * 80 + off, A16 + (size_t)(m0 + row) * 512 + kc * 32 + e);
        }
#pragma unroll
        for (int j = 0; j < 2; j++) {
            int cc = tid + 256 * j;
            int row = cc >> 4, off = (cc & 15) * 16, e = (cc & 15) * 8;
            cpa16(sBs + row * 272 + off, W16 + (size_t)(kc * 32 + row) * 512 + n0 + e);
        }
    };

    float acc[4][4][4];
#pragma unroll
    for (int i = 0; i < 4; i++)
#pragma unroll
        for (int j = 0; j < 4; j++)
#pragma unroll
            for (int c = 0; c < 4; c++) acc[i][j][c] = 0.f;

    load(0, 0); CP_COMMIT();
    load(1, 1); CP_COMMIT();

    for (int kc = 0; kc < 16; kc++) {
        CP_WAIT1();
        __syncthreads();
        if (kc + 2 < 16) load(kc + 2, (kc + 2) % 3);
        CP_COMMIT();
        const uint32_t sAs = sb + (kc % 3) * D1_ST;
        const uint32_t sBs = sAs + 10240;
#pragma unroll
        for (int ks = 0; ks < 2; ks++) {
            uint32_t ah[4][4];
#pragma unroll
            for (int sm = 0; sm < 4; sm++)
                lda(ah[sm], sAs, wm * 64 + sm * 16, ks * 32, 80, lane);
            uint32_t bh[4][2];
#pragma unroll
            for (int p = 0; p < 2; p++) {
                uint32_t r[4];
                ldb_t(r, sBs, ks * 16, wn * 32 + p * 16, 272, lane);
                bh[2*p][0] = r[0]; bh[2*p][1] = r[1];
                bh[2*p+1][0] = r[2]; bh[2*p+1][1] = r[3];
            }
#pragma unroll
            for (int sm = 0; sm < 4; sm++)
#pragma unroll
                for (int sn = 0; sn < 4; sn++)
                    mma16816(acc[sm][sn], ah[sm], bh[sn]);
        }
    }

#pragma unroll
    for (int sm = 0; sm < 4; sm++) {
        const int row = m0 + wm * 64 + sm * 16 + (lane >> 2);
#pragma unroll
        for (int sn = 0; sn < 4; sn++) {
            const int col = n0 + wn * 32 + sn * 8 + (lane & 3) * 2;
            const float* a = acc[sm][sn];
            const int hh = col >> 6, dd = col & 63;
#pragma unroll
            for (int half = 0; half < 2; half++) {
                const int gm = row + half * 8;
                const int bb = gm >> 11, nn = gm & 2047;
                const size_t idx = ((size_t)(bb * H_ + hh) * NQ_ + nn) * cstride + dd;
                *(uint32_t*)&C16[idx] = pkf(a[half*2], a[half*2+1]);
            }
        }
    }
}

// =====================================================================
// denseY: Y = X - (O @ W0 + b0), single-plane operands, split-plane out.
// 3-stage single-barrier pipeline.
// =====================================================================
__global__ void __launch_bounds__(256, 2)
denseY_mma(const bf16* __restrict__ A16, const bf16* __restrict__ W16,
           const float* __restrict__ X, const float* __restrict__ bias,
           bf16* __restrict__ Ch, bf16* __restrict__ Cl)
{
    extern __shared__ __align__(16) char dyn[];
    const int tid = threadIdx.x, lane = tid & 31, wid = tid >> 5;
    const int wm = wid >> 2, wn = wid & 3;
    const int m0 = blockIdx.y * 128, n0 = blockIdx.x * 128;
    const uint32_t sb = smem_u32(dyn);

    auto load = [&](int kc, int st) {
        const uint32_t sAs = sb + st * D1_ST;
        const uint32_t sBs = sAs + 10240;
#pragma unroll
        for (int j = 0; j < 2; j++) {
            int cc = tid + 256 * j;
            int row = cc >> 2, off = (cc & 3) * 16, e = (cc & 3) * 8;
            cpa16(sAs + row * 80 + off, A16 + (size_t)(m0 + row) * 512 + kc * 32 + e);
        }
#pragma unroll
        for (int j = 0; j < 2; j++) {
            int cc = tid + 256 * j;
            int row = cc >> 4, off = (cc & 15) * 16, e = (cc & 15) * 8;
            cpa16(sBs + row * 272 + off, W16 + (size_t)(kc * 32 + row) * 512 + n0 + e);
        }
    };

    float acc[4][4][4];
#pragma unroll
    for (int i = 0; i < 4; i++)
#pragma unroll
        for (int j = 0; j < 4; j++)
#pragma unroll
            for (int c = 0; c < 4; c++) acc[i][j][c] = 0.f;

    load(0, 0); CP_COMMIT();
    load(1, 1); CP_COMMIT();

    for (int kc = 0; kc < 16; kc++) {
        CP_WAIT1();
        __syncthreads();
        if (kc + 2 < 16) load(kc + 2, (kc + 2) % 3);
        CP_COMMIT();
        const uint32_t sAs = sb + (kc % 3) * D1_ST;
        const uint32_t sBs = sAs + 10240;
#pragma unroll
        for (int ks = 0; ks < 2; ks++) {
            uint32_t ah[4][4];
#pragma unroll
            for (int sm = 0; sm < 4; sm++)
                lda(ah[sm], sAs, wm * 64 + sm * 16, ks * 32, 80, lane);
            uint32_t bh[4][2];
#pragma unroll
            for (int p = 0; p < 2; p++) {
                uint32_t r[4];
                ldb_t(r, sBs, ks * 16, wn * 32 + p * 16, 272, lane);
                bh[2*p][0] = r[0]; bh[2*p][1] = r[1];
                bh[2*p+1][0] = r[2]; bh[2*p+1][1] = r[3];
            }
#pragma unroll
            for (int sm = 0; sm < 4; sm++)
#pragma unroll
                for (int sn = 0; sn < 4; sn++)
                    mma16816(acc[sm][sn], ah[sm], bh[sn]);
        }
    }

#pragma unroll
    for (int sm = 0; sm < 4; sm++) {
        const int row = m0 + wm * 64 + sm * 16 + (lane >> 2);
#pragma unroll
        for (int sn = 0; sn < 4; sn++) {
            const int col = n0 + wn * 32 + sn * 8 + (lane & 3) * 2;
            const float* a = acc[sm][sn];
            float2 bv = *(const float2*)&bias[col];
#pragma unroll
            for (int half = 0; half < 2; half++) {
                const int gm = row + half * 8;
                float2 xv = *(const float2*)&X[(size_t)gm * 512 + col];
                float o0 = xv.x - (a[half*2] + bv.x);
                float o1 = xv.y - (a[half*2+1] + bv.y);
                uint32_t ph, pl;
                split2(o0, o1, ph, pl);
                *(uint32_t*)&Ch[(size_t)gm * 512 + col] = ph;
                *(uint32_t*)&Cl[(size_t)gm * 512 + col] = pl;
            }
        }
    }
}

// =====================================================================
// dense3: split-operand GEMM out = Y @ W1 + b1 (3 products), 3-stage
// single-barrier pipeline.
// =====================================================================
#define DA_ST 35328
__global__ void __launch_bounds__(256, 2)
dense3_mma(const bf16* __restrict__ Ah, const bf16* __restrict__ Al,
           const bf16* __restrict__ Wh, const bf16* __restrict__ Wl,
           const float* __restrict__ bias, float* __restrict__ Cf)
{
    extern __shared__ __align__(16) char dyn[];
    const int tid = threadIdx.x, lane = tid & 31, wid = tid >> 5;
    const int wm = wid >> 2, wn = wid & 3;
    const int m0 = blockIdx.y * 128, n0 = blockIdx.x * 128;
    const uint32_t sb = smem_u32(dyn);

    auto load = [&](int kc, int st) {
        const uint32_t sAs = sb + st * DA_ST;
        const uint32_t sBs = sAs + 18432;
#pragma unroll
        for (int j = 0; j < 2; j++) {
            int cc = tid + 256 * j;
            int row = cc >> 2, off = (cc & 3) * 16, e = (cc & 3) * 8;
            const size_t gi = (size_t)(m0 + row) * 512 + kc * 32 + e;
            cpa16(sAs + row * 144 + off,      Ah + gi);
            cpa16(sAs + row * 144 + 64 + off, Al + gi);
        }
#pragma unroll
        for (int j = 0; j < 2; j++) {
            int cc = tid + 256 * j;
            int row = cc >> 4, off = (cc & 15) * 16, e = (cc & 15) * 8;
            const size_t gi = (size_t)(kc * 32 + row) * 512 + n0 + e;
            cpa16(sBs + row * 528 + off,       Wh + gi);
            cpa16(sBs + row * 528 + 256 + off, Wl + gi);
        }
    };

    float acc[4][4][4];
#pragma unroll
    for (int i = 0; i < 4; i++)
#pragma unroll
        for (int j = 0; j < 4; j++)
#pragma unroll
            for (int c = 0; c < 4; c++) acc[i][j][c] = 0.f;

    load(0, 0); CP_COMMIT();
    load(1, 1); CP_COMMIT();

    for (int kc = 0; kc < 16; kc++) {
        CP_WAIT1();
        __syncthreads();
        if (kc + 2 < 16) load(kc + 2, (kc + 2) % 3);
        CP_COMMIT();
        const uint32_t sAs = sb + (kc % 3) * DA_ST;
        const uint32_t sBs = sAs + 18432;
#pragma unroll
        for (int ks = 0; ks < 2; ks++) {
            uint32_t ah[4][4], al[4][4];
#pragma unroll
            for (int sm = 0; sm < 4; sm++) {
                lda(ah[sm], sAs, wm * 64 + sm * 16, ks * 32, 144, lane);
                lda(al[sm], sAs, wm * 64 + sm * 16, 64 + ks * 32, 144, lane);
            }
            uint32_t bh[4][2], bl[4][2];
#pragma unroll
            for (int p = 0; p < 2; p++) {
                uint32_t r[4];
                ldb_t(r, sBs, ks * 16, wn * 32 + p * 16, 528, lane);
                bh[2*p][0] = r[0]; bh[2*p][1] = r[1];
                bh[2*p+1][0] = r[2]; bh[2*p+1][1] = r[3];
                ldb_t(r, sBs + 256, ks * 16, wn * 32 + p * 16, 528, lane);
                bl[2*p][0] = r[0]; bl[2*p][1] = r[1];
                bl[2*p+1][0] = r[2]; bl[2*p+1][1] = r[3];
            }
#pragma unroll
            for (int sm = 0; sm < 4; sm++)
#pragma unroll
                for (int sn = 0; sn < 4; sn++) {
                    mma16816(acc[sm][sn], ah[sm], bh[sn]);
                    mma16816(acc[sm][sn], al[sm], bh[sn]);
                    mma16816(acc[sm][sn], ah[sm], bl[sn]);
                }
        }
    }

#pragma unroll
    for (int sm = 0; sm < 4; sm++) {
        const int row = m0 + wm * 64 + sm * 16 + (lane >> 2);
#pragma unroll
        for (int sn = 0; sn < 4; sn++) {
            const int col = n0 + wn * 32 + sn * 8 + (lane & 3) * 2;
            const float* a = acc[sm][sn];
            float2 bv = *(const float2*)&bias[col];
#pragma unroll
            for (int half = 0; half < 2; half++) {
                const int gm = row + half * 8;
                *(float2*)&Cf[(size_t)gm * 512 + col] =
                    make_float2(a[half*2] + bv.x, a[half*2+1] + bv.y);
            }
        }
    }
}

// =====================================================================
// Pass 1: colsum = sum over q of exp2(Q' @ K^T) — NO E store.
// =====================================================================
__global__ void __launch_bounds__(256, 2)
colsum_mma()
{
    extern __shared__ __align__(16) char dyn[];
    __shared__ float colsum[128];
    const int tid = threadIdx.x, lane = tid & 31, wid = tid >> 5;
    const int wm = wid >> 2, wn = wid & 3;
    const int bh = blockIdx.z, m0 = blockIdx.y * 128, n0 = blockIdx.x * 128;
    const bf16* __restrict__ Qp = g_Q16 + (size_t)bh * NQ_ * DH_;
    const bf16* __restrict__ Kp = g_K16 + (size_t)bh * NQ_ * DH_;
    const uint32_t sQ = smem_u32(dyn);
    const uint32_t sK = sQ + 18432;

#pragma unroll
    for (int j = 0; j < 4; j++) {
        int cc = tid + 256 * j;
        int row = cc >> 3, off = (cc & 7) * 16, e = (cc & 7) * 8;
        cpa16(sQ + row * 144 + off, Qp + (size_t)(m0 + row) * 64 + e);
        cpa16(sK + row * 144 + off, Kp + (size_t)(n0 + row) * 64 + e);
    }
    CP_COMMIT();
    if (tid < 128) colsum[tid] = 0.f;
    CP_WAIT0();
    __syncthreads();

    float acc[4][4][4];
#pragma unroll
    for (int i = 0; i < 4; i++)
#pragma unroll
        for (int j = 0; j < 4; j++)
#pragma unroll
            for (int c = 0; c < 4; c++) acc[i][j][c] = 0.f;

#pragma unroll
    for (int ks = 0; ks < 4; ks++) {
        uint32_t ah[4][4];
#pragma unroll
        for (int sm = 0; sm < 4; sm++)
            lda(ah[sm], sQ, wm * 64 + sm * 16, ks * 32, 144, lane);
        uint32_t bh_[4][2];
#pragma unroll
        for (int p = 0; p < 2; p++) {
            uint32_t r[4];
            ldb_nt(r, sK, wn * 32 + p * 16, ks * 32, 144, lane);
            bh_[2*p][0] = r[0]; bh_[2*p][1] = r[1];
            bh_[2*p+1][0] = r[2]; bh_[2*p+1][1] = r[3];
        }
#pragma unroll
        for (int sm = 0; sm < 4; sm++)
#pragma unroll
            for (int sn = 0; sn < 4; sn++)
                mma16816(acc[sm][sn], ah[sm], bh_[sn]);
    }

    float cs[4][2];
#pragma unroll
    for (int sn = 0; sn < 4; sn++) { cs[sn][0] = 0.f; cs[sn][1] = 0.f; }
#pragma unroll
    for (int sm = 0; sm < 4; sm++) {
#pragma unroll
        for (int sn = 0; sn < 4; sn++) {
            cs[sn][0] += ex2f(acc[sm][sn][0]) + ex2f(acc[sm][sn][2]);
            cs[sn][1] += ex2f(acc[sm][sn][1]) + ex2f(acc[sm][sn][3]);
        }
    }
#pragma unroll
    for (int o = 4; o <= 16; o <<= 1)
#pragma unroll
        for (int sn = 0; sn < 4; sn++) {
            cs[sn][0] += __shfl_xor_sync(0xffffffffu, cs[sn][0], o);
            cs[sn][1] += __shfl_xor_sync(0xffffffffu, cs[sn][1], o);
        }
    if (lane < 4) {
#pragma unroll
        for (int sn = 0; sn < 4; sn++) {
            atomicAdd(&colsum[wn * 32 + sn * 8 + lane * 2],     cs[sn][0]);
            atomicAdd(&colsum[wn * 32 + sn * 8 + lane * 2 + 1], cs[sn][1]);
        }
    }
    __syncthreads();
    if (tid < 128) atomicAdd(&g_csum[bh * NQ_ + n0 + tid], colsum[tid]);
}

// =====================================================================
// vscale: V' *= 1/csum in place (ones cols become rcs; zeros stay 0).
// =====================================================================
__global__ void __launch_bounds__(256)
vscale_kernel()
{
    const int idx = blockIdx.x * 256 + threadIdx.x;     // 655360
    const int row = idx / 10, c8 = (idx - row * 10) * 8;
    const float r = 1.f / g_csum[row];
    uint4 v = *(uint4*)&g_Vp16[(size_t)row * 80 + c8];
    const bf16* p = (const bf16*)&v;
    uint32_t* w = (uint32_t*)&v;
#pragma unroll
    for (int i = 0; i < 4; i++) {
        float a = __bfloat162float(p[2*i])     * r;
        float b = __bfloat162float(p[2*i + 1]) * r;
        w[i] = pkf(a, b);
    }
    *(uint4*)&g_Vp16[(size_t)row * 80 + c8] = v;
}

// =====================================================================
// Pass 2: fused attention. S' = Q'K^T, E = exp2(S') in registers,
// C-frags -> PV A-frags, V' pre-scaled by rcs, rs from cols 64-71.
// 3-stage single-barrier pipeline over 64-key chunks.
// =====================================================================
#define FA_Q  18432                 // Q 128*144
#define FA_ST 20480                 // K 64*144 + V 64*176
__global__ void __launch_bounds__(256, 2)
fused_pv()
{
    extern __shared__ __align__(16) char dyn[];
    const int tid = threadIdx.x, lane = tid & 31, wid = tid >> 5;
    const int bh = blockIdx.y, q0 = blockIdx.x * 128;
    const int bb = bh >> 3, hh = bh & 7;
    const bf16* __restrict__ Qp = g_Q16 + (size_t)bh * NQ_ * DH_;
    const bf16* __restrict__ Kp = g_K16 + (size_t)bh * NQ_ * DH_;
    const bf16* __restrict__ Vp = g_Vp16 + (size_t)bh * NQ_ * 80;
    const uint32_t sb = smem_u32(dyn);
    const uint32_t sQ = sb;

    auto loadKV = [&](int kc, int st) {
        const uint32_t base = sb + FA_Q + st * FA_ST;
        const uint32_t sK = base, sV = base + 9216;
#pragma unroll
        for (int j = 0; j < 2; j++) {
            int cc = tid + 256 * j;                  // 512: 64 rows x 8 chunks
            int row = cc >> 3, m = cc & 7;
            cpa16(sK + row * 144 + m * 16, Kp + (size_t)(kc * 64 + row) * 64 + m * 8);
        }
#pragma unroll
        for (int j = 0; j < 3; j++) {
            int cc = tid + 256 * j;                  // 640: 64 rows x 10 chunks
            if (cc < 640) {
                int row = cc / 10, m = cc - row * 10;
                cpa16(sV + row * 176 + m * 16, Vp + (size_t)(kc * 64 + row) * 80 + m * 8);
            }
        }
    };

#pragma unroll
    for (int j = 0; j < 4; j++) {
        int cc = tid + 256 * j;
        int row = cc >> 3, off = (cc & 7) * 16, e = (cc & 7) * 8;
        cpa16(sQ + row * 144 + off, Qp + (size_t)(q0 + row) * 64 + e);
    }
    loadKV(0, 0); CP_COMMIT();
    loadKV(1, 1); CP_COMMIT();

    float pacc[9][4];
#pragma unroll
    for (int j = 0; j < 9; j++)
#pragma unroll
        for (int c = 0; c < 4; c++) pacc[j][c] = 0.f;

    uint32_t Qa[4][4];
    bool qloaded = false;

    for (int kc = 0; kc < 32; kc++) {
        CP_WAIT1();
        __syncthreads();
        if (kc + 2 < 32) loadKV(kc + 2, (kc + 2) % 3);
        CP_COMMIT();
        const uint32_t base = sb + FA_Q + (kc % 3) * FA_ST;
        const uint32_t sK = base, sV = base + 9216;
        if (!qloaded) {
#pragma unroll
            for (int ks = 0; ks < 4; ks++)
                lda(Qa[ks], sQ, wid * 16, ks * 32, 144, lane);
            qloaded = true;
        }
        // QK: m16 x n64 x k64 over this 64-key chunk
        float qk[8][4];
#pragma unroll
        for (int j = 0; j < 8; j++)
#pragma unroll
            for (int c = 0; c < 4; c++) qk[j][c] = 0.f;
#pragma unroll
        for (int ks = 0; ks < 4; ks++) {
#pragma unroll
            for (int p = 0; p < 4; p++) {
                uint32_t r[4];
                ldb_nt(r, sK, p * 16, ks * 32, 144, lane);
                mma16816(qk[2*p],   Qa[ks], r);
                mma16816(qk[2*p+1], Qa[ks], r + 2);
            }
        }
        // exp2, pack to PV A-frags; PV mma per 16-key group
#pragma unroll
        for (int kp = 0; kp < 4; kp++) {
            const float* s0 = qk[2*kp];
            const float* s1 = qk[2*kp+1];
            uint32_t pa[4];
            pa[0] = pkf(ex2f(s0[0]), ex2f(s0[1]));
            pa[1] = pkf(ex2f(s0[2]), ex2f(s0[3]));
            pa[2] = pkf(ex2f(s1[0]), ex2f(s1[1]));
            pa[3] = pkf(ex2f(s1[2]), ex2f(s1[3]));
            const int k0 = kp * 16;
            uint32_t v0[4], v1[4], v2[4], v3[4], v4[2];
            ldb_t(v0, sV, k0, 0,  176, lane);
            ldb_t(v1, sV, k0, 16, 176, lane);
            ldb_t(v2, sV, k0, 32, 176, lane);
            ldb_t(v3, sV, k0, 48, 176, lane);
            ldb_t2(v4, sV, k0, 64, 176, lane);
            mma16816(pacc[0], pa, v0);
            mma16816(pacc[1], pa, v0 + 2);
            mma16816(pacc[2], pa, v1);
            mma16816(pacc[3], pa, v1 + 2);
            mma16816(pacc[4], pa, v2);
            mma16816(pacc[5], pa, v2 + 2);
            mma16816(pacc[6], pa, v3);
            mma16816(pacc[7], pa, v3 + 2);
            mma16816(pacc[8], pa, v4);
        }
    }

    const float inv0 = 1.f / (1e-12f + pacc[8][0]);
    const float inv1 = 1.f / (1e-12f + pacc[8][2]);
    const int gq = q0 + wid * 16 + (lane >> 2);
#pragma unroll
    for (int sn = 0; sn < 8; sn++) {
        const int col = sn * 8 + (lane & 3) * 2;
        size_t idx = (size_t)(bb * NQ_ + gq) * D_ + hh * DH_ + col;
        *(uint32_t*)&g_O16[idx] = pkf(pacc[sn][0] * inv0, pacc[sn][1] * inv0);
        idx = (size_t)(bb * NQ_ + gq + 8) * D_ + hh * DH_ + col;
        *(uint32_t*)&g_O16[idx] = pkf(pacc[sn][2] * inv1, pacc[sn][3] * inv1);
    }
}

// =====================================================================
// Launch
// =====================================================================
extern "C" void kernel_launch(void* const* d_in, const int* in_sizes, int n_in,
                              void* d_out, int out_size)
{
    const float* x_q = (const float*)d_in[0];
    const float* x_e = (const float*)d_in[1];
    const float* Wq  = (const float*)d_in[2];
    const float* Wk  = (const float*)d_in[3];
    const float* Wv  = (const float*)d_in[4];
    const float* W0  = (const float*)d_in[5];
    const float* b0  = (const float*)d_in[6];
    const float* W1  = (const float*)d_in[7];
    const float* b1  = (const float*)d_in[8];
    float* out = (float*)d_out;

    bf16 *W16, *W1h, *W1l, *O16, *Yh, *Yl;
    cudaGetSymbolAddress((void**)&W16,  g_W16);
    cudaGetSymbolAddress((void**)&W1h,  g_W1h);
    cudaGetSymbolAddress((void**)&W1l,  g_W1l);
    cudaGetSymbolAddress((void**)&O16,  g_O16);
    cudaGetSymbolAddress((void**)&Yh,   g_Yh);
    cudaGetSymbolAddress((void**)&Yl,   g_Yl);

    cudaFuncSetAttribute(proj_mma,   cudaFuncAttributeMaxDynamicSharedMemorySize, 3*D1_ST);
    cudaFuncSetAttribute(denseY_mma, cudaFuncAttributeMaxDynamicSharedMemorySize, 3*D1_ST);
    cudaFuncSetAttribute(dense3_mma, cudaFuncAttributeMaxDynamicSharedMemorySize, 3*DA_ST);
    cudaFuncSetAttribute(colsum_mma, cudaFuncAttributeMaxDynamicSharedMemorySize, 36864);
    cudaFuncSetAttribute(fused_pv,   cudaFuncAttributeMaxDynamicSharedMemorySize,
                         FA_Q + 3*FA_ST);

    prep_kernel<<<9984, 256>>>(x_q, x_e, Wq, Wk, Wv, W0, W1);

    proj_mma<<<dim3(4, 64, 3), 256, 3*D1_ST>>>();

    colsum_mma<<<dim3(16, 16, 32), 256, 36864>>>();
    vscale_kernel<<<2560, 256>>>();
    fused_pv<<<dim3(16, 32), 256, FA_Q + 3*FA_ST>>>();

    denseY_mma<<<dim3(4, 64), 256, 3*D1_ST>>>(O16, W16 + (size_t)3*D_*D_, x_q, b0, Yh, Yl);

    dense3_mma<<<dim3(4, 64), 256, 3*DA_ST>>>(Yh, Yl, W1h, W1l, b1, out);
}

// round 14
// speedup vs baseline: 1.4219x; 1.0888x over previous
#include <cuda_runtime.h>
#include <cuda_bf16.h>
#include <cstdint>

#define B_   4
#define NQ_  2048
#define D_   512
#define H_   8
#define DH_  64
#define M_   (B_*NQ_)
#define BH_  (B_*H_)

typedef __nv_bfloat16 bf16;

// ---------------- device scratch ----------------
__device__ __align__(16) bf16 g_Xq16[M_*D_];
__device__ __align__(16) bf16 g_Xe16[M_*D_];
__device__ __align__(16) bf16 g_W16[4*D_*D_];            // Wq*log2e, Wk, Wv, W0
__device__ __align__(16) bf16 g_W1h[D_*D_], g_W1l[D_*D_];
__device__ __align__(16) bf16 g_Q16[BH_*NQ_*DH_];        // Q' = X Wq log2e
__device__ __align__(16) bf16 g_K16[BH_*NQ_*DH_];
__device__ __align__(16) bf16 g_Vp16[BH_*NQ_*80];        // V bf16 [k][80]; 64-71=1, 72-79=0
__device__ __align__(16) bf16 g_O16[M_*D_];
__device__ __align__(16) bf16 g_Yh[M_*D_], g_Yl[M_*D_];

// ---------------- helpers ----------------
__device__ __forceinline__ uint32_t smem_u32(const void* p) {
    uint32_t a;
    asm("{ .reg .u64 t; cvta.to.shared.u64 t, %1; cvt.u32.u64 %0, t; }" : "=r"(a) : "l"(p));
    return a;
}
__device__ __forceinline__ float ex2f(float x) {
    float y; asm("ex2.approx.ftz.f32 %0, %1;" : "=f"(y) : "f"(x)); return y;
}
__device__ __forceinline__ void mma16816(float* c, const uint32_t* a, const uint32_t* b) {
    asm volatile(
        "mma.sync.aligned.m16n8k16.row.col.f32.bf16.bf16.f32 "
        "{%0,%1,%2,%3}, {%4,%5,%6,%7}, {%8,%9}, {%0,%1,%2,%3};"
        : "+f"(c[0]), "+f"(c[1]), "+f"(c[2]), "+f"(c[3])
        : "r"(a[0]), "r"(a[1]), "r"(a[2]), "r"(a[3]), "r"(b[0]), "r"(b[1]));
}
__device__ __forceinline__ void ldmx4(uint32_t* r, uint32_t a) {
    asm volatile("ldmatrix.sync.aligned.m8n8.x4.shared.b16 {%0,%1,%2,%3}, [%4];"
                 : "=r"(r[0]), "=r"(r[1]), "=r"(r[2]), "=r"(r[3]) : "r"(a));
}
__device__ __forceinline__ void ldmx4t(uint32_t* r, uint32_t a) {
    asm volatile("ldmatrix.sync.aligned.m8n8.x4.trans.shared.b16 {%0,%1,%2,%3}, [%4];"
                 : "=r"(r[0]), "=r"(r[1]), "=r"(r[2]), "=r"(r[3]) : "r"(a));
}
__device__ __forceinline__ void ldmx2t(uint32_t* r, uint32_t a) {
    asm volatile("ldmatrix.sync.aligned.m8n8.x2.trans.shared.b16 {%0,%1}, [%2];"
                 : "=r"(r[0]), "=r"(r[1]) : "r"(a));
}
__device__ __forceinline__ void lda(uint32_t* r, uint32_t base, int row0, int kbyte,
                                    int SB, int lane) {
    uint32_t a = base + (uint32_t)(row0 + (lane & 15)) * SB + kbyte + ((lane >> 4) << 4);
    ldmx4(r, a);
}
__device__ __forceinline__ void ldb_nt(uint32_t* r, uint32_t base, int n0, int kbyte,
                                       int SB, int lane) {
    uint32_t a = base + (uint32_t)(n0 + (lane & 7) + ((lane >> 4) << 3)) * SB
               + kbyte + (((lane >> 3) & 1) << 4);
    ldmx4(r, a);
}
__device__ __forceinline__ void ldb_t(uint32_t* r, uint32_t base, int k0, int n0,
                                      int SB, int lane) {
    uint32_t a = base + (uint32_t)(k0 + (lane & 7) + (((lane >> 3) & 1) << 3)) * SB
               + n0 * 2 + ((lane >> 4) << 4);
    ldmx4t(r, a);
}
__device__ __forceinline__ void ldb_t2(uint32_t* r, uint32_t base, int k0, int n0,
                                       int SB, int lane) {
    uint32_t a = base + (uint32_t)(k0 + (lane & 15)) * SB + n0 * 2;
    ldmx2t(r, a);
}
__device__ __forceinline__ uint32_t pk(bf16 a, bf16 b) {
    return (uint32_t)__bfloat16_as_ushort(a) | ((uint32_t)__bfloat16_as_ushort(b) << 16);
}
__device__ __forceinline__ uint32_t pkf(float a, float b) {
    return pk(__float2bfloat16(a), __float2bfloat16(b));
}
__device__ __forceinline__ uint2 cvt4(float4 v) {
    return make_uint2(pkf(v.x, v.y), pkf(v.z, v.w));
}
__device__ __forceinline__ void split4(float4 v, uint2& h, uint2& l) {
    bf16 h0 = __float2bfloat16(v.x), h1 = __float2bfloat16(v.y);
    bf16 h2 = __float2bfloat16(v.z), h3 = __float2bfloat16(v.w);
    bf16 l0 = __float2bfloat16(v.x - __bfloat162float(h0));
    bf16 l1 = __float2bfloat16(v.y - __bfloat162float(h1));
    bf16 l2 = __float2bfloat16(v.z - __bfloat162float(h2));
    bf16 l3 = __float2bfloat16(v.w - __bfloat162float(h3));
    h = make_uint2(pk(h0, h1), pk(h2, h3));
    l = make_uint2(pk(l0, l1), pk(l2, l3));
}
__device__ __forceinline__ void split2(float a, float b, uint32_t& ph, uint32_t& pl) {
    bf16 ha = __float2bfloat16(a), hb = __float2bfloat16(b);
    bf16 la = __float2bfloat16(a - __bfloat162float(ha));
    bf16 lb = __float2bfloat16(b - __bfloat162float(hb));
    ph = pk(ha, hb); pl = pk(la, lb);
}
__device__ __forceinline__ void cpa16(uint32_t dst, const void* src) {
    asm volatile("cp.async.cg.shared.global [%0], [%1], 16;" :: "r"(dst), "l"(src));
}
#define CP_COMMIT() asm volatile("cp.async.commit_group;" ::: "memory")
#define CP_WAIT1()  asm volatile("cp.async.wait_group 1;"  ::: "memory")
#define CP_WAIT0()  asm volatile("cp.async.wait_group 0;"  ::: "memory")

// =====================================================================
// prep: conversions (Wq scaled by log2e) + V' pad columns.
// =====================================================================
__global__ void __launch_bounds__(256)
prep_kernel(const float* __restrict__ x_q, const float* __restrict__ x_e,
            const float* __restrict__ Wq, const float* __restrict__ Wk,
            const float* __restrict__ Wv, const float* __restrict__ W0,
            const float* __restrict__ W1)
{
    const int b = blockIdx.x, tid = threadIdx.x;
    if (b < 8192) {
        const float* s = (b < 4096) ? x_q : x_e;
        bf16* d = (b < 4096) ? g_Xq16 : g_Xe16;
        const int i = (((b & 4095) * 256) + tid) * 4;
        *(uint2*)&d[i] = cvt4(*(const float4*)&s[i]);
    } else if (b < 9216) {
        const int w = (b - 8192) >> 8;
        const float* s = (w == 0) ? Wq : (w == 1) ? Wk : (w == 2) ? Wv : W0;
        const float sc = (w == 0) ? 1.4426950408889634f : 1.0f;   // log2(e) into Wq
        const int i = ((((b - 8192) & 255) * 256) + tid) * 4;
        float4 v = *(const float4*)&s[i];
        v.x *= sc; v.y *= sc; v.z *= sc; v.w *= sc;
        *(uint2*)&g_W16[(size_t)w * D_ * D_ + i] = cvt4(v);
    } else if (b < 9472) {
        const int i = (((b - 9216) * 256) + tid) * 4;
        float4 v = *(const float4*)&W1[i];
        uint2 h, l; split4(v, h, l);
        *(uint2*)&g_W1h[i] = h; *(uint2*)&g_W1l[i] = l;
    } else {
        const int row = (b - 9472) * 256 + tid;            // 65536 rows
        uint4 ones = make_uint4(0x3F803F80u, 0x3F803F80u, 0x3F803F80u, 0x3F803F80u);
        uint4 zero = make_uint4(0u, 0u, 0u, 0u);
        *(uint4*)&g_Vp16[(size_t)row * 80 + 64] = ones;
        *(uint4*)&g_Vp16[(size_t)row * 80 + 72] = zero;
    }
}

// =====================================================================
// proj: merged Q/K/V projections, blockIdx.z selects the problem.
// =====================================================================
#define D1_ST 18944   // A 128*80 + B 32*272
__global__ void __launch_bounds__(256, 2)
proj_mma()
{
    extern __shared__ __align__(16) char dyn[];
    const int tid = threadIdx.x, lane = tid & 31, wid = tid >> 5;
    const int wm = wid >> 2, wn = wid & 3;
    const int m0 = blockIdx.y * 128, n0 = blockIdx.x * 128;
    const int z = blockIdx.z;
    const bf16* __restrict__ A16 = (z == 0) ? g_Xq16 : g_Xe16;
    const bf16* __restrict__ W16 = g_W16 + (size_t)z * D_ * D_;
    bf16* __restrict__ C16 = (z == 0) ? g_Q16 : ((z == 1) ? g_K16 : g_Vp16);
    const int cstride = (z == 2) ? 80 : 64;
    const uint32_t sb = smem_u32(dyn);

    auto load = [&](int kc, int st) {
        const uint32_t sAs = sb + st * D1_ST;
        const uint32_t sBs = sAs + 10240;
#pragma unroll
        for (int j = 0; j < 2; j++) {
            int cc = tid + 256 * j;
            int row = cc >> 2, off = (cc & 3) * 16, e = (cc & 3) * 8;
            cpa16(sAs + row * 80 + off, A16 + (size_t)(m0 + row) * 512 + kc * 32 + e);
        }
#pragma unroll
        for (int j = 0; j < 2; j++) {
            int cc = tid + 256 * j;
            int row = cc >> 4, off = (cc & 15) * 16, e = (cc & 15) * 8;
            cpa16(sBs + row * 272 + off, W16 + (size_t)(kc * 32 + row) * 512 + n0 + e);
        }
    };

    float acc[4][4][4];
#pragma unroll
    for (int i = 0; i < 4; i++)
#pragma unroll
        for (int j = 0; j < 4; j++)
#pragma unroll
            for (int c = 0; c < 4; c++) acc[i][j][c] = 0.f;

    load(0, 0); CP_COMMIT();
    load(1, 1); CP_COMMIT();

    for (int kc = 0; kc < 16; kc++) {
        CP_WAIT1();
        __syncthreads();
        if (kc + 2 < 16) load(kc + 2, (kc + 2) % 3);
        CP_COMMIT();
        const uint32_t sAs = sb + (kc % 3) * D1_ST;
        const uint32_t sBs = sAs + 10240;
#pragma unroll
        for (int ks = 0; ks < 2; ks++) {
            uint32_t ah[4][4];
#pragma unroll
            for (int sm = 0; sm < 4; sm++)
                lda(ah[sm], sAs, wm * 64 + sm * 16, ks * 32, 80, lane);
            uint32_t bh[4][2];
#pragma unroll
            for (int p = 0; p < 2; p++) {
                uint32_t r[4];
                ldb_t(r, sBs, ks * 16, wn * 32 + p * 16, 272, lane);
                bh[2*p][0] = r[0]; bh[2*p][1] = r[1];
                bh[2*p+1][0] = r[2]; bh[2*p+1][1] = r[3];
            }
#pragma unroll
            for (int sm = 0; sm < 4; sm++)
#pragma unroll
                for (int sn = 0; sn < 4; sn++)
                    mma16816(acc[sm][sn], ah[sm], bh[sn]);
        }
    }

#pragma unroll
    for (int sm = 0; sm < 4; sm++) {
        const int row = m0 + wm * 64 + sm * 16 + (lane >> 2);
#pragma unroll
        for (int sn = 0; sn < 4; sn++) {
            const int col = n0 + wn * 32 + sn * 8 + (lane & 3) * 2;
            const float* a = acc[sm][sn];
            const int hh = col >> 6, dd = col & 63;
#pragma unroll
            for (int half = 0; half < 2; half++) {
                const int gm = row + half * 8;
                const int bb = gm >> 11, nn = gm & 2047;
                const size_t idx = ((size_t)(bb * H_ + hh) * NQ_ + nn) * cstride + dd;
                *(uint32_t*)&C16[idx] = pkf(a[half*2], a[half*2+1]);
            }
        }
    }
}

// =====================================================================
// denseY: Y = X - (O @ W0 + b0), single-plane operands, split-plane out.
// =====================================================================
__global__ void __launch_bounds__(256, 2)
denseY_mma(const bf16* __restrict__ A16, const bf16* __restrict__ W16,
           const float* __restrict__ X, const float* __restrict__ bias,
           bf16* __restrict__ Ch, bf16* __restrict__ Cl)
{
    extern __shared__ __align__(16) char dyn[];
    const int tid = threadIdx.x, lane = tid & 31, wid = tid >> 5;
    const int wm = wid >> 2, wn = wid & 3;
    const int m0 = blockIdx.y * 128, n0 = blockIdx.x * 128;
    const uint32_t sb = smem_u32(dyn);

    auto load = [&](int kc, int st) {
        const uint32_t sAs = sb + st * D1_ST;
        const uint32_t sBs = sAs + 10240;
#pragma unroll
        for (int j = 0; j < 2; j++) {
            int cc = tid + 256 * j;
            int row = cc >> 2, off = (cc & 3) * 16, e = (cc & 3) * 8;
            cpa16(sAs + row * 80 + off, A16 + (size_t)(m0 + row) * 512 + kc * 32 + e);
        }
#pragma unroll
        for (int j = 0; j < 2; j++) {
            int cc = tid + 256 * j;
            int row = cc >> 4, off = (cc & 15) * 16, e = (cc & 15) * 8;
            cpa16(sBs + row * 272 + off, W16 + (size_t)(kc * 32 + row) * 512 + n0 + e);
        }
    };

    float acc[4][4][4];
#pragma unroll
    for (int i = 0; i < 4; i++)
#pragma unroll
        for (int j = 0; j < 4; j++)
#pragma unroll
            for (int c = 0; c < 4; c++) acc[i][j][c] = 0.f;

    load(0, 0); CP_COMMIT();
    load(1, 1); CP_COMMIT();

    for (int kc = 0; kc < 16; kc++) {
        CP_WAIT1();
        __syncthreads();
        if (kc + 2 < 16) load(kc + 2, (kc + 2) % 3);
        CP_COMMIT();
        const uint32_t sAs = sb + (kc % 3) * D1_ST;
        const uint32_t sBs = sAs + 10240;
#pragma unroll
        for (int ks = 0; ks < 2; ks++) {
            uint32_t ah[4][4];
#pragma unroll
            for (int sm = 0; sm < 4; sm++)
                lda(ah[sm], sAs, wm * 64 + sm * 16, ks * 32, 80, lane);
            uint32_t bh[4][2];
#pragma unroll
            for (int p = 0; p < 2; p++) {
                uint32_t r[4];
                ldb_t(r, sBs, ks * 16, wn * 32 + p * 16, 272, lane);
                bh[2*p][0] = r[0]; bh[2*p][1] = r[1];
                bh[2*p+1][0] = r[2]; bh[2*p+1][1] = r[3];
            }
#pragma unroll
            for (int sm = 0; sm < 4; sm++)
#pragma unroll
                for (int sn = 0; sn < 4; sn++)
                    mma16816(acc[sm][sn], ah[sm], bh[sn]);
        }
    }

#pragma unroll
    for (int sm = 0; sm < 4; sm++) {
        const int row = m0 + wm * 64 + sm * 16 + (lane >> 2);
#pragma unroll
        for (int sn = 0; sn < 4; sn++) {
            const int col = n0 + wn * 32 + sn * 8 + (lane & 3) * 2;
            const float* a = acc[sm][sn];
            float2 bv = *(const float2*)&bias[col];
#pragma unroll
            for (int half = 0; half < 2; half++) {
                const int gm = row + half * 8;
                float2 xv = *(const float2*)&X[(size_t)gm * 512 + col];
                float o0 = xv.x - (a[half*2] + bv.x);
                float o1 = xv.y - (a[half*2+1] + bv.y);
                uint32_t ph, pl;
                split2(o0, o1, ph, pl);
                *(uint32_t*)&Ch[(size_t)gm * 512 + col] = ph;
                *(uint32_t*)&Cl[(size_t)gm * 512 + col] = pl;
            }
        }
    }
}

// =====================================================================
// dense3: split-operand GEMM out = Y @ W1 + b1 (3 products).
// =====================================================================
#define DA_ST 35328
__global__ void __launch_bounds__(256, 2)
dense3_mma(const bf16* __restrict__ Ah, const bf16* __restrict__ Al,
           const bf16* __restrict__ Wh, const bf16* __restrict__ Wl,
           const float* __restrict__ bias, float* __restrict__ Cf)
{
    extern __shared__ __align__(16) char dyn[];
    const int tid = threadIdx.x, lane = tid & 31, wid = tid >> 5;
    const int wm = wid >> 2, wn = wid & 3;
    const int m0 = blockIdx.y * 128, n0 = blockIdx.x * 128;
    const uint32_t sb = smem_u32(dyn);

    auto load = [&](int kc, int st) {
        const uint32_t sAs = sb + st * DA_ST;
        const uint32_t sBs = sAs + 18432;
#pragma unroll
        for (int j = 0; j < 2; j++) {
            int cc = tid + 256 * j;
            int row = cc >> 2, off = (cc & 3) * 16, e = (cc & 3) * 8;
            const size_t gi = (size_t)(m0 + row) * 512 + kc * 32 + e;
            cpa16(sAs + row * 144 + off,      Ah + gi);
            cpa16(sAs + row * 144 + 64 + off, Al + gi);
        }
#pragma unroll
        for (int j = 0; j < 2; j++) {
            int cc = tid + 256 * j;
            int row = cc >> 4, off = (cc & 15) * 16, e = (cc & 15) * 8;
            const size_t gi = (size_t)(kc * 32 + row) * 512 + n0 + e;
            cpa16(sBs + row * 528 + off,       Wh + gi);
            cpa16(sBs + row * 528 + 256 + off, Wl + gi);
        }
    };

    float acc[4][4][4];
#pragma unroll
    for (int i = 0; i < 4; i++)
#pragma unroll
        for (int j = 0; j < 4; j++)
#pragma unroll
            for (int c = 0; c < 4; c++) acc[i][j][c] = 0.f;

    load(0, 0); CP_COMMIT();
    load(1, 1); CP_COMMIT();

    for (int kc = 0; kc < 16; kc++) {
        CP_WAIT1();
        __syncthreads();
        if (kc + 2 < 16) load(kc + 2, (kc + 2) % 3);
        CP_COMMIT();
        const uint32_t sAs = sb + (kc % 3) * DA_ST;
        const uint32_t sBs = sAs + 18432;
#pragma unroll
        for (int ks = 0; ks < 2; ks++) {
            uint32_t ah[4][4], al[4][4];
#pragma unroll
            for (int sm = 0; sm < 4; sm++) {
                lda(ah[sm], sAs, wm * 64 + sm * 16, ks * 32, 144, lane);
                lda(al[sm], sAs, wm * 64 + sm * 16, 64 + ks * 32, 144, lane);
            }
            uint32_t bh[4][2], bl[4][2];
#pragma unroll
            for (int p = 0; p < 2; p++) {
                uint32_t r[4];
                ldb_t(r, sBs, ks * 16, wn * 32 + p * 16, 528, lane);
                bh[2*p][0] = r[0]; bh[2*p][1] = r[1];
                bh[2*p+1][0] = r[2]; bh[2*p+1][1] = r[3];
                ldb_t(r, sBs + 256, ks * 16, wn * 32 + p * 16, 528, lane);
                bl[2*p][0] = r[0]; bl[2*p][1] = r[1];
                bl[2*p+1][0] = r[2]; bl[2*p+1][1] = r[3];
            }
#pragma unroll
            for (int sm = 0; sm < 4; sm++)
#pragma unroll
                for (int sn = 0; sn < 4; sn++) {
                    mma16816(acc[sm][sn], ah[sm], bh[sn]);
                    mma16816(acc[sm][sn], al[sm], bh[sn]);
                    mma16816(acc[sm][sn], ah[sm], bl[sn]);
                }
        }
    }

#pragma unroll
    for (int sm = 0; sm < 4; sm++) {
        const int row = m0 + wm * 64 + sm * 16 + (lane >> 2);
#pragma unroll
        for (int sn = 0; sn < 4; sn++) {
            const int col = n0 + wn * 32 + sn * 8 + (lane & 3) * 2;
            const float* a = acc[sm][sn];
            float2 bv = *(const float2*)&bias[col];
#pragma unroll
            for (int half = 0; half < 2; half++) {
                const int gm = row + half * 8;
                *(float2*)&Cf[(size_t)gm * 512 + col] =
                    make_float2(a[half*2] + bv.x, a[half*2+1] + bv.y);
            }
        }
    }
}

// =====================================================================
// Pass 1: per (128-key block, bh) CTA: csum_k = sum over ALL q of
// exp2(K_k . Q_q); then scale own V' rows by 1/csum in place.
// Keys are the M dim; Q streamed in 16 chunks, 3-stage single-barrier.
// =====================================================================
#define CS_ST 18432   // Q chunk 128*144
__global__ void __launch_bounds__(256, 2)
colsum_mma()
{
    extern __shared__ __align__(16) char dyn[];
    __shared__ float csum_s[128];
    const int tid = threadIdx.x, lane = tid & 31, wid = tid >> 5;
    const int wm = wid >> 2, wn = wid & 3;
    const int bh = blockIdx.y, k0g = blockIdx.x * 128;
    const bf16* __restrict__ Qp = g_Q16 + (size_t)bh * NQ_ * DH_;
    const bf16* __restrict__ Kp = g_K16 + (size_t)bh * NQ_ * DH_;
    const uint32_t sb = smem_u32(dyn);
    const uint32_t sK = sb;                      // K block 128*144
    const uint32_t sQ0 = sb + 18432;             // 3 Q stages

    auto loadQ = [&](int qc, int st) {
        const uint32_t sQs = sQ0 + st * CS_ST;
#pragma unroll
        for (int j = 0; j < 4; j++) {
            int cc = tid + 256 * j;
            int row = cc >> 3, m = cc & 7;
            cpa16(sQs + row * 144 + m * 16, Qp + (size_t)(qc * 128 + row) * 64 + m * 8);
        }
    };

    // group 0: K block + Q chunk 0 ; group 1: Q chunk 1
#pragma unroll
    for (int j = 0; j < 4; j++) {
        int cc = tid + 256 * j;
        int row = cc >> 3, m = cc & 7;
        cpa16(sK + row * 144 + m * 16, Kp + (size_t)(k0g + row) * 64 + m * 8);
    }
    loadQ(0, 0); CP_COMMIT();
    loadQ(1, 1); CP_COMMIT();

    if (tid < 128) csum_s[tid] = 0.f;

    float run[4][2];
#pragma unroll
    for (int sm = 0; sm < 4; sm++) { run[sm][0] = 0.f; run[sm][1] = 0.f; }

    uint32_t Ka[4][4];
    bool kloaded = false;

    for (int qc = 0; qc < 16; qc++) {
        CP_WAIT1();
        __syncthreads();
        if (qc + 2 < 16) loadQ(qc + 2, (qc + 2) % 3);
        CP_COMMIT();
        const uint32_t sQs = sQ0 + (qc % 3) * CS_ST;
        if (!kloaded) {
#pragma unroll
            for (int ks = 0; ks < 4; ks++)
                lda(Ka[ks], sK, wm * 64 + 0, ks * 32, 144, lane);   // placeholder; real per-sm below
            kloaded = true;
        }
        float acc[4][4][4];
#pragma unroll
        for (int i = 0; i < 4; i++)
#pragma unroll
            for (int j = 0; j < 4; j++)
#pragma unroll
                for (int c = 0; c < 4; c++) acc[i][j][c] = 0.f;
#pragma unroll
        for (int ks = 0; ks < 4; ks++) {
            uint32_t ah[4][4];
#pragma unroll
            for (int sm = 0; sm < 4; sm++)
                lda(ah[sm], sK, wm * 64 + sm * 16, ks * 32, 144, lane);
            uint32_t bh_[4][2];
#pragma unroll
            for (int p = 0; p < 2; p++) {
                uint32_t r[4];
                ldb_nt(r, sQs, wn * 32 + p * 16, ks * 32, 144, lane);
                bh_[2*p][0] = r[0]; bh_[2*p][1] = r[1];
                bh_[2*p+1][0] = r[2]; bh_[2*p+1][1] = r[3];
            }
#pragma unroll
            for (int sm = 0; sm < 4; sm++)
#pragma unroll
                for (int sn = 0; sn < 4; sn++)
                    mma16816(acc[sm][sn], ah[sm], bh_[sn]);
        }
#pragma unroll
        for (int sm = 0; sm < 4; sm++)
#pragma unroll
            for (int sn = 0; sn < 4; sn++) {
                run[sm][0] += ex2f(acc[sm][sn][0]) + ex2f(acc[sm][sn][1]);
                run[sm][1] += ex2f(acc[sm][sn][2]) + ex2f(acc[sm][sn][3]);
            }
    }

    // reduce over the 4 col-lanes (lane&3)
#pragma unroll
    for (int o = 1; o <= 2; o <<= 1)
#pragma unroll
        for (int sm = 0; sm < 4; sm++) {
            run[sm][0] += __shfl_xor_sync(0xffffffffu, run[sm][0], o);
            run[sm][1] += __shfl_xor_sync(0xffffffffu, run[sm][1], o);
        }
    if ((lane & 3) == 0) {
#pragma unroll
        for (int sm = 0; sm < 4; sm++) {
            const int r = wm * 64 + sm * 16 + (lane >> 2);
            atomicAdd(&csum_s[r],     run[sm][0]);
            atomicAdd(&csum_s[r + 8], run[sm][1]);
        }
    }
    __syncthreads();
    if (tid < 128) csum_s[tid] = 1.f / csum_s[tid];
    __syncthreads();

    // scale own V' rows in place
    bf16* __restrict__ Vp = g_Vp16 + ((size_t)bh * NQ_ + k0g) * 80;
    for (int i = tid; i < 1280; i += 256) {
        const int row = i / 10, c8 = (i - row * 10) * 8;
        const float r = csum_s[row];
        uint4 v = *(uint4*)&Vp[(size_t)row * 80 + c8];
        const bf16* p = (const bf16*)&v;
        uint32_t* w = (uint32_t*)&v;
#pragma unroll
        for (int e = 0; e < 4; e++) {
            float a = __bfloat162float(p[2*e])     * r;
            float b = __bfloat162float(p[2*e + 1]) * r;
            w[e] = pkf(a, b);
        }
        *(uint4*)&Vp[(size_t)row * 80 + c8] = v;
    }
}

// =====================================================================
// Pass 2: fused attention. S' = Q'K^T, E = exp2(S') in registers,
// C-frags -> PV A-frags, V' pre-scaled by rcs, rs from cols 64-71.
// 3-stage single-barrier pipeline over 64-key chunks.
// =====================================================================
#define FA_Q  18432                 // Q 128*144
#define FA_ST 20480                 // K 64*144 + V 64*176
__global__ void __launch_bounds__(256, 2)
fused_pv()
{
    extern __shared__ __align__(16) char dyn[];
    const int tid = threadIdx.x, lane = tid & 31, wid = tid >> 5;
    const int bh = blockIdx.y, q0 = blockIdx.x * 128;
    const int bb = bh >> 3, hh = bh & 7;
    const bf16* __restrict__ Qp = g_Q16 + (size_t)bh * NQ_ * DH_;
    const bf16* __restrict__ Kp = g_K16 + (size_t)bh * NQ_ * DH_;
    const bf16* __restrict__ Vp = g_Vp16 + (size_t)bh * NQ_ * 80;
    const uint32_t sb = smem_u32(dyn);
    const uint32_t sQ = sb;

    auto loadKV = [&](int kc, int st) {
        const uint32_t base = sb + FA_Q + st * FA_ST;
        const uint32_t sK = base, sV = base + 9216;
#pragma unroll
        for (int j = 0; j < 2; j++) {
            int cc = tid + 256 * j;
            int row = cc >> 3, m = cc & 7;
            cpa16(sK + row * 144 + m * 16, Kp + (size_t)(kc * 64 + row) * 64 + m * 8);
        }
#pragma unroll
        for (int j = 0; j < 3; j++) {
            int cc = tid + 256 * j;
            if (cc < 640) {
                int row = cc / 10, m = cc - row * 10;
                cpa16(sV + row * 176 + m * 16, Vp + (size_t)(kc * 64 + row) * 80 + m * 8);
            }
        }
    };

#pragma unroll
    for (int j = 0; j < 4; j++) {
        int cc = tid + 256 * j;
        int row = cc >> 3, off = (cc & 7) * 16, e = (cc & 7) * 8;
        cpa16(sQ + row * 144 + off, Qp + (size_t)(q0 + row) * 64 + e);
    }
    loadKV(0, 0); CP_COMMIT();
    loadKV(1, 1); CP_COMMIT();

    float pacc[9][4];
#pragma unroll
    for (int j = 0; j < 9; j++)
#pragma unroll
        for (int c = 0; c < 4; c++) pacc[j][c] = 0.f;

    uint32_t Qa[4][4];
    bool qloaded = false;

    for (int kc = 0; kc < 32; kc++) {
        CP_WAIT1();
        __syncthreads();
        if (kc + 2 < 32) loadKV(kc + 2, (kc + 2) % 3);
        CP_COMMIT();
        const uint32_t base = sb + FA_Q + (kc % 3) * FA_ST;
        const uint32_t sK = base, sV = base + 9216;
        if (!qloaded) {
#pragma unroll
            for (int ks = 0; ks < 4; ks++)
                lda(Qa[ks], sQ, wid * 16, ks * 32, 144, lane);
            qloaded = true;
        }
        float qk[8][4];
#pragma unroll
        for (int j = 0; j < 8; j++)
#pragma unroll
            for (int c = 0; c < 4; c++) qk[j][c] = 0.f;
#pragma unroll
        for (int ks = 0; ks < 4; ks++) {
#pragma unroll
            for (int p = 0; p < 4; p++) {
                uint32_t r[4];
                ldb_nt(r, sK, p * 16, ks * 32, 144, lane);
                mma16816(qk[2*p],   Qa[ks], r);
                mma16816(qk[2*p+1], Qa[ks], r + 2);
            }
        }
#pragma unroll
        for (int kp = 0; kp < 4; kp++) {
            const float* s0 = qk[2*kp];
            const float* s1 = qk[2*kp+1];
            uint32_t pa[4];
            pa[0] = pkf(ex2f(s0[0]), ex2f(s0[1]));
            pa[1] = pkf(ex2f(s0[2]), ex2f(s0[3]));
            pa[2] = pkf(ex2f(s1[0]), ex2f(s1[1]));
            pa[3] = pkf(ex2f(s1[2]), ex2f(s1[3]));
            const int k0 = kp * 16;
            uint32_t v0[4], v1[4], v2[4], v3[4], v4[2];
            ldb_t(v0, sV, k0, 0,  176, lane);
            ldb_t(v1, sV, k0, 16, 176, lane);
            ldb_t(v2, sV, k0, 32, 176, lane);
            ldb_t(v3, sV, k0, 48, 176, lane);
            ldb_t2(v4, sV, k0, 64, 176, lane);
            mma16816(pacc[0], pa, v0);
            mma16816(pacc[1], pa, v0 + 2);
            mma16816(pacc[2], pa, v1);
            mma16816(pacc[3], pa, v1 + 2);
            mma16816(pacc[4], pa, v2);
            mma16816(pacc[5], pa, v2 + 2);
            mma16816(pacc[6], pa, v3);
            mma16816(pacc[7], pa, v3 + 2);
            mma16816(pacc[8], pa, v4);
        }
    }

    const float inv0 = 1.f / (1e-12f + pacc[8][0]);
    const float inv1 = 1.f / (1e-12f + pacc[8][2]);
    const int gq = q0 + wid * 16 + (lane >> 2);
#pragma unroll
    for (int sn = 0; sn < 8; sn++) {
        const int col = sn * 8 + (lane & 3) * 2;
        size_t idx = (size_t)(bb * NQ_ + gq) * D_ + hh * DH_ + col;
        *(uint32_t*)&g_O16[idx] = pkf(pacc[sn][0] * inv0, pacc[sn][1] * inv0);
        idx = (size_t)(bb * NQ_ + gq + 8) * D_ + hh * DH_ + col;
        *(uint32_t*)&g_O16[idx] = pkf(pacc[sn][2] * inv1, pacc[sn][3] * inv1);
    }
}

// =====================================================================
// Launch
// =====================================================================
extern "C" void kernel_launch(void* const* d_in, const int* in_sizes, int n_in,
                              void* d_out, int out_size)
{
    const float* x_q = (const float*)d_in[0];
    const float* x_e = (const float*)d_in[1];
    const float* Wq  = (const float*)d_in[2];
    const float* Wk  = (const float*)d_in[3];
    const float* Wv  = (const float*)d_in[4];
    const float* W0  = (const float*)d_in[5];
    const float* b0  = (const float*)d_in[6];
    const float* W1  = (const float*)d_in[7];
    const float* b1  = (const float*)d_in[8];
    float* out = (float*)d_out;

    bf16 *W16, *W1h, *W1l, *O16, *Yh, *Yl;
    cudaGetSymbolAddress((void**)&W16,  g_W16);
    cudaGetSymbolAddress((void**)&W1h,  g_W1h);
    cudaGetSymbolAddress((void**)&W1l,  g_W1l);
    cudaGetSymbolAddress((void**)&O16,  g_O16);
    cudaGetSymbolAddress((void**)&Yh,   g_Yh);
    cudaGetSymbolAddress((void**)&Yl,   g_Yl);

    cudaFuncSetAttribute(proj_mma,   cudaFuncAttributeMaxDynamicSharedMemorySize, 3*D1_ST);
    cudaFuncSetAttribute(denseY_mma, cudaFuncAttributeMaxDynamicSharedMemorySize, 3*D1_ST);
    cudaFuncSetAttribute(dense3_mma, cudaFuncAttributeMaxDynamicSharedMemorySize, 3*DA_ST);
    cudaFuncSetAttribute(colsum_mma, cudaFuncAttributeMaxDynamicSharedMemorySize, 4*CS_ST);
    cudaFuncSetAttribute(fused_pv,   cudaFuncAttributeMaxDynamicSharedMemorySize,
                         FA_Q + 3*FA_ST);

    prep_kernel<<<9728, 256>>>(x_q, x_e, Wq, Wk, Wv, W0, W1);

    proj_mma<<<dim3(4, 64, 3), 256, 3*D1_ST>>>();

    colsum_mma<<<dim3(16, 32), 256, 4*CS_ST>>>();
    fused_pv<<<dim3(16, 32), 256, FA_Q + 3*FA_ST>>>();

    denseY_mma<<<dim3(4, 64), 256, 3*D1_ST>>>(O16, W16 + (size_t)3*D_*D_, x_q, b0, Yh, Yl);

    dense3_mma<<<dim3(4, 64), 256, 3*DA_ST>>>(Yh, Yl, W1h, W1l, b1, out);
}

// round 15
// speedup vs baseline: 1.4411x; 1.0135x over previous
#include <cuda_runtime.h>
#include <cuda_bf16.h>
#include <cstdint>

#define B_   4
#define NQ_  2048
#define D_   512
#define H_   8
#define DH_  64
#define M_   (B_*NQ_)
#define BH_  (B_*H_)

typedef __nv_bfloat16 bf16;

// ---------------- device scratch ----------------
__device__ __align__(16) bf16 g_Xq16[M_*D_];
__device__ __align__(16) bf16 g_Xe16[M_*D_];
__device__ __align__(16) bf16 g_W16[4*D_*D_];            // Wq*log2e, Wk, Wv, W0
__device__ __align__(16) bf16 g_W1h[D_*D_], g_W1l[D_*D_];
__device__ __align__(16) bf16 g_Q16[BH_*NQ_*DH_];        // Q' = X Wq log2e
__device__ __align__(16) bf16 g_K16[BH_*NQ_*DH_];
__device__ __align__(16) bf16 g_Vp16[BH_*NQ_*80];        // V bf16 [k][80]; 64-71=1, 72-79=0
__device__ __align__(16) bf16 g_O16[M_*D_];
__device__ __align__(16) bf16 g_Yh[M_*D_], g_Yl[M_*D_];

// ---------------- helpers ----------------
__device__ __forceinline__ uint32_t smem_u32(const void* p) {
    uint32_t a;
    asm("{ .reg .u64 t; cvta.to.shared.u64 t, %1; cvt.u32.u64 %0, t; }" : "=r"(a) : "l"(p));
    return a;
}
__device__ __forceinline__ float ex2f(float x) {
    float y; asm("ex2.approx.ftz.f32 %0, %1;" : "=f"(y) : "f"(x)); return y;
}
__device__ __forceinline__ void mma16816(float* c, const uint32_t* a, const uint32_t* b) {
    asm volatile(
        "mma.sync.aligned.m16n8k16.row.col.f32.bf16.bf16.f32 "
        "{%0,%1,%2,%3}, {%4,%5,%6,%7}, {%8,%9}, {%0,%1,%2,%3};"
        : "+f"(c[0]), "+f"(c[1]), "+f"(c[2]), "+f"(c[3])
        : "r"(a[0]), "r"(a[1]), "r"(a[2]), "r"(a[3]), "r"(b[0]), "r"(b[1]));
}
__device__ __forceinline__ void ldmx4(uint32_t* r, uint32_t a) {
    asm volatile("ldmatrix.sync.aligned.m8n8.x4.shared.b16 {%0,%1,%2,%3}, [%4];"
                 : "=r"(r[0]), "=r"(r[1]), "=r"(r[2]), "=r"(r[3]) : "r"(a));
}
__device__ __forceinline__ void ldmx4t(uint32_t* r, uint32_t a) {
    asm volatile("ldmatrix.sync.aligned.m8n8.x4.trans.shared.b16 {%0,%1,%2,%3}, [%4];"
                 : "=r"(r[0]), "=r"(r[1]), "=r"(r[2]), "=r"(r[3]) : "r"(a));
}
__device__ __forceinline__ void ldmx2t(uint32_t* r, uint32_t a) {
    asm volatile("ldmatrix.sync.aligned.m8n8.x2.trans.shared.b16 {%0,%1}, [%2];"
                 : "=r"(r[0]), "=r"(r[1]) : "r"(a));
}
__device__ __forceinline__ void lda(uint32_t* r, uint32_t base, int row0, int kbyte,
                                    int SB, int lane) {
    uint32_t a = base + (uint32_t)(row0 + (lane & 15)) * SB + kbyte + ((lane >> 4) << 4);
    ldmx4(r, a);
}
__device__ __forceinline__ void ldb_nt(uint32_t* r, uint32_t base, int n0, int kbyte,
                                       int SB, int lane) {
    uint32_t a = base + (uint32_t)(n0 + (lane & 7) + ((lane >> 4) << 3)) * SB
               + kbyte + (((lane >> 3) & 1) << 4);
    ldmx4(r, a);
}
__device__ __forceinline__ void ldb_t(uint32_t* r, uint32_t base, int k0, int n0,
                                      int SB, int lane) {
    uint32_t a = base + (uint32_t)(k0 + (lane & 7) + (((lane >> 3) & 1) << 3)) * SB
               + n0 * 2 + ((lane >> 4) << 4);
    ldmx4t(r, a);
}
__device__ __forceinline__ void ldb_t2(uint32_t* r, uint32_t base, int k0, int n0,
                                       int SB, int lane) {
    uint32_t a = base + (uint32_t)(k0 + (lane & 15)) * SB + n0 * 2;
    ldmx2t(r, a);
}
__device__ __forceinline__ uint32_t pk(bf16 a, bf16 b) {
    return (uint32_t)__bfloat16_as_ushort(a) | ((uint32_t)__bfloat16_as_ushort(b) << 16);
}
__device__ __forceinline__ uint32_t pkf(float a, float b) {
    return pk(__float2bfloat16(a), __float2bfloat16(b));
}
__device__ __forceinline__ uint2 cvt4(float4 v) {
    return make_uint2(pkf(v.x, v.y), pkf(v.z, v.w));
}
__device__ __forceinline__ void split4(float4 v, uint2& h, uint2& l) {
    bf16 h0 = __float2bfloat16(v.x), h1 = __float2bfloat16(v.y);
    bf16 h2 = __float2bfloat16(v.z), h3 = __float2bfloat16(v.w);
    bf16 l0 = __float2bfloat16(v.x - __bfloat162float(h0));
    bf16 l1 = __float2bfloat16(v.y - __bfloat162float(h1));
    bf16 l2 = __float2bfloat16(v.z - __bfloat162float(h2));
    bf16 l3 = __float2bfloat16(v.w - __bfloat162float(h3));
    h = make_uint2(pk(h0, h1), pk(h2, h3));
    l = make_uint2(pk(l0, l1), pk(l2, l3));
}
__device__ __forceinline__ void split2(float a, float b, uint32_t& ph, uint32_t& pl) {
    bf16 ha = __float2bfloat16(a), hb = __float2bfloat16(b);
    bf16 la = __float2bfloat16(a - __bfloat162float(ha));
    bf16 lb = __float2bfloat16(b - __bfloat162float(hb));
    ph = pk(ha, hb); pl = pk(la, lb);
}
__device__ __forceinline__ void cpa16(uint32_t dst, const void* src) {
    asm volatile("cp.async.cg.shared.global [%0], [%1], 16;" :: "r"(dst), "l"(src));
}
#define CP_COMMIT() asm volatile("cp.async.commit_group;" ::: "memory")
#define CP_WAIT1()  asm volatile("cp.async.wait_group 1;"  ::: "memory")
#define CP_WAIT0()  asm volatile("cp.async.wait_group 0;"  ::: "memory")

// =====================================================================
// prep: conversions (Wq scaled by log2e) + V' pad columns.
// =====================================================================
__global__ void __launch_bounds__(256)
prep_kernel(const float* __restrict__ x_q, const float* __restrict__ x_e,
            const float* __restrict__ Wq, const float* __restrict__ Wk,
            const float* __restrict__ Wv, const float* __restrict__ W0,
            const float* __restrict__ W1)
{
    const int b = blockIdx.x, tid = threadIdx.x;
    if (b < 8192) {
        const float* s = (b < 4096) ? x_q : x_e;
        bf16* d = (b < 4096) ? g_Xq16 : g_Xe16;
        const int i = (((b & 4095) * 256) + tid) * 4;
        *(uint2*)&d[i] = cvt4(*(const float4*)&s[i]);
    } else if (b < 9216) {
        const int w = (b - 8192) >> 8;
        const float* s = (w == 0) ? Wq : (w == 1) ? Wk : (w == 2) ? Wv : W0;
        const float sc = (w == 0) ? 1.4426950408889634f : 1.0f;   // log2(e) into Wq
        const int i = ((((b - 8192) & 255) * 256) + tid) * 4;
        float4 v = *(const float4*)&s[i];
        v.x *= sc; v.y *= sc; v.z *= sc; v.w *= sc;
        *(uint2*)&g_W16[(size_t)w * D_ * D_ + i] = cvt4(v);
    } else if (b < 9472) {
        const int i = (((b - 9216) * 256) + tid) * 4;
        float4 v = *(const float4*)&W1[i];
        uint2 h, l; split4(v, h, l);
        *(uint2*)&g_W1h[i] = h; *(uint2*)&g_W1l[i] = l;
    } else {
        const int row = (b - 9472) * 256 + tid;            // 65536 rows
        uint4 ones = make_uint4(0x3F803F80u, 0x3F803F80u, 0x3F803F80u, 0x3F803F80u);
        uint4 zero = make_uint4(0u, 0u, 0u, 0u);
        *(uint4*)&g_Vp16[(size_t)row * 80 + 64] = ones;
        *(uint4*)&g_Vp16[(size_t)row * 80 + 72] = zero;
    }
}

// =====================================================================
// proj: merged Q/K/V projections, blockIdx.z selects the problem.
// =====================================================================
#define D1_ST 18944   // A 128*80 + B 32*272
__global__ void __launch_bounds__(256, 2)
proj_mma()
{
    extern __shared__ __align__(16) char dyn[];
    const int tid = threadIdx.x, lane = tid & 31, wid = tid >> 5;
    const int wm = wid >> 2, wn = wid & 3;
    const int m0 = blockIdx.y * 128, n0 = blockIdx.x * 128;
    const int z = blockIdx.z;
    const bf16* __restrict__ A16 = (z == 0) ? g_Xq16 : g_Xe16;
    const bf16* __restrict__ W16 = g_W16 + (size_t)z * D_ * D_;
    bf16* __restrict__ C16 = (z == 0) ? g_Q16 : ((z == 1) ? g_K16 : g_Vp16);
    const int cstride = (z == 2) ? 80 : 64;
    const uint32_t sb = smem_u32(dyn);

    auto load = [&](int kc, int st) {
        const uint32_t sAs = sb + st * D1_ST;
        const uint32_t sBs = sAs + 10240;
#pragma unroll
        for (int j = 0; j < 2; j++) {
            int cc = tid + 256 * j;
            int row = cc >> 2, off = (cc & 3) * 16, e = (cc & 3) * 8;
            cpa16(sAs + row * 80 + off, A16 + (size_t)(m0 + row) * 512 + kc * 32 + e);
        }
#pragma unroll
        for (int j = 0; j < 2; j++) {
            int cc = tid + 256 * j;
            int row = cc >> 4, off = (cc & 15) * 16, e = (cc & 15) * 8;
            cpa16(sBs + row * 272 + off, W16 + (size_t)(kc * 32 + row) * 512 + n0 + e);
        }
    };

    float acc[4][4][4];
#pragma unroll
    for (int i = 0; i < 4; i++)
#pragma unroll
        for (int j = 0; j < 4; j++)
#pragma unroll
            for (int c = 0; c < 4; c++) acc[i][j][c] = 0.f;

    load(0, 0); CP_COMMIT();
    load(1, 1); CP_COMMIT();

    for (int kc = 0; kc < 16; kc++) {
        CP_WAIT1();
        __syncthreads();
        if (kc + 2 < 16) load(kc + 2, (kc + 2) % 3);
        CP_COMMIT();
        const uint32_t sAs = sb + (kc % 3) * D1_ST;
        const uint32_t sBs = sAs + 10240;
#pragma unroll
        for (int ks = 0; ks < 2; ks++) {
            uint32_t ah[4][4];
#pragma unroll
            for (int sm = 0; sm < 4; sm++)
                lda(ah[sm], sAs, wm * 64 + sm * 16, ks * 32, 80, lane);
            uint32_t bh[4][2];
#pragma unroll
            for (int p = 0; p < 2; p++) {
                uint32_t r[4];
                ldb_t(r, sBs, ks * 16, wn * 32 + p * 16, 272, lane);
                bh[2*p][0] = r[0]; bh[2*p][1] = r[1];
                bh[2*p+1][0] = r[2]; bh[2*p+1][1] = r[3];
            }
#pragma unroll
            for (int sm = 0; sm < 4; sm++)
#pragma unroll
                for (int sn = 0; sn < 4; sn++)
                    mma16816(acc[sm][sn], ah[sm], bh[sn]);
        }
    }

#pragma unroll
    for (int sm = 0; sm < 4; sm++) {
        const int row = m0 + wm * 64 + sm * 16 + (lane >> 2);
#pragma unroll
        for (int sn = 0; sn < 4; sn++) {
            const int col = n0 + wn * 32 + sn * 8 + (lane & 3) * 2;
            const float* a = acc[sm][sn];
            const int hh = col >> 6, dd = col & 63;
#pragma unroll
            for (int half = 0; half < 2; half++) {
                const int gm = row + half * 8;
                const int bb = gm >> 11, nn = gm & 2047;
                const size_t idx = ((size_t)(bb * H_ + hh) * NQ_ + nn) * cstride + dd;
                *(uint32_t*)&C16[idx] = pkf(a[half*2], a[half*2+1]);
            }
        }
    }
}

// =====================================================================
// denseY: Y = X - (O @ W0 + b0), single-plane operands, split-plane out.
// =====================================================================
__global__ void __launch_bounds__(256, 2)
denseY_mma(const bf16* __restrict__ A16, const bf16* __restrict__ W16,
           const float* __restrict__ X, const float* __restrict__ bias,
           bf16* __restrict__ Ch, bf16* __restrict__ Cl)
{
    extern __shared__ __align__(16) char dyn[];
    const int tid = threadIdx.x, lane = tid & 31, wid = tid >> 5;
    const int wm = wid >> 2, wn = wid & 3;
    const int m0 = blockIdx.y * 128, n0 = blockIdx.x * 128;
    const uint32_t sb = smem_u32(dyn);

    auto load = [&](int kc, int st) {
        const uint32_t sAs = sb + st * D1_ST;
        const uint32_t sBs = sAs + 10240;
#pragma unroll
        for (int j = 0; j < 2; j++) {
            int cc = tid + 256 * j;
            int row = cc >> 2, off = (cc & 3) * 16, e = (cc & 3) * 8;
            cpa16(sAs + row * 80 + off, A16 + (size_t)(m0 + row) * 512 + kc * 32 + e);
        }
#pragma unroll
        for (int j = 0; j < 2; j++) {
            int cc = tid + 256 * j;
            int row = cc >> 4, off = (cc & 15) * 16, e = (cc & 15) * 8;
            cpa16(sBs + row * 272 + off, W16 + (size_t)(kc * 32 + row) * 512 + n0 + e);
        }
    };

    float acc[4][4][4];
#pragma unroll
    for (int i = 0; i < 4; i++)
#pragma unroll
        for (int j = 0; j < 4; j++)
#pragma unroll
            for (int c = 0; c < 4; c++) acc[i][j][c] = 0.f;

    load(0, 0); CP_COMMIT();
    load(1, 1); CP_COMMIT();

    for (int kc = 0; kc < 16; kc++) {
        CP_WAIT1();
        __syncthreads();
        if (kc + 2 < 16) load(kc + 2, (kc + 2) % 3);
        CP_COMMIT();
        const uint32_t sAs = sb + (kc % 3) * D1_ST;
        const uint32_t sBs = sAs + 10240;
#pragma unroll
        for (int ks = 0; ks < 2; ks++) {
            uint32_t ah[4][4];
#pragma unroll
            for (int sm = 0; sm < 4; sm++)
                lda(ah[sm], sAs, wm * 64 + sm * 16, ks * 32, 80, lane);
            uint32_t bh[4][2];
#pragma unroll
            for (int p = 0; p < 2; p++) {
                uint32_t r[4];
                ldb_t(r, sBs, ks * 16, wn * 32 + p * 16, 272, lane);
                bh[2*p][0] = r[0]; bh[2*p][1] = r[1];
                bh[2*p+1][0] = r[2]; bh[2*p+1][1] = r[3];
            }
#pragma unroll
            for (int sm = 0; sm < 4; sm++)
#pragma unroll
                for (int sn = 0; sn < 4; sn++)
                    mma16816(acc[sm][sn], ah[sm], bh[sn]);
        }
    }

#pragma unroll
    for (int sm = 0; sm < 4; sm++) {
        const int row = m0 + wm * 64 + sm * 16 + (lane >> 2);
#pragma unroll
        for (int sn = 0; sn < 4; sn++) {
            const int col = n0 + wn * 32 + sn * 8 + (lane & 3) * 2;
            const float* a = acc[sm][sn];
            float2 bv = *(const float2*)&bias[col];
#pragma unroll
            for (int half = 0; half < 2; half++) {
                const int gm = row + half * 8;
                float2 xv = *(const float2*)&X[(size_t)gm * 512 + col];
                float o0 = xv.x - (a[half*2] + bv.x);
                float o1 = xv.y - (a[half*2+1] + bv.y);
                uint32_t ph, pl;
                split2(o0, o1, ph, pl);
                *(uint32_t*)&Ch[(size_t)gm * 512 + col] = ph;
                *(uint32_t*)&Cl[(size_t)gm * 512 + col] = pl;
            }
        }
    }
}

// =====================================================================
// dense3: split-operand GEMM out = Y @ W1 + b1 (3 products).
// =====================================================================
#define DA_ST 35328
__global__ void __launch_bounds__(256, 2)
dense3_mma(const bf16* __restrict__ Ah, const bf16* __restrict__ Al,
           const bf16* __restrict__ Wh, const bf16* __restrict__ Wl,
           const float* __restrict__ bias, float* __restrict__ Cf)
{
    extern __shared__ __align__(16) char dyn[];
    const int tid = threadIdx.x, lane = tid & 31, wid = tid >> 5;
    const int wm = wid >> 2, wn = wid & 3;
    const int m0 = blockIdx.y * 128, n0 = blockIdx.x * 128;
    const uint32_t sb = smem_u32(dyn);

    auto load = [&](int kc, int st) {
        const uint32_t sAs = sb + st * DA_ST;
        const uint32_t sBs = sAs + 18432;
#pragma unroll
        for (int j = 0; j < 2; j++) {
            int cc = tid + 256 * j;
            int row = cc >> 2, off = (cc & 3) * 16, e = (cc & 3) * 8;
            const size_t gi = (size_t)(m0 + row) * 512 + kc * 32 + e;
            cpa16(sAs + row * 144 + off,      Ah + gi);
            cpa16(sAs + row * 144 + 64 + off, Al + gi);
        }
#pragma unroll
        for (int j = 0; j < 2; j++) {
            int cc = tid + 256 * j;
            int row = cc >> 4, off = (cc & 15) * 16, e = (cc & 15) * 8;
            const size_t gi = (size_t)(kc * 32 + row) * 512 + n0 + e;
            cpa16(sBs + row * 528 + off,       Wh + gi);
            cpa16(sBs + row * 528 + 256 + off, Wl + gi);
        }
    };

    float acc[4][4][4];
#pragma unroll
    for (int i = 0; i < 4; i++)
#pragma unroll
        for (int j = 0; j < 4; j++)
#pragma unroll
            for (int c = 0; c < 4; c++) acc[i][j][c] = 0.f;

    load(0, 0); CP_COMMIT();
    load(1, 1); CP_COMMIT();

    for (int kc = 0; kc < 16; kc++) {
        CP_WAIT1();
        __syncthreads();
        if (kc + 2 < 16) load(kc + 2, (kc + 2) % 3);
        CP_COMMIT();
        const uint32_t sAs = sb + (kc % 3) * DA_ST;
        const uint32_t sBs = sAs + 18432;
#pragma unroll
        for (int ks = 0; ks < 2; ks++) {
            uint32_t ah[4][4], al[4][4];
#pragma unroll
            for (int sm = 0; sm < 4; sm++) {
                lda(ah[sm], sAs, wm * 64 + sm * 16, ks * 32, 144, lane);
                lda(al[sm], sAs, wm * 64 + sm * 16, 64 + ks * 32, 144, lane);
            }
            uint32_t bh[4][2], bl[4][2];
#pragma unroll
            for (int p = 0; p < 2; p++) {
                uint32_t r[4];
                ldb_t(r, sBs, ks * 16, wn * 32 + p * 16, 528, lane);
                bh[2*p][0] = r[0]; bh[2*p][1] = r[1];
                bh[2*p+1][0] = r[2]; bh[2*p+1][1] = r[3];
                ldb_t(r, sBs + 256, ks * 16, wn * 32 + p * 16, 528, lane);
                bl[2*p][0] = r[0]; bl[2*p][1] = r[1];
                bl[2*p+1][0] = r[2]; bl[2*p+1][1] = r[3];
            }
#pragma unroll
            for (int sm = 0; sm < 4; sm++)
#pragma unroll
                for (int sn = 0; sn < 4; sn++) {
                    mma16816(acc[sm][sn], ah[sm], bh[sn]);
                    mma16816(acc[sm][sn], al[sm], bh[sn]);
                    mma16816(acc[sm][sn], ah[sm], bl[sn]);
                }
        }
    }

#pragma unroll
    for (int sm = 0; sm < 4; sm++) {
        const int row = m0 + wm * 64 + sm * 16 + (lane >> 2);
#pragma unroll
        for (int sn = 0; sn < 4; sn++) {
            const int col = n0 + wn * 32 + sn * 8 + (lane & 3) * 2;
            const float* a = acc[sm][sn];
            float2 bv = *(const float2*)&bias[col];
#pragma unroll
            for (int half = 0; half < 2; half++) {
                const int gm = row + half * 8;
                *(float2*)&Cf[(size_t)gm * 512 + col] =
                    make_float2(a[half*2] + bv.x, a[half*2+1] + bv.y);
            }
        }
    }
}

// =====================================================================
// Pass 1: per (128-key block, bh) CTA: csum_k = sum over ALL q of
// exp2(K_k . Q_q); then scale own V' rows by 1/csum in place.
// =====================================================================
#define CS_ST 18432   // Q chunk 128*144
__global__ void __launch_bounds__(256, 2)
colsum_mma()
{
    extern __shared__ __align__(16) char dyn[];
    __shared__ float csum_s[128];
    const int tid = threadIdx.x, lane = tid & 31, wid = tid >> 5;
    const int wm = wid >> 2, wn = wid & 3;
    const int bh = blockIdx.y, k0g = blockIdx.x * 128;
    const bf16* __restrict__ Qp = g_Q16 + (size_t)bh * NQ_ * DH_;
    const bf16* __restrict__ Kp = g_K16 + (size_t)bh * NQ_ * DH_;
    const uint32_t sb = smem_u32(dyn);
    const uint32_t sK = sb;                      // K block 128*144
    const uint32_t sQ0 = sb + 18432;             // 3 Q stages

    auto loadQ = [&](int qc, int st) {
        const uint32_t sQs = sQ0 + st * CS_ST;
#pragma unroll
        for (int j = 0; j < 4; j++) {
            int cc = tid + 256 * j;
            int row = cc >> 3, m = cc & 7;
            cpa16(sQs + row * 144 + m * 16, Qp + (size_t)(qc * 128 + row) * 64 + m * 8);
        }
    };

#pragma unroll
    for (int j = 0; j < 4; j++) {
        int cc = tid + 256 * j;
        int row = cc >> 3, m = cc & 7;
        cpa16(sK + row * 144 + m * 16, Kp + (size_t)(k0g + row) * 64 + m * 8);
    }
    loadQ(0, 0); CP_COMMIT();
    loadQ(1, 1); CP_COMMIT();

    if (tid < 128) csum_s[tid] = 0.f;

    float run[4][2];
#pragma unroll
    for (int sm = 0; sm < 4; sm++) { run[sm][0] = 0.f; run[sm][1] = 0.f; }

    for (int qc = 0; qc < 16; qc++) {
        CP_WAIT1();
        __syncthreads();
        if (qc + 2 < 16) loadQ(qc + 2, (qc + 2) % 3);
        CP_COMMIT();
        const uint32_t sQs = sQ0 + (qc % 3) * CS_ST;
        float acc[4][4][4];
#pragma unroll
        for (int i = 0; i < 4; i++)
#pragma unroll
            for (int j = 0; j < 4; j++)
#pragma unroll
                for (int c = 0; c < 4; c++) acc[i][j][c] = 0.f;
#pragma unroll
        for (int ks = 0; ks < 4; ks++) {
            uint32_t ah[4][4];
#pragma unroll
            for (int sm = 0; sm < 4; sm++)
                lda(ah[sm], sK, wm * 64 + sm * 16, ks * 32, 144, lane);
            uint32_t bh_[4][2];
#pragma unroll
            for (int p = 0; p < 2; p++) {
                uint32_t r[4];
                ldb_nt(r, sQs, wn * 32 + p * 16, ks * 32, 144, lane);
                bh_[2*p][0] = r[0]; bh_[2*p][1] = r[1];
                bh_[2*p+1][0] = r[2]; bh_[2*p+1][1] = r[3];
            }
#pragma unroll
            for (int sm = 0; sm < 4; sm++)
#pragma unroll
                for (int sn = 0; sn < 4; sn++)
                    mma16816(acc[sm][sn], ah[sm], bh_[sn]);
        }
#pragma unroll
        for (int sm = 0; sm < 4; sm++)
#pragma unroll
            for (int sn = 0; sn < 4; sn++) {
                run[sm][0] += ex2f(acc[sm][sn][0]) + ex2f(acc[sm][sn][1]);
                run[sm][1] += ex2f(acc[sm][sn][2]) + ex2f(acc[sm][sn][3]);
            }
    }

#pragma unroll
    for (int o = 1; o <= 2; o <<= 1)
#pragma unroll
        for (int sm = 0; sm < 4; sm++) {
            run[sm][0] += __shfl_xor_sync(0xffffffffu, run[sm][0], o);
            run[sm][1] += __shfl_xor_sync(0xffffffffu, run[sm][1], o);
        }
    if ((lane & 3) == 0) {
#pragma unroll
        for (int sm = 0; sm < 4; sm++) {
            const int r = wm * 64 + sm * 16 + (lane >> 2);
            atomicAdd(&csum_s[r],     run[sm][0]);
            atomicAdd(&csum_s[r + 8], run[sm][1]);
        }
    }
    __syncthreads();
    if (tid < 128) csum_s[tid] = 1.f / csum_s[tid];
    __syncthreads();

    bf16* __restrict__ Vp = g_Vp16 + ((size_t)bh * NQ_ + k0g) * 80;
    for (int i = tid; i < 1280; i += 256) {
        const int row = i / 10, c8 = (i - row * 10) * 8;
        const float r = csum_s[row];
        uint4 v = *(uint4*)&Vp[(size_t)row * 80 + c8];
        const bf16* p = (const bf16*)&v;
        uint32_t* w = (uint32_t*)&v;
#pragma unroll
        for (int e = 0; e < 4; e++) {
            float a = __bfloat162float(p[2*e])     * r;
            float b = __bfloat162float(p[2*e + 1]) * r;
            w[e] = pkf(a, b);
        }
        *(uint4*)&Vp[(size_t)row * 80 + c8] = v;
    }
}

// =====================================================================
// Pass 2: fused attention, m32 per warp (q-tile 256), 1 CTA/SM.
// Each K/V B-fragment load feeds BOTH m16 blocks -> LDSM traffic halved.
// =====================================================================
#define FA_Q  36864                 // Q 256*144
#define FA_ST 20480                 // K 64*144 + V 64*176
__global__ void __launch_bounds__(256)
fused_pv()
{
    extern __shared__ __align__(16) char dyn[];
    const int tid = threadIdx.x, lane = tid & 31, wid = tid >> 5;
    const int bh = blockIdx.y, q0 = blockIdx.x * 256;
    const int bb = bh >> 3, hh = bh & 7;
    const bf16* __restrict__ Qp = g_Q16 + (size_t)bh * NQ_ * DH_;
    const bf16* __restrict__ Kp = g_K16 + (size_t)bh * NQ_ * DH_;
    const bf16* __restrict__ Vp = g_Vp16 + (size_t)bh * NQ_ * 80;
    const uint32_t sb = smem_u32(dyn);
    const uint32_t sQ = sb;

    auto loadKV = [&](int kc, int st) {
        const uint32_t base = sb + FA_Q + st * FA_ST;
        const uint32_t sK = base, sV = base + 9216;
#pragma unroll
        for (int j = 0; j < 2; j++) {
            int cc = tid + 256 * j;
            int row = cc >> 3, m = cc & 7;
            cpa16(sK + row * 144 + m * 16, Kp + (size_t)(kc * 64 + row) * 64 + m * 8);
        }
#pragma unroll
        for (int j = 0; j < 3; j++) {
            int cc = tid + 256 * j;
            if (cc < 640) {
                int row = cc / 10, m = cc - row * 10;
                cpa16(sV + row * 176 + m * 16, Vp + (size_t)(kc * 64 + row) * 80 + m * 8);
            }
        }
    };

    // Q: 256 rows
#pragma unroll
    for (int j = 0; j < 8; j++) {
        int cc = tid + 256 * j;
        int row = cc >> 3, m = cc & 7;
        cpa16(sQ + row * 144 + m * 16, Qp + (size_t)(q0 + row) * 64 + m * 8);
    }
    loadKV(0, 0); CP_COMMIT();
    loadKV(1, 1); CP_COMMIT();

    float pacc[2][9][4];
#pragma unroll
    for (int m = 0; m < 2; m++)
#pragma unroll
        for (int j = 0; j < 9; j++)
#pragma unroll
            for (int c = 0; c < 4; c++) pacc[m][j][c] = 0.f;

    uint32_t Qa[2][4][4];
    bool qloaded = false;

    for (int kc = 0; kc < 32; kc++) {
        CP_WAIT1();
        __syncthreads();
        if (kc + 2 < 32) loadKV(kc + 2, (kc + 2) % 3);
        CP_COMMIT();
        const uint32_t base = sb + FA_Q + (kc % 3) * FA_ST;
        const uint32_t sK = base, sV = base + 9216;
        if (!qloaded) {
#pragma unroll
            for (int m = 0; m < 2; m++)
#pragma unroll
                for (int ks = 0; ks < 4; ks++)
                    lda(Qa[m][ks], sQ, wid * 32 + m * 16, ks * 32, 144, lane);
            qloaded = true;
        }
        // QK: m32 x n64 x k64; each K frag feeds both m16 blocks
        float qk[2][8][4];
#pragma unroll
        for (int m = 0; m < 2; m++)
#pragma unroll
            for (int j = 0; j < 8; j++)
#pragma unroll
                for (int c = 0; c < 4; c++) qk[m][j][c] = 0.f;
#pragma unroll
        for (int ks = 0; ks < 4; ks++) {
#pragma unroll
            for (int p = 0; p < 4; p++) {
                uint32_t r[4];
                ldb_nt(r, sK, p * 16, ks * 32, 144, lane);
                mma16816(qk[0][2*p],   Qa[0][ks], r);
                mma16816(qk[0][2*p+1], Qa[0][ks], r + 2);
                mma16816(qk[1][2*p],   Qa[1][ks], r);
                mma16816(qk[1][2*p+1], Qa[1][ks], r + 2);
            }
        }
        // exp2 + pack both m blocks
        uint32_t pa[2][4][4];
#pragma unroll
        for (int m = 0; m < 2; m++)
#pragma unroll
            for (int kp = 0; kp < 4; kp++) {
                const float* s0 = qk[m][2*kp];
                const float* s1 = qk[m][2*kp+1];
                pa[m][kp][0] = pkf(ex2f(s0[0]), ex2f(s0[1]));
                pa[m][kp][1] = pkf(ex2f(s0[2]), ex2f(s0[3]));
                pa[m][kp][2] = pkf(ex2f(s1[0]), ex2f(s1[1]));
                pa[m][kp][3] = pkf(ex2f(s1[2]), ex2f(s1[3]));
            }
        // PV: each V frag feeds both m blocks
#pragma unroll
        for (int kp = 0; kp < 4; kp++) {
            const int k0 = kp * 16;
            uint32_t v0[4], v1[4], v2[4], v3[4], v4[2];
            ldb_t(v0, sV, k0, 0,  176, lane);
            ldb_t(v1, sV, k0, 16, 176, lane);
            ldb_t(v2, sV, k0, 32, 176, lane);
            ldb_t(v3, sV, k0, 48, 176, lane);
            ldb_t2(v4, sV, k0, 64, 176, lane);
#pragma unroll
            for (int m = 0; m < 2; m++) {
                mma16816(pacc[m][0], pa[m][kp], v0);
                mma16816(pacc[m][1], pa[m][kp], v0 + 2);
                mma16816(pacc[m][2], pa[m][kp], v1);
                mma16816(pacc[m][3], pa[m][kp], v1 + 2);
                mma16816(pacc[m][4], pa[m][kp], v2);
                mma16816(pacc[m][5], pa[m][kp], v2 + 2);
                mma16816(pacc[m][6], pa[m][kp], v3);
                mma16816(pacc[m][7], pa[m][kp], v3 + 2);
                mma16816(pacc[m][8], pa[m][kp], v4);
            }
        }
    }

#pragma unroll
    for (int m = 0; m < 2; m++) {
        const float inv0 = 1.f / (1e-12f + pacc[m][8][0]);
        const float inv1 = 1.f / (1e-12f + pacc[m][8][2]);
        const int gq = q0 + wid * 32 + m * 16 + (lane >> 2);
#pragma unroll
        for (int sn = 0; sn < 8; sn++) {
            const int col = sn * 8 + (lane & 3) * 2;
            size_t idx = (size_t)(bb * NQ_ + gq) * D_ + hh * DH_ + col;
            *(uint32_t*)&g_O16[idx] = pkf(pacc[m][sn][0] * inv0, pacc[m][sn][1] * inv0);
            idx = (size_t)(bb * NQ_ + gq + 8) * D_ + hh * DH_ + col;
            *(uint32_t*)&g_O16[idx] = pkf(pacc[m][sn][2] * inv1, pacc[m][sn][3] * inv1);
        }
    }
}

// =====================================================================
// Launch
// =====================================================================
extern "C" void kernel_launch(void* const* d_in, const int* in_sizes, int n_in,
                              void* d_out, int out_size)
{
    const float* x_q = (const float*)d_in[0];
    const float* x_e = (const float*)d_in[1];
    const float* Wq  = (const float*)d_in[2];
    const float* Wk  = (const float*)d_in[3];
    const float* Wv  = (const float*)d_in[4];
    const float* W0  = (const float*)d_in[5];
    const float* b0  = (const float*)d_in[6];
    const float* W1  = (const float*)d_in[7];
    const float* b1  = (const float*)d_in[8];
    float* out = (float*)d_out;

    bf16 *W16, *W1h, *W1l, *O16, *Yh, *Yl;
    cudaGetSymbolAddress((void**)&W16,  g_W16);
    cudaGetSymbolAddress((void**)&W1h,  g_W1h);
    cudaGetSymbolAddress((void**)&W1l,  g_W1l);
    cudaGetSymbolAddress((void**)&O16,  g_O16);
    cudaGetSymbolAddress((void**)&Yh,   g_Yh);
    cudaGetSymbolAddress((void**)&Yl,   g_Yl);

    cudaFuncSetAttribute(proj_mma,   cudaFuncAttributeMaxDynamicSharedMemorySize, 3*D1_ST);
    cudaFuncSetAttribute(denseY_mma, cudaFuncAttributeMaxDynamicSharedMemorySize, 3*D1_ST);
    cudaFuncSetAttribute(dense3_mma, cudaFuncAttributeMaxDynamicSharedMemorySize, 3*DA_ST);
    cudaFuncSetAttribute(colsum_mma, cudaFuncAttributeMaxDynamicSharedMemorySize, 4*CS_ST);
    cudaFuncSetAttribute(fused_pv,   cudaFuncAttributeMaxDynamicSharedMemorySize,
                         FA_Q + 3*FA_ST);

    prep_kernel<<<9728, 256>>>(x_q, x_e, Wq, Wk, Wv, W0, W1);

    proj_mma<<<dim3(4, 64, 3), 256, 3*D1_ST>>>();

    colsum_mma<<<dim3(16, 32), 256, 4*CS_ST>>>();
    fused_pv<<<dim3(8, 32), 256, FA_Q + 3*FA_ST>>>();

    denseY_mma<<<dim3(4, 64), 256, 3*D1_ST>>>(O16, W16 + (size_t)3*D_*D_, x_q, b0, Yh, Yl);

    dense3_mma<<<dim3(4, 64), 256, 3*DA_ST>>>(Yh, Yl, W1h, W1l, b1, out);
}